// round 2
// baseline (speedup 1.0000x reference)
#include <cuda_runtime.h>
#include <cmath>

#define N_NODES   131072
#define NODES_PER 2048
#define B_AUD     64
#define IN_F      512
#define HID_F     256
#define OUT_F     128
#define NHEAD     2
#define NCLS      7
#define NEG_SLOPE 0.2f

// ---------------- scratch (static device allocations; no cudaMalloc) ----------------
__device__ float g_h1raw[(size_t)N_NODES * NHEAD * HID_F]; // 256 MB
__device__ float g_h1   [(size_t)N_NODES * HID_F];         // 128 MB
__device__ float g_h2raw[(size_t)N_NODES * NHEAD * OUT_F]; // 128 MB
__device__ float g_emb  [(size_t)N_NODES * OUT_F];         //  64 MB
__device__ float g_als1 [N_NODES * NHEAD];
__device__ float g_ald1 [N_NODES * NHEAD];
__device__ float g_als2 [N_NODES * NHEAD];
__device__ float g_ald2 [N_NODES * NHEAD];
__device__ float g_logit[N_NODES];

__device__ __forceinline__ float lrelu(float v) {
    return v > 0.f ? v : NEG_SLOPE * v;
}

// ---------------- GEMM: C[N,M] = A[N,K] * B[M,K]^T  (both K-major, "NT") ----------------
// 128x128 block, BK=16, 256 threads, 8x8 micro-tile per thread.
__global__ __launch_bounds__(256)
void gemm_nt128(const float* __restrict__ A, const float* __restrict__ B,
                float* __restrict__ C, int K, int M) {
    __shared__ float As[16][132];
    __shared__ float Bs[16][132];
    const int tid  = threadIdx.x;
    const int row0 = blockIdx.y * 128;
    const int col0 = blockIdx.x * 128;
    const int tx = tid & 15;   // 16 thread cols
    const int ty = tid >> 4;   // 16 thread rows

    float acc[8][8] = {};

    for (int k0 = 0; k0 < K; k0 += 16) {
#pragma unroll
        for (int i = 0; i < 2; i++) {
            int idx = tid * 2 + i;          // 0..511
            int r   = idx >> 2;             // 0..127
            int c4  = (idx & 3) * 4;        // 0,4,8,12
            float4 va = *(const float4*)&A[(size_t)(row0 + r) * K + k0 + c4];
            As[c4 + 0][r] = va.x; As[c4 + 1][r] = va.y;
            As[c4 + 2][r] = va.z; As[c4 + 3][r] = va.w;
            float4 vb = *(const float4*)&B[(size_t)(col0 + r) * K + k0 + c4];
            Bs[c4 + 0][r] = vb.x; Bs[c4 + 1][r] = vb.y;
            Bs[c4 + 2][r] = vb.z; Bs[c4 + 3][r] = vb.w;
        }
        __syncthreads();
#pragma unroll
        for (int k = 0; k < 16; k++) {
            float a[8], b[8];
            float4 a0 = *(const float4*)&As[k][ty * 8];
            float4 a1 = *(const float4*)&As[k][ty * 8 + 4];
            float4 b0 = *(const float4*)&Bs[k][tx * 8];
            float4 b1 = *(const float4*)&Bs[k][tx * 8 + 4];
            a[0]=a0.x;a[1]=a0.y;a[2]=a0.z;a[3]=a0.w;a[4]=a1.x;a[5]=a1.y;a[6]=a1.z;a[7]=a1.w;
            b[0]=b0.x;b[1]=b0.y;b[2]=b0.z;b[3]=b0.w;b[4]=b1.x;b[5]=b1.y;b[6]=b1.z;b[7]=b1.w;
#pragma unroll
            for (int i = 0; i < 8; i++)
#pragma unroll
                for (int j = 0; j < 8; j++)
                    acc[i][j] += a[i] * b[j];
        }
        __syncthreads();
    }
#pragma unroll
    for (int i = 0; i < 8; i++) {
        size_t r = (size_t)(row0 + ty * 8 + i);
        float4* cp = (float4*)&C[r * M + col0 + tx * 8];
        cp[0] = make_float4(acc[i][0], acc[i][1], acc[i][2], acc[i][3]);
        cp[1] = make_float4(acc[i][4], acc[i][5], acc[i][6], acc[i][7]);
    }
}

// ---------------- attention logits: al_s/al_d[n,h] = <h[n,h,:], a_s/a_d[h,:]> ----------------
template <int C>
__global__ __launch_bounds__(256)
void compute_al(const float* __restrict__ h, const float* __restrict__ a_s,
                const float* __restrict__ a_d, float* __restrict__ al_s,
                float* __restrict__ al_d) {
    int warp = (blockIdx.x * blockDim.x + threadIdx.x) >> 5;
    int lane = threadIdx.x & 31;
    if (warp >= N_NODES) return;
    const float* hr = h + (size_t)warp * NHEAD * C;
#pragma unroll
    for (int hh = 0; hh < NHEAD; hh++) {
        float ss = 0.f, sd = 0.f;
#pragma unroll
        for (int c = lane; c < C; c += 32) {
            float v = hr[hh * C + c];
            ss = fmaf(v, a_s[hh * C + c], ss);
            sd = fmaf(v, a_d[hh * C + c], sd);
        }
#pragma unroll
        for (int o = 16; o; o >>= 1) {
            ss += __shfl_xor_sync(0xffffffffu, ss, o);
            sd += __shfl_xor_sync(0xffffffffu, sd, o);
        }
        if (lane == 0) {
            al_s[warp * NHEAD + hh] = ss;
            al_d[warp * NHEAD + hh] = sd;
        }
    }
}

// ---------------- GAT combine: chain graph => softmax over {self, predecessor} ----------------
template <int C, bool RELU>
__global__ __launch_bounds__(256)
void gat_combine(const float* __restrict__ hraw, const float* __restrict__ al_s,
                 const float* __restrict__ al_d, const float* __restrict__ bias,
                 float* __restrict__ out) {
    int gid = blockIdx.x * blockDim.x + threadIdx.x;
    if (gid >= N_NODES * C) return;
    int d = gid / C;
    int c = gid - d * C;
    bool has_prev = (d % NODES_PER) != 0;
    float acc = 0.f;
#pragma unroll
    for (int hh = 0; hh < NHEAD; hh++) {
        float ald = al_d[d * NHEAD + hh];
        float es  = lrelu(al_s[d * NHEAD + hh] + ald);
        float h_self = hraw[(size_t)d * NHEAD * C + hh * C + c];
        if (has_prev) {
            float ep = lrelu(al_s[(d - 1) * NHEAD + hh] + ald);
            float m  = fmaxf(es, ep);
            float xs = __expf(es - m), xp = __expf(ep - m);
            float inv = 1.f / (xs + xp);
            float h_prev = hraw[(size_t)(d - 1) * NHEAD * C + hh * C + c];
            acc += (xs * h_self + xp * h_prev) * inv;
        } else {
            acc += h_self;   // lone self-loop: alpha = 1
        }
    }
    acc = acc * (1.f / NHEAD) + bias[c];
    if (RELU) acc = fmaxf(acc, 0.f);
    out[gid] = acc;
}

// ---------------- node heads: softmax(emb@Wn^T+bn) and temporal logit ----------------
__global__ __launch_bounds__(256)
void node_heads(const float* __restrict__ emb, const float* __restrict__ Wn,
                const float* __restrict__ bn, const float* __restrict__ Wt,
                const float* __restrict__ bt, float* __restrict__ node_pred,
                float* __restrict__ logit) {
    int warp = (blockIdx.x * blockDim.x + threadIdx.x) >> 5;
    int lane = threadIdx.x & 31;
    if (warp >= N_NODES) return;
    float4 e4 = *(const float4*)&emb[(size_t)warp * OUT_F + lane * 4];
    float vals[8];
#pragma unroll
    for (int o = 0; o < 8; o++) {
        const float* w = (o < NCLS) ? &Wn[o * OUT_F] : Wt;
        float4 w4 = *(const float4*)&w[lane * 4];
        float s = e4.x * w4.x + e4.y * w4.y + e4.z * w4.z + e4.w * w4.w;
#pragma unroll
        for (int sh = 16; sh; sh >>= 1) s += __shfl_xor_sync(0xffffffffu, s, sh);
        vals[o] = s;
    }
    if (lane == 0) {
        float z[NCLS], m = -1e30f;
#pragma unroll
        for (int i = 0; i < NCLS; i++) { z[i] = vals[i] + bn[i]; m = fmaxf(m, z[i]); }
        float ssum = 0.f;
#pragma unroll
        for (int i = 0; i < NCLS; i++) { z[i] = __expf(z[i] - m); ssum += z[i]; }
        float inv = 1.f / ssum;
#pragma unroll
        for (int i = 0; i < NCLS; i++) node_pred[(size_t)warp * NCLS + i] = z[i] * inv;
        logit[warp] = vals[7] + bt[0];
    }
}

// ---------------- audio pooling: per-audio softmax over logits, weighted emb sum, Wa head ----------------
__global__ __launch_bounds__(128)
void audio_pool(const float* __restrict__ emb, const float* __restrict__ logit,
                const float* __restrict__ Wa, const float* __restrict__ ba,
                float* __restrict__ audio_pred) {
    __shared__ float w_sh[NODES_PER];
    __shared__ float red[128];
    int b = blockIdx.x, t = threadIdx.x;
    const float* lg = logit + b * NODES_PER;

    float m = -1e30f;
    for (int i = t; i < NODES_PER; i += 128) m = fmaxf(m, lg[i]);
    red[t] = m; __syncthreads();
    for (int s = 64; s; s >>= 1) { if (t < s) red[t] = fmaxf(red[t], red[t + s]); __syncthreads(); }
    m = red[0]; __syncthreads();

    float ssum = 0.f;
    for (int i = t; i < NODES_PER; i += 128) {
        float e = __expf(lg[i] - m);
        w_sh[i] = e;
        ssum += e;
    }
    red[t] = ssum; __syncthreads();
    for (int s = 64; s; s >>= 1) { if (t < s) red[t] += red[t + s]; __syncthreads(); }
    float inv = 1.f / red[0]; __syncthreads();

    // channel t weighted sum
    const float* eb = emb + (size_t)b * NODES_PER * OUT_F;
    float a0 = 0.f, a1 = 0.f, a2 = 0.f, a3 = 0.f;
    for (int i = 0; i < NODES_PER; i += 4) {
        a0 = fmaf(w_sh[i + 0], eb[(size_t)(i + 0) * OUT_F + t], a0);
        a1 = fmaf(w_sh[i + 1], eb[(size_t)(i + 1) * OUT_F + t], a1);
        a2 = fmaf(w_sh[i + 2], eb[(size_t)(i + 2) * OUT_F + t], a2);
        a3 = fmaf(w_sh[i + 3], eb[(size_t)(i + 3) * OUT_F + t], a3);
    }
    float att = ((a0 + a1) + (a2 + a3)) * inv;

    // audio_pred[b, 0:2] = att . Wa[0:2, :] + ba
#pragma unroll
    for (int o = 0; o < 2; o++) {
        red[t] = att * Wa[o * OUT_F + t]; __syncthreads();
        for (int s = 64; s; s >>= 1) { if (t < s) red[t] += red[t + s]; __syncthreads(); }
        if (t == 0) audio_pred[b * 2 + o] = red[0] + ba[o];
        __syncthreads();
    }
}

// ---------------- launch ----------------
extern "C" void kernel_launch(void* const* d_in, const int* in_sizes, int n_in,
                              void* d_out, int out_size) {
    // weights are the LAST 14 inputs: W1, as1, ad1, b1, W2, as2, ad2, b2, Wt, bt, Wa, ba, Wn, bn
    int wi = n_in - 14;
    const float* x   = (const float*)d_in[0];
    const float* W1  = (const float*)d_in[wi + 0];
    const float* as1 = (const float*)d_in[wi + 1];
    const float* ad1 = (const float*)d_in[wi + 2];
    const float* b1  = (const float*)d_in[wi + 3];
    const float* W2  = (const float*)d_in[wi + 4];
    const float* as2 = (const float*)d_in[wi + 5];
    const float* ad2 = (const float*)d_in[wi + 6];
    const float* b2  = (const float*)d_in[wi + 7];
    const float* Wt  = (const float*)d_in[wi + 8];
    const float* bt  = (const float*)d_in[wi + 9];
    const float* Wa  = (const float*)d_in[wi + 10];
    const float* ba  = (const float*)d_in[wi + 11];
    const float* Wn  = (const float*)d_in[wi + 12];
    const float* bn  = (const float*)d_in[wi + 13];

    float *h1raw, *h1, *h2raw, *emb, *als1, *ald1, *als2, *ald2, *logit;
    cudaGetSymbolAddress((void**)&h1raw, g_h1raw);
    cudaGetSymbolAddress((void**)&h1,    g_h1);
    cudaGetSymbolAddress((void**)&h2raw, g_h2raw);
    cudaGetSymbolAddress((void**)&emb,   g_emb);
    cudaGetSymbolAddress((void**)&als1,  g_als1);
    cudaGetSymbolAddress((void**)&ald1,  g_ald1);
    cudaGetSymbolAddress((void**)&als2,  g_als2);
    cudaGetSymbolAddress((void**)&ald2,  g_ald2);
    cudaGetSymbolAddress((void**)&logit, g_logit);

    float* node_pred  = (float*)d_out;
    float* audio_pred = node_pred + (size_t)N_NODES * NCLS;

    // layer 1: h1raw = x @ W1^T   [N, 512]
    gemm_nt128<<<dim3((NHEAD * HID_F) / 128, N_NODES / 128), 256>>>(x, W1, h1raw, IN_F, NHEAD * HID_F);
    compute_al<HID_F><<<N_NODES / 8, 256>>>(h1raw, as1, ad1, als1, ald1);
    gat_combine<HID_F, true><<<(N_NODES * HID_F) / 256, 256>>>(h1raw, als1, ald1, b1, h1);

    // layer 2: h2raw = h1 @ W2^T  [N, 256]
    gemm_nt128<<<dim3((NHEAD * OUT_F) / 128, N_NODES / 128), 256>>>(h1, W2, h2raw, HID_F, NHEAD * OUT_F);
    compute_al<OUT_F><<<N_NODES / 8, 256>>>(h2raw, as2, ad2, als2, ald2);
    gat_combine<OUT_F, false><<<(N_NODES * OUT_F) / 256, 256>>>(h2raw, als2, ald2, b2, emb);

    // heads
    node_heads<<<N_NODES / 8, 256>>>(emb, Wn, bn, Wt, bt, node_pred, logit);
    audio_pool<<<B_AUD, 128>>>(emb, logit, Wa, ba, audio_pred);
}

// round 3
// speedup vs baseline: 1.0042x; 1.0042x over previous
#include <cuda_runtime.h>
#include <cmath>

#define N_NODES   131072
#define NODES_PER 2048
#define B_AUD     64
#define IN_F      512
#define HID_F     256
#define OUT_F     128
#define NHEAD     2
#define NCLS      7
#define NEG_SLOPE 0.2f

// ---------------- scratch (static device allocations; no cudaMalloc) ----------------
__device__ float g_h1raw[(size_t)N_NODES * NHEAD * HID_F]; // 256 MB
__device__ float g_h1   [(size_t)N_NODES * HID_F];         // 128 MB
__device__ float g_h2raw[(size_t)N_NODES * NHEAD * OUT_F]; // 128 MB
__device__ float g_emb  [(size_t)N_NODES * OUT_F];         //  64 MB
__device__ float g_als1 [N_NODES * NHEAD];
__device__ float g_ald1 [N_NODES * NHEAD];
__device__ float g_als2 [N_NODES * NHEAD];
__device__ float g_ald2 [N_NODES * NHEAD];
__device__ float g_logit[N_NODES];

__device__ __forceinline__ float lrelu(float v) {
    return v > 0.f ? v : NEG_SLOPE * v;
}

// ---------------- GEMM: C[N,M] = A[N,K] * B[M,K]^T  (both K-major, "NT") ----------------
// 128x128 block, BK=16, 256 threads, 8x8 micro-tile per thread.
__global__ __launch_bounds__(256)
void gemm_nt128(const float* __restrict__ A, const float* __restrict__ B,
                float* __restrict__ C, int K, int M) {
    __shared__ float As[16][132];
    __shared__ float Bs[16][132];
    const int tid  = threadIdx.x;
    const int row0 = blockIdx.y * 128;
    const int col0 = blockIdx.x * 128;
    const int tx = tid & 15;   // 16 thread cols
    const int ty = tid >> 4;   // 16 thread rows

    float acc[8][8] = {};

    for (int k0 = 0; k0 < K; k0 += 16) {
#pragma unroll
        for (int i = 0; i < 2; i++) {
            int idx = tid * 2 + i;          // 0..511
            int r   = idx >> 2;             // 0..127
            int c4  = (idx & 3) * 4;        // 0,4,8,12
            float4 va = *(const float4*)&A[(size_t)(row0 + r) * K + k0 + c4];
            As[c4 + 0][r] = va.x; As[c4 + 1][r] = va.y;
            As[c4 + 2][r] = va.z; As[c4 + 3][r] = va.w;
            float4 vb = *(const float4*)&B[(size_t)(col0 + r) * K + k0 + c4];
            Bs[c4 + 0][r] = vb.x; Bs[c4 + 1][r] = vb.y;
            Bs[c4 + 2][r] = vb.z; Bs[c4 + 3][r] = vb.w;
        }
        __syncthreads();
#pragma unroll
        for (int k = 0; k < 16; k++) {
            float a[8], b[8];
            float4 a0 = *(const float4*)&As[k][ty * 8];
            float4 a1 = *(const float4*)&As[k][ty * 8 + 4];
            float4 b0 = *(const float4*)&Bs[k][tx * 8];
            float4 b1 = *(const float4*)&Bs[k][tx * 8 + 4];
            a[0]=a0.x;a[1]=a0.y;a[2]=a0.z;a[3]=a0.w;a[4]=a1.x;a[5]=a1.y;a[6]=a1.z;a[7]=a1.w;
            b[0]=b0.x;b[1]=b0.y;b[2]=b0.z;b[3]=b0.w;b[4]=b1.x;b[5]=b1.y;b[6]=b1.z;b[7]=b1.w;
#pragma unroll
            for (int i = 0; i < 8; i++)
#pragma unroll
                for (int j = 0; j < 8; j++)
                    acc[i][j] += a[i] * b[j];
        }
        __syncthreads();
    }
#pragma unroll
    for (int i = 0; i < 8; i++) {
        size_t r = (size_t)(row0 + ty * 8 + i);
        float4* cp = (float4*)&C[r * M + col0 + tx * 8];
        cp[0] = make_float4(acc[i][0], acc[i][1], acc[i][2], acc[i][3]);
        cp[1] = make_float4(acc[i][4], acc[i][5], acc[i][6], acc[i][7]);
    }
}

// ---------------- attention logits: al_s/al_d[n,h] = <h[n,h,:], a_s/a_d[h,:]> ----------------
template <int C>
__global__ __launch_bounds__(256)
void compute_al(const float* __restrict__ h, const float* __restrict__ a_s,
                const float* __restrict__ a_d, float* __restrict__ al_s,
                float* __restrict__ al_d) {
    int warp = (blockIdx.x * blockDim.x + threadIdx.x) >> 5;
    int lane = threadIdx.x & 31;
    if (warp >= N_NODES) return;
    const float* hr = h + (size_t)warp * NHEAD * C;
#pragma unroll
    for (int hh = 0; hh < NHEAD; hh++) {
        float ss = 0.f, sd = 0.f;
#pragma unroll
        for (int c = lane; c < C; c += 32) {
            float v = hr[hh * C + c];
            ss = fmaf(v, a_s[hh * C + c], ss);
            sd = fmaf(v, a_d[hh * C + c], sd);
        }
#pragma unroll
        for (int o = 16; o; o >>= 1) {
            ss += __shfl_xor_sync(0xffffffffu, ss, o);
            sd += __shfl_xor_sync(0xffffffffu, sd, o);
        }
        if (lane == 0) {
            al_s[warp * NHEAD + hh] = ss;
            al_d[warp * NHEAD + hh] = sd;
        }
    }
}

// ---------------- GAT combine: chain graph => softmax over {self, predecessor} ----------------
template <int C, bool RELU>
__global__ __launch_bounds__(256)
void gat_combine(const float* __restrict__ hraw, const float* __restrict__ al_s,
                 const float* __restrict__ al_d, const float* __restrict__ bias,
                 float* __restrict__ out) {
    int gid = blockIdx.x * blockDim.x + threadIdx.x;
    if (gid >= N_NODES * C) return;
    int d = gid / C;
    int c = gid - d * C;
    bool has_prev = (d % NODES_PER) != 0;
    float acc = 0.f;
#pragma unroll
    for (int hh = 0; hh < NHEAD; hh++) {
        float ald = al_d[d * NHEAD + hh];
        float es  = lrelu(al_s[d * NHEAD + hh] + ald);
        float h_self = hraw[(size_t)d * NHEAD * C + hh * C + c];
        if (has_prev) {
            float ep = lrelu(al_s[(d - 1) * NHEAD + hh] + ald);
            float m  = fmaxf(es, ep);
            float xs = __expf(es - m), xp = __expf(ep - m);
            float inv = 1.f / (xs + xp);
            float h_prev = hraw[(size_t)(d - 1) * NHEAD * C + hh * C + c];
            acc += (xs * h_self + xp * h_prev) * inv;
        } else {
            acc += h_self;   // lone self-loop: alpha = 1
        }
    }
    acc = acc * (1.f / NHEAD) + bias[c];
    if (RELU) acc = fmaxf(acc, 0.f);
    out[gid] = acc;
}

// ---------------- node heads: softmax(emb@Wn^T+bn) and temporal logit ----------------
__global__ __launch_bounds__(256)
void node_heads(const float* __restrict__ emb, const float* __restrict__ Wn,
                const float* __restrict__ bn, const float* __restrict__ Wt,
                const float* __restrict__ bt, float* __restrict__ node_pred,
                float* __restrict__ logit) {
    int warp = (blockIdx.x * blockDim.x + threadIdx.x) >> 5;
    int lane = threadIdx.x & 31;
    if (warp >= N_NODES) return;
    float4 e4 = *(const float4*)&emb[(size_t)warp * OUT_F + lane * 4];
    float vals[8];
#pragma unroll
    for (int o = 0; o < 8; o++) {
        const float* w = (o < NCLS) ? &Wn[o * OUT_F] : Wt;
        float4 w4 = *(const float4*)&w[lane * 4];
        float s = e4.x * w4.x + e4.y * w4.y + e4.z * w4.z + e4.w * w4.w;
#pragma unroll
        for (int sh = 16; sh; sh >>= 1) s += __shfl_xor_sync(0xffffffffu, s, sh);
        vals[o] = s;
    }
    if (lane == 0) {
        float z[NCLS], m = -1e30f;
#pragma unroll
        for (int i = 0; i < NCLS; i++) { z[i] = vals[i] + bn[i]; m = fmaxf(m, z[i]); }
        float ssum = 0.f;
#pragma unroll
        for (int i = 0; i < NCLS; i++) { z[i] = __expf(z[i] - m); ssum += z[i]; }
        float inv = 1.f / ssum;
#pragma unroll
        for (int i = 0; i < NCLS; i++) node_pred[(size_t)warp * NCLS + i] = z[i] * inv;
        logit[warp] = vals[7] + bt[0];
    }
}

// ---------------- audio pooling: per-audio softmax over logits, weighted emb sum, Wa head ----------------
__global__ __launch_bounds__(128)
void audio_pool(const float* __restrict__ emb, const float* __restrict__ logit,
                const float* __restrict__ Wa, const float* __restrict__ ba,
                float* __restrict__ audio_pred) {
    __shared__ float w_sh[NODES_PER];
    __shared__ float red[128];
    int b = blockIdx.x, t = threadIdx.x;
    const float* lg = logit + b * NODES_PER;

    float m = -1e30f;
    for (int i = t; i < NODES_PER; i += 128) m = fmaxf(m, lg[i]);
    red[t] = m; __syncthreads();
    for (int s = 64; s; s >>= 1) { if (t < s) red[t] = fmaxf(red[t], red[t + s]); __syncthreads(); }
    m = red[0]; __syncthreads();

    float ssum = 0.f;
    for (int i = t; i < NODES_PER; i += 128) {
        float e = __expf(lg[i] - m);
        w_sh[i] = e;
        ssum += e;
    }
    red[t] = ssum; __syncthreads();
    for (int s = 64; s; s >>= 1) { if (t < s) red[t] += red[t + s]; __syncthreads(); }
    float inv = 1.f / red[0]; __syncthreads();

    // channel t weighted sum
    const float* eb = emb + (size_t)b * NODES_PER * OUT_F;
    float a0 = 0.f, a1 = 0.f, a2 = 0.f, a3 = 0.f;
    for (int i = 0; i < NODES_PER; i += 4) {
        a0 = fmaf(w_sh[i + 0], eb[(size_t)(i + 0) * OUT_F + t], a0);
        a1 = fmaf(w_sh[i + 1], eb[(size_t)(i + 1) * OUT_F + t], a1);
        a2 = fmaf(w_sh[i + 2], eb[(size_t)(i + 2) * OUT_F + t], a2);
        a3 = fmaf(w_sh[i + 3], eb[(size_t)(i + 3) * OUT_F + t], a3);
    }
    float att = ((a0 + a1) + (a2 + a3)) * inv;

    // audio_pred[b, 0:2] = att . Wa[0:2, :] + ba
#pragma unroll
    for (int o = 0; o < 2; o++) {
        red[t] = att * Wa[o * OUT_F + t]; __syncthreads();
        for (int s = 64; s; s >>= 1) { if (t < s) red[t] += red[t + s]; __syncthreads(); }
        if (t == 0) audio_pred[b * 2 + o] = red[0] + ba[o];
        __syncthreads();
    }
}

// ---------------- launch ----------------
extern "C" void kernel_launch(void* const* d_in, const int* in_sizes, int n_in,
                              void* d_out, int out_size) {
    // weights are the LAST 14 inputs: W1, as1, ad1, b1, W2, as2, ad2, b2, Wt, bt, Wa, ba, Wn, bn
    int wi = n_in - 14;
    const float* x   = (const float*)d_in[0];
    const float* W1  = (const float*)d_in[wi + 0];
    const float* as1 = (const float*)d_in[wi + 1];
    const float* ad1 = (const float*)d_in[wi + 2];
    const float* b1  = (const float*)d_in[wi + 3];
    const float* W2  = (const float*)d_in[wi + 4];
    const float* as2 = (const float*)d_in[wi + 5];
    const float* ad2 = (const float*)d_in[wi + 6];
    const float* b2  = (const float*)d_in[wi + 7];
    const float* Wt  = (const float*)d_in[wi + 8];
    const float* bt  = (const float*)d_in[wi + 9];
    const float* Wa  = (const float*)d_in[wi + 10];
    const float* ba  = (const float*)d_in[wi + 11];
    const float* Wn  = (const float*)d_in[wi + 12];
    const float* bn  = (const float*)d_in[wi + 13];

    float *h1raw, *h1, *h2raw, *emb, *als1, *ald1, *als2, *ald2, *logit;
    cudaGetSymbolAddress((void**)&h1raw, g_h1raw);
    cudaGetSymbolAddress((void**)&h1,    g_h1);
    cudaGetSymbolAddress((void**)&h2raw, g_h2raw);
    cudaGetSymbolAddress((void**)&emb,   g_emb);
    cudaGetSymbolAddress((void**)&als1,  g_als1);
    cudaGetSymbolAddress((void**)&ald1,  g_ald1);
    cudaGetSymbolAddress((void**)&als2,  g_als2);
    cudaGetSymbolAddress((void**)&ald2,  g_ald2);
    cudaGetSymbolAddress((void**)&logit, g_logit);

    float* node_pred  = (float*)d_out;
    float* audio_pred = node_pred + (size_t)N_NODES * NCLS;

    // layer 1: h1raw = x @ W1^T   [N, 512]
    gemm_nt128<<<dim3((NHEAD * HID_F) / 128, N_NODES / 128), 256>>>(x, W1, h1raw, IN_F, NHEAD * HID_F);
    compute_al<HID_F><<<N_NODES / 8, 256>>>(h1raw, as1, ad1, als1, ald1);
    gat_combine<HID_F, true><<<(N_NODES * HID_F) / 256, 256>>>(h1raw, als1, ald1, b1, h1);

    // layer 2: h2raw = h1 @ W2^T  [N, 256]
    gemm_nt128<<<dim3((NHEAD * OUT_F) / 128, N_NODES / 128), 256>>>(h1, W2, h2raw, HID_F, NHEAD * OUT_F);
    compute_al<OUT_F><<<N_NODES / 8, 256>>>(h2raw, as2, ad2, als2, ald2);
    gat_combine<OUT_F, false><<<(N_NODES * OUT_F) / 256, 256>>>(h2raw, als2, ald2, b2, emb);

    // heads
    node_heads<<<N_NODES / 8, 256>>>(emb, Wn, bn, Wt, bt, node_pred, logit);
    audio_pool<<<B_AUD, 128>>>(emb, logit, Wa, ba, audio_pred);
}

// round 5
// speedup vs baseline: 1.9076x; 1.8996x over previous
#include <cuda_runtime.h>
#include <cuda_bf16.h>
#include <cstdint>

#define N_NODES   131072
#define NODES_PER 2048
#define B_AUD     64
#define IN_F      512
#define HID_F     256
#define OUT_F     128
#define NHEAD     2
#define NCLS      7
#define NEG_SLOPE 0.2f

// ---------------- scratch (static device allocations; no cudaMalloc) ----------------
__device__ float         g_h1raw[(size_t)N_NODES * NHEAD * HID_F]; // 256 MB
__device__ float         g_h2raw[(size_t)N_NODES * NHEAD * OUT_F]; // 128 MB
__device__ float         g_emb  [(size_t)N_NODES * OUT_F];         //  64 MB
__device__ __nv_bfloat16 g_xh  [(size_t)N_NODES * IN_F];
__device__ __nv_bfloat16 g_xl  [(size_t)N_NODES * IN_F];
__device__ __nv_bfloat16 g_h1h [(size_t)N_NODES * HID_F];
__device__ __nv_bfloat16 g_h1l [(size_t)N_NODES * HID_F];
__device__ __nv_bfloat16 g_w1h [512 * 512];
__device__ __nv_bfloat16 g_w1l [512 * 512];
__device__ __nv_bfloat16 g_w2h [256 * 256];
__device__ __nv_bfloat16 g_w2l [256 * 256];
__device__ float g_als1 [N_NODES * NHEAD];
__device__ float g_ald1 [N_NODES * NHEAD];
__device__ float g_als2 [N_NODES * NHEAD];
__device__ float g_ald2 [N_NODES * NHEAD];
__device__ float g_logit[N_NODES];

__device__ __forceinline__ float lrelu(float v) { return v > 0.f ? v : NEG_SLOPE * v; }

// ---------------- PTX helpers (portable: sm_80-class, compiles at compute_103) ----------------
__device__ __forceinline__ uint32_t smem_u32(const void* p) {
    uint32_t a;
    asm("{ .reg .u64 t; cvta.to.shared.u64 t, %1; cvt.u32.u64 %0, t; }" : "=r"(a) : "l"(p));
    return a;
}
__device__ __forceinline__ uint32_t swz(uint32_t b) { return b ^ ((b >> 3) & 0x70); }
__device__ __forceinline__ void cp16(uint32_t dst, const void* src) {
    asm volatile("cp.async.cg.shared.global [%0], [%1], 16;" :: "r"(dst), "l"(src));
}
__device__ __forceinline__ void ldm_x4(uint32_t* r, uint32_t addr) {
    asm volatile("ldmatrix.sync.aligned.m8n8.x4.shared.b16 {%0,%1,%2,%3}, [%4];"
                 : "=r"(r[0]), "=r"(r[1]), "=r"(r[2]), "=r"(r[3]) : "r"(addr));
}
__device__ __forceinline__ void mma_bf16(float* c, const uint32_t* a, uint32_t b0, uint32_t b1) {
    asm volatile(
        "mma.sync.aligned.m16n8k16.row.col.f32.bf16.bf16.f32 "
        "{%0,%1,%2,%3}, {%4,%5,%6,%7}, {%8,%9}, {%0,%1,%2,%3};"
        : "+f"(c[0]), "+f"(c[1]), "+f"(c[2]), "+f"(c[3])
        : "r"(a[0]), "r"(a[1]), "r"(a[2]), "r"(a[3]), "r"(b0), "r"(b1));
}

// ---------------- hi/lo bf16 split ----------------
__global__ __launch_bounds__(256)
void split_bf16(const float* __restrict__ a, __nv_bfloat16* __restrict__ hi,
                __nv_bfloat16* __restrict__ lo, int n4) {
    int i = blockIdx.x * 256 + threadIdx.x;
    if (i >= n4) return;
    float4 v = ((const float4*)a)[i];
    __nv_bfloat16 h0 = __float2bfloat16(v.x), h1 = __float2bfloat16(v.y);
    __nv_bfloat16 h2 = __float2bfloat16(v.z), h3 = __float2bfloat16(v.w);
    __nv_bfloat16 l0 = __float2bfloat16(v.x - __bfloat162float(h0));
    __nv_bfloat16 l1 = __float2bfloat16(v.y - __bfloat162float(h1));
    __nv_bfloat16 l2 = __float2bfloat16(v.z - __bfloat162float(h2));
    __nv_bfloat16 l3 = __float2bfloat16(v.w - __bfloat162float(h3));
    __nv_bfloat162 ph0; ph0.x = h0; ph0.y = h1;
    __nv_bfloat162 ph1; ph1.x = h2; ph1.y = h3;
    __nv_bfloat162 pl0; pl0.x = l0; pl0.y = l1;
    __nv_bfloat162 pl1; pl1.x = l2; pl1.y = l3;
    ((__nv_bfloat162*)hi)[2 * i]     = ph0;
    ((__nv_bfloat162*)hi)[2 * i + 1] = ph1;
    ((__nv_bfloat162*)lo)[2 * i]     = pl0;
    ((__nv_bfloat162*)lo)[2 * i + 1] = pl1;
}

// ---------------- split-bf16 warp-MMA GEMM ----------------
// C[Ntot, Mtot] = A[Ntot,K] * B[Mtot,K]^T, with A = Ah+Al, B = Bh+Bl,
// C = Ah*Bh + Ah*Bl + Al*Bh (fp32 accumulate). 3 terms folded into K loop.
// CTA 128x128, BK=64 (SW128 atoms), 3-stage cp.async pipeline, 8 warps (2x4),
// warp tile 64x32 via mma.sync.m16n8k16 bf16.
#define NSTAGE    3
#define STG_BYTES 32768   /* 16KB A + 16KB B */
#define GEMM_SMEM (NSTAGE * STG_BYTES)

template <int K>
__global__ __launch_bounds__(256, 2)
void gemm_mma(const __nv_bfloat16* __restrict__ Ah, const __nv_bfloat16* __restrict__ Al,
              const __nv_bfloat16* __restrict__ Bh, const __nv_bfloat16* __restrict__ Bl,
              float* __restrict__ C, int Mtot) {
    extern __shared__ __align__(1024) char smem[];
    uint32_t sb = smem_u32(smem);
    const int tid = threadIdx.x, wid = tid >> 5, lane = tid & 31;
    const int row0 = blockIdx.y * 128, col0 = blockIdx.x * 128;
    const int warp_m = wid >> 2;   // 0..1 -> 64 rows
    const int warp_n = wid & 3;    // 0..3 -> 32 cols
    constexpr int KCH = K / 64;
    constexpr int NIT = 3 * KCH;

    const __nv_bfloat16* Asrc[3] = {Ah, Ah, Al};
    const __nv_bfloat16* Bsrc[3] = {Bh, Bl, Bh};

    auto load = [&](int it) {
        int t = it / KCH, kc = it - t * KCH;
        const __nv_bfloat16* A = Asrc[t];
        const __nv_bfloat16* B = Bsrc[t];
        uint32_t st = sb + (it % NSTAGE) * STG_BYTES;
#pragma unroll
        for (int i = 0; i < 4; i++) {
            int idx = tid + i * 256;
            int r = idx >> 3, c16 = idx & 7;
            uint32_t so = swz(r * 128 + c16 * 16);
            cp16(st + so,         A + (size_t)(row0 + r) * K + kc * 64 + c16 * 8);
            cp16(st + 16384 + so, B + (size_t)(col0 + r) * K + kc * 64 + c16 * 8);
        }
        asm volatile("cp.async.commit_group;" ::: "memory");
    };

    float acc[4][4][4] = {};

    load(0);
    load(1);

    const int lrow = lane & 15, lhi = lane >> 4;

#pragma unroll 1
    for (int it = 0; it < NIT; it++) {
        asm volatile("cp.async.wait_group 1;" ::: "memory");
        __syncthreads();
        if (it + NSTAGE - 1 < NIT) load(it + NSTAGE - 1);
        else asm volatile("cp.async.commit_group;" ::: "memory");

        uint32_t st = sb + (it % NSTAGE) * STG_BYTES;
#pragma unroll
        for (int kk = 0; kk < 4; kk++) {
            uint32_t a[4][4];
#pragma unroll
            for (int mt = 0; mt < 4; mt++)
                ldm_x4(a[mt], st + swz((warp_m * 64 + mt * 16 + lrow) * 128 + (kk * 2 + lhi) * 16));
#pragma unroll
            for (int nt2 = 0; nt2 < 2; nt2++) {
                uint32_t b[4];
                ldm_x4(b, st + 16384 + swz((warp_n * 32 + nt2 * 16 + lrow) * 128 + (kk * 2 + lhi) * 16));
                // b regs: r0=(n0:8,k0:8) r1=(n8:16,k0:8) r2=(n0:8,k8:16) r3=(n8:16,k8:16)
#pragma unroll
                for (int mt = 0; mt < 4; mt++) {
                    mma_bf16(acc[mt][nt2 * 2 + 0], a[mt], b[0], b[2]);
                    mma_bf16(acc[mt][nt2 * 2 + 1], a[mt], b[1], b[3]);
                }
            }
        }
    }

    // epilogue: direct fp32 stores (float2 per fragment row)
#pragma unroll
    for (int mt = 0; mt < 4; mt++) {
        int row = row0 + warp_m * 64 + mt * 16 + (lane >> 2);
#pragma unroll
        for (int nt = 0; nt < 4; nt++) {
            int col = col0 + warp_n * 32 + nt * 8 + (lane & 3) * 2;
            float2 v0; v0.x = acc[mt][nt][0]; v0.y = acc[mt][nt][1];
            float2 v1; v1.x = acc[mt][nt][2]; v1.y = acc[mt][nt][3];
            *(float2*)&C[(size_t)row * Mtot + col]       = v0;
            *(float2*)&C[(size_t)(row + 8) * Mtot + col] = v1;
        }
    }
}

// ---------------- attention logits ----------------
template <int C>
__global__ __launch_bounds__(256)
void compute_al(const float* __restrict__ h, const float* __restrict__ a_s,
                const float* __restrict__ a_d, float* __restrict__ al_s,
                float* __restrict__ al_d) {
    int warp = (blockIdx.x * blockDim.x + threadIdx.x) >> 5;
    int lane = threadIdx.x & 31;
    if (warp >= N_NODES) return;
    const float* hr = h + (size_t)warp * NHEAD * C;
#pragma unroll
    for (int hh = 0; hh < NHEAD; hh++) {
        float ss = 0.f, sd = 0.f;
#pragma unroll
        for (int c = lane; c < C; c += 32) {
            float v = hr[hh * C + c];
            ss = fmaf(v, a_s[hh * C + c], ss);
            sd = fmaf(v, a_d[hh * C + c], sd);
        }
#pragma unroll
        for (int o = 16; o; o >>= 1) {
            ss += __shfl_xor_sync(0xffffffffu, ss, o);
            sd += __shfl_xor_sync(0xffffffffu, sd, o);
        }
        if (lane == 0) {
            al_s[warp * NHEAD + hh] = ss;
            al_d[warp * NHEAD + hh] = sd;
        }
    }
}

// ---------------- GAT combine (chain graph); optionally emits bf16 hi/lo split ----------------
template <int C, bool RELU, bool SPLIT>
__global__ __launch_bounds__(256)
void gat_combine(const float* __restrict__ hraw, const float* __restrict__ al_s,
                 const float* __restrict__ al_d, const float* __restrict__ bias,
                 float* __restrict__ out, __nv_bfloat16* __restrict__ out_hi,
                 __nv_bfloat16* __restrict__ out_lo) {
    int gid = blockIdx.x * blockDim.x + threadIdx.x;
    if (gid >= N_NODES * C) return;
    int d = gid / C;
    int c = gid - d * C;
    bool has_prev = (d % NODES_PER) != 0;
    float acc = 0.f;
#pragma unroll
    for (int hh = 0; hh < NHEAD; hh++) {
        float ald = al_d[d * NHEAD + hh];
        float es  = lrelu(al_s[d * NHEAD + hh] + ald);
        float h_self = hraw[(size_t)d * NHEAD * C + hh * C + c];
        if (has_prev) {
            float ep = lrelu(al_s[(d - 1) * NHEAD + hh] + ald);
            float m  = fmaxf(es, ep);
            float xs = __expf(es - m), xp = __expf(ep - m);
            float inv = 1.f / (xs + xp);
            float h_prev = hraw[(size_t)(d - 1) * NHEAD * C + hh * C + c];
            acc += (xs * h_self + xp * h_prev) * inv;
        } else {
            acc += h_self;
        }
    }
    acc = acc * (1.f / NHEAD) + bias[c];
    if (RELU) acc = fmaxf(acc, 0.f);
    if (SPLIT) {
        __nv_bfloat16 h = __float2bfloat16(acc);
        out_hi[gid] = h;
        out_lo[gid] = __float2bfloat16(acc - __bfloat162float(h));
    } else {
        out[gid] = acc;
    }
}

// ---------------- node heads ----------------
__global__ __launch_bounds__(256)
void node_heads(const float* __restrict__ emb, const float* __restrict__ Wn,
                const float* __restrict__ bn, const float* __restrict__ Wt,
                const float* __restrict__ bt, float* __restrict__ node_pred,
                float* __restrict__ logit) {
    int warp = (blockIdx.x * blockDim.x + threadIdx.x) >> 5;
    int lane = threadIdx.x & 31;
    if (warp >= N_NODES) return;
    float4 e4 = *(const float4*)&emb[(size_t)warp * OUT_F + lane * 4];
    float vals[8];
#pragma unroll
    for (int o = 0; o < 8; o++) {
        const float* w = (o < NCLS) ? &Wn[o * OUT_F] : Wt;
        float4 w4 = *(const float4*)&w[lane * 4];
        float s = e4.x * w4.x + e4.y * w4.y + e4.z * w4.z + e4.w * w4.w;
#pragma unroll
        for (int sh = 16; sh; sh >>= 1) s += __shfl_xor_sync(0xffffffffu, s, sh);
        vals[o] = s;
    }
    if (lane == 0) {
        float z[NCLS], m = -1e30f;
#pragma unroll
        for (int i = 0; i < NCLS; i++) { z[i] = vals[i] + bn[i]; m = fmaxf(m, z[i]); }
        float ssum = 0.f;
#pragma unroll
        for (int i = 0; i < NCLS; i++) { z[i] = __expf(z[i] - m); ssum += z[i]; }
        float inv = 1.f / ssum;
#pragma unroll
        for (int i = 0; i < NCLS; i++) node_pred[(size_t)warp * NCLS + i] = z[i] * inv;
        logit[warp] = vals[7] + bt[0];
    }
}

// ---------------- audio pooling ----------------
__global__ __launch_bounds__(128)
void audio_pool(const float* __restrict__ emb, const float* __restrict__ logit,
                const float* __restrict__ Wa, const float* __restrict__ ba,
                float* __restrict__ audio_pred) {
    __shared__ float w_sh[NODES_PER];
    __shared__ float red[128];
    int b = blockIdx.x, t = threadIdx.x;
    const float* lg = logit + b * NODES_PER;

    float m = -1e30f;
    for (int i = t; i < NODES_PER; i += 128) m = fmaxf(m, lg[i]);
    red[t] = m; __syncthreads();
    for (int s = 64; s; s >>= 1) { if (t < s) red[t] = fmaxf(red[t], red[t + s]); __syncthreads(); }
    m = red[0]; __syncthreads();

    float ssum = 0.f;
    for (int i = t; i < NODES_PER; i += 128) {
        float e = __expf(lg[i] - m);
        w_sh[i] = e;
        ssum += e;
    }
    red[t] = ssum; __syncthreads();
    for (int s = 64; s; s >>= 1) { if (t < s) red[t] += red[t + s]; __syncthreads(); }
    float inv = 1.f / red[0]; __syncthreads();

    const float* eb = emb + (size_t)b * NODES_PER * OUT_F;
    float a0 = 0.f, a1 = 0.f, a2 = 0.f, a3 = 0.f;
    for (int i = 0; i < NODES_PER; i += 4) {
        a0 = fmaf(w_sh[i + 0], eb[(size_t)(i + 0) * OUT_F + t], a0);
        a1 = fmaf(w_sh[i + 1], eb[(size_t)(i + 1) * OUT_F + t], a1);
        a2 = fmaf(w_sh[i + 2], eb[(size_t)(i + 2) * OUT_F + t], a2);
        a3 = fmaf(w_sh[i + 3], eb[(size_t)(i + 3) * OUT_F + t], a3);
    }
    float att = ((a0 + a1) + (a2 + a3)) * inv;

#pragma unroll
    for (int o = 0; o < 2; o++) {
        red[t] = att * Wa[o * OUT_F + t]; __syncthreads();
        for (int s = 64; s; s >>= 1) { if (t < s) red[t] += red[t + s]; __syncthreads(); }
        if (t == 0) audio_pred[b * 2 + o] = red[0] + ba[o];
        __syncthreads();
    }
}

// ---------------- launch ----------------
extern "C" void kernel_launch(void* const* d_in, const int* in_sizes, int n_in,
                              void* d_out, int out_size) {
    int wi = n_in - 14;
    const float* x   = (const float*)d_in[0];
    const float* W1  = (const float*)d_in[wi + 0];
    const float* as1 = (const float*)d_in[wi + 1];
    const float* ad1 = (const float*)d_in[wi + 2];
    const float* b1  = (const float*)d_in[wi + 3];
    const float* W2  = (const float*)d_in[wi + 4];
    const float* as2 = (const float*)d_in[wi + 5];
    const float* ad2 = (const float*)d_in[wi + 6];
    const float* b2  = (const float*)d_in[wi + 7];
    const float* Wt  = (const float*)d_in[wi + 8];
    const float* bt  = (const float*)d_in[wi + 9];
    const float* Wa  = (const float*)d_in[wi + 10];
    const float* ba  = (const float*)d_in[wi + 11];
    const float* Wn  = (const float*)d_in[wi + 12];
    const float* bn  = (const float*)d_in[wi + 13];

    float *h1raw, *h2raw, *emb, *als1, *ald1, *als2, *ald2, *logit;
    __nv_bfloat16 *xh, *xl, *h1h, *h1l, *w1h, *w1l, *w2h, *w2l;
    cudaGetSymbolAddress((void**)&h1raw, g_h1raw);
    cudaGetSymbolAddress((void**)&h2raw, g_h2raw);
    cudaGetSymbolAddress((void**)&emb,   g_emb);
    cudaGetSymbolAddress((void**)&xh,    g_xh);
    cudaGetSymbolAddress((void**)&xl,    g_xl);
    cudaGetSymbolAddress((void**)&h1h,   g_h1h);
    cudaGetSymbolAddress((void**)&h1l,   g_h1l);
    cudaGetSymbolAddress((void**)&w1h,   g_w1h);
    cudaGetSymbolAddress((void**)&w1l,   g_w1l);
    cudaGetSymbolAddress((void**)&w2h,   g_w2h);
    cudaGetSymbolAddress((void**)&w2l,   g_w2l);
    cudaGetSymbolAddress((void**)&als1,  g_als1);
    cudaGetSymbolAddress((void**)&ald1,  g_ald1);
    cudaGetSymbolAddress((void**)&als2,  g_als2);
    cudaGetSymbolAddress((void**)&ald2,  g_ald2);
    cudaGetSymbolAddress((void**)&logit, g_logit);

    float* node_pred  = (float*)d_out;
    float* audio_pred = node_pred + (size_t)N_NODES * NCLS;

    cudaFuncSetAttribute(gemm_mma<512>, cudaFuncAttributeMaxDynamicSharedMemorySize, GEMM_SMEM);
    cudaFuncSetAttribute(gemm_mma<256>, cudaFuncAttributeMaxDynamicSharedMemorySize, GEMM_SMEM);

    // splits
    {
        int n4 = (N_NODES * IN_F) / 4;
        split_bf16<<<(n4 + 255) / 256, 256>>>(x, xh, xl, n4);
    }
    split_bf16<<<(512 * 512 / 4 + 255) / 256, 256>>>(W1, w1h, w1l, 512 * 512 / 4);
    split_bf16<<<(256 * 256 / 4 + 255) / 256, 256>>>(W2, w2h, w2l, 256 * 256 / 4);

    // layer 1: h1raw = x @ W1^T   [N, 512]
    gemm_mma<512><<<dim3(4, N_NODES / 128), 256, GEMM_SMEM>>>(xh, xl, w1h, w1l, h1raw, 512);
    compute_al<HID_F><<<N_NODES / 8, 256>>>(h1raw, as1, ad1, als1, ald1);
    gat_combine<HID_F, true, true><<<(N_NODES * HID_F) / 256, 256>>>(
        h1raw, als1, ald1, b1, nullptr, h1h, h1l);

    // layer 2: h2raw = h1 @ W2^T  [N, 256]
    gemm_mma<256><<<dim3(2, N_NODES / 128), 256, GEMM_SMEM>>>(h1h, h1l, w2h, w2l, h2raw, 256);
    compute_al<OUT_F><<<N_NODES / 8, 256>>>(h2raw, as2, ad2, als2, ald2);
    gat_combine<OUT_F, false, false><<<(N_NODES * OUT_F) / 256, 256>>>(
        h2raw, als2, ald2, b2, emb, nullptr, nullptr);

    // heads
    node_heads<<<N_NODES / 8, 256>>>(emb, Wn, bn, Wt, bt, node_pred, logit);
    audio_pool<<<B_AUD, 128>>>(emb, logit, Wa, ba, audio_pred);
}

// round 6
// speedup vs baseline: 2.0837x; 1.0923x over previous
#include <cuda_runtime.h>
#include <cuda_bf16.h>
#include <cstdint>

#define N_NODES   131072
#define NODES_PER 2048
#define B_AUD     64
#define IN_F      512
#define HID_F     256
#define OUT_F     128
#define NHEAD     2
#define NCLS      7
#define NEG_SLOPE 0.2f
#define PART_STRIDE ((size_t)N_NODES * NHEAD)

// ---------------- scratch (static device allocations; no cudaMalloc) ----------------
__device__ float         g_h1raw[(size_t)N_NODES * NHEAD * HID_F]; // 256 MB
__device__ float         g_h2raw[(size_t)N_NODES * NHEAD * OUT_F]; // 128 MB
__device__ float         g_emb  [(size_t)N_NODES * OUT_F];         //  64 MB
__device__ __nv_bfloat16 g_xh  [(size_t)N_NODES * IN_F];
__device__ __nv_bfloat16 g_xl  [(size_t)N_NODES * IN_F];
__device__ __nv_bfloat16 g_h1h [(size_t)N_NODES * HID_F];
__device__ __nv_bfloat16 g_h1l [(size_t)N_NODES * HID_F];
__device__ __nv_bfloat16 g_w1h [512 * 512];
__device__ __nv_bfloat16 g_w1l [512 * 512];
__device__ __nv_bfloat16 g_w2h [256 * 256];
__device__ __nv_bfloat16 g_w2l [256 * 256];
__device__ float g_als1p[2 * PART_STRIDE];
__device__ float g_ald1p[2 * PART_STRIDE];
__device__ float g_als2p[2 * PART_STRIDE];
__device__ float g_ald2p[2 * PART_STRIDE];
__device__ float g_logit[N_NODES];

__device__ __forceinline__ float lrelu(float v) { return v > 0.f ? v : NEG_SLOPE * v; }

// ---------------- PTX helpers (portable: sm_80-class, compiles at compute_103) ----------------
__device__ __forceinline__ uint32_t smem_u32(const void* p) {
    uint32_t a;
    asm("{ .reg .u64 t; cvta.to.shared.u64 t, %1; cvt.u32.u64 %0, t; }" : "=r"(a) : "l"(p));
    return a;
}
__device__ __forceinline__ uint32_t swz(uint32_t b) { return b ^ ((b >> 3) & 0x70); }
__device__ __forceinline__ void cp16(uint32_t dst, const void* src) {
    asm volatile("cp.async.cg.shared.global [%0], [%1], 16;" :: "r"(dst), "l"(src));
}
__device__ __forceinline__ void ldm_x4(uint32_t* r, uint32_t addr) {
    asm volatile("ldmatrix.sync.aligned.m8n8.x4.shared.b16 {%0,%1,%2,%3}, [%4];"
                 : "=r"(r[0]), "=r"(r[1]), "=r"(r[2]), "=r"(r[3]) : "r"(addr));
}
__device__ __forceinline__ void mma_bf16(float* c, const uint32_t* a, uint32_t b0, uint32_t b1) {
    asm volatile(
        "mma.sync.aligned.m16n8k16.row.col.f32.bf16.bf16.f32 "
        "{%0,%1,%2,%3}, {%4,%5,%6,%7}, {%8,%9}, {%0,%1,%2,%3};"
        : "+f"(c[0]), "+f"(c[1]), "+f"(c[2]), "+f"(c[3])
        : "r"(a[0]), "r"(a[1]), "r"(a[2]), "r"(a[3]), "r"(b0), "r"(b1));
}

// ---------------- hi/lo bf16 split ----------------
__global__ __launch_bounds__(256)
void split_bf16(const float* __restrict__ a, __nv_bfloat16* __restrict__ hi,
                __nv_bfloat16* __restrict__ lo, int n4) {
    int i = blockIdx.x * 256 + threadIdx.x;
    if (i >= n4) return;
    float4 v = ((const float4*)a)[i];
    __nv_bfloat16 h0 = __float2bfloat16(v.x), h1 = __float2bfloat16(v.y);
    __nv_bfloat16 h2 = __float2bfloat16(v.z), h3 = __float2bfloat16(v.w);
    __nv_bfloat16 l0 = __float2bfloat16(v.x - __bfloat162float(h0));
    __nv_bfloat16 l1 = __float2bfloat16(v.y - __bfloat162float(h1));
    __nv_bfloat16 l2 = __float2bfloat16(v.z - __bfloat162float(h2));
    __nv_bfloat16 l3 = __float2bfloat16(v.w - __bfloat162float(h3));
    __nv_bfloat162 ph0; ph0.x = h0; ph0.y = h1;
    __nv_bfloat162 ph1; ph1.x = h2; ph1.y = h3;
    __nv_bfloat162 pl0; pl0.x = l0; pl0.y = l1;
    __nv_bfloat162 pl1; pl1.x = l2; pl1.y = l3;
    ((__nv_bfloat162*)hi)[2 * i]     = ph0;
    ((__nv_bfloat162*)hi)[2 * i + 1] = ph1;
    ((__nv_bfloat162*)lo)[2 * i]     = pl0;
    ((__nv_bfloat162*)lo)[2 * i + 1] = pl1;
}

// ---------------- split-bf16 warp-MMA GEMM, pass-grouped, fused al-epilogue ----------------
// C[Ntot,Mtot] = (Ah+Al)(Bh+Bl)^T approx = Ah*Bh + Ah*Bl + Al*Bh (fp32 acc).
// Pass 0 stages {Ah,Bh,Bl} -> 2 terms per A-frag; pass 1 stages {Al,Bh} -> 1 term.
// CTA 128x128, BK=64, 2-stage cp.async; 8 warps 2x4, warp tile 64x32.
// Epilogue: store C + per-(node,head) partial dot with a_src/a_dst.
#define STG_A     0
#define STG_BH    16384
#define STG_BL    32768
#define STG_BYTES 49152
#define GEMM_SMEM (2 * STG_BYTES)

template <int K>
__global__ __launch_bounds__(256, 2)
void gemm_mma(const __nv_bfloat16* __restrict__ Ah, const __nv_bfloat16* __restrict__ Al,
              const __nv_bfloat16* __restrict__ Bh, const __nv_bfloat16* __restrict__ Bl,
              float* __restrict__ C, int Mtot,
              const float* __restrict__ ws_flat, const float* __restrict__ wd_flat,
              float* __restrict__ alsP, float* __restrict__ aldP) {
    extern __shared__ __align__(1024) char smem[];
    uint32_t sb = smem_u32(smem);
    const int tid = threadIdx.x, wid = tid >> 5, lane = tid & 31;
    const int row0 = blockIdx.y * 128, col0 = blockIdx.x * 128;
    const int warp_m = wid >> 2;   // 0..1 -> 64 rows
    const int warp_n = wid & 3;    // 0..3 -> 32 cols
    constexpr int KCH = K / 64;
    constexpr int NIT = 2 * KCH;

    auto load = [&](int it) {
        int p  = it >= KCH;
        int kc = it - p * KCH;
        const __nv_bfloat16* A = p ? Al : Ah;
        uint32_t st = sb + (it & 1) * STG_BYTES;
#pragma unroll
        for (int i = 0; i < 4; i++) {
            int idx = tid + i * 256;
            int r = idx >> 3, c16 = idx & 7;
            uint32_t so = swz(r * 128 + c16 * 16);
            cp16(st + STG_A + so,  A  + (size_t)(row0 + r) * K + kc * 64 + c16 * 8);
            cp16(st + STG_BH + so, Bh + (size_t)(col0 + r) * K + kc * 64 + c16 * 8);
            if (!p)
                cp16(st + STG_BL + so, Bl + (size_t)(col0 + r) * K + kc * 64 + c16 * 8);
        }
        asm volatile("cp.async.commit_group;" ::: "memory");
    };

    float acc[4][4][4] = {};

    load(0);
    load(1);

    const int lrow = lane & 15, lhi = lane >> 4;

#pragma unroll 1
    for (int it = 0; it < NIT; it++) {
        asm volatile("cp.async.wait_group 1;" ::: "memory");
        __syncthreads();

        const int p = it >= KCH;
        uint32_t st = sb + (it & 1) * STG_BYTES;
#pragma unroll
        for (int kk = 0; kk < 4; kk++) {
            uint32_t a[4][4];
#pragma unroll
            for (int mt = 0; mt < 4; mt++)
                ldm_x4(a[mt], st + STG_A + swz((warp_m * 64 + mt * 16 + lrow) * 128 + (kk * 2 + lhi) * 16));
#pragma unroll
            for (int nt2 = 0; nt2 < 2; nt2++) {
                uint32_t bso = swz((warp_n * 32 + nt2 * 16 + lrow) * 128 + (kk * 2 + lhi) * 16);
                uint32_t b[4];
                ldm_x4(b, st + STG_BH + bso);
#pragma unroll
                for (int mt = 0; mt < 4; mt++) {
                    mma_bf16(acc[mt][nt2 * 2 + 0], a[mt], b[0], b[2]);
                    mma_bf16(acc[mt][nt2 * 2 + 1], a[mt], b[1], b[3]);
                }
                if (!p) {
                    uint32_t bl[4];
                    ldm_x4(bl, st + STG_BL + bso);
#pragma unroll
                    for (int mt = 0; mt < 4; mt++) {
                        mma_bf16(acc[mt][nt2 * 2 + 0], a[mt], bl[0], bl[2]);
                        mma_bf16(acc[mt][nt2 * 2 + 1], a[mt], bl[1], bl[3]);
                    }
                }
            }
        }
        __syncthreads();
        if (it + 2 < NIT) load(it + 2);
        else asm volatile("cp.async.commit_group;" ::: "memory");
    }

    // ---- epilogue 1: store C tile ----
#pragma unroll
    for (int mt = 0; mt < 4; mt++) {
        int row = row0 + warp_m * 64 + mt * 16 + (lane >> 2);
#pragma unroll
        for (int nt = 0; nt < 4; nt++) {
            int col = col0 + warp_n * 32 + nt * 8 + (lane & 3) * 2;
            float2 v0; v0.x = acc[mt][nt][0]; v0.y = acc[mt][nt][1];
            float2 v1; v1.x = acc[mt][nt][2]; v1.y = acc[mt][nt][3];
            *(float2*)&C[(size_t)row * Mtot + col]       = v0;
            *(float2*)&C[(size_t)(row + 8) * Mtot + col] = v1;
        }
    }

    // ---- epilogue 2: partial attention logits (dot with a_src / a_dst over this CTA's 128 cols) ----
    const int C_head = Mtot / NHEAD;
    const int head = col0 / C_head;
    const int slot = (col0 % C_head) >> 7;   // 0 or 1 (which 128-col half of the head)
    float* bufss = (float*)smem;             // [4 warp_n][128 rows]
    float* bufsd = bufss + 512;

#pragma unroll
    for (int mt = 0; mt < 4; mt++) {
        float ss0 = 0.f, ss1 = 0.f, sd0 = 0.f, sd1 = 0.f;
#pragma unroll
        for (int nt = 0; nt < 4; nt++) {
            int c = col0 + warp_n * 32 + nt * 8 + (lane & 3) * 2;
            float w0s = ws_flat[c], w1s = ws_flat[c + 1];
            float w0d = wd_flat[c], w1d = wd_flat[c + 1];
            ss0 = fmaf(acc[mt][nt][0], w0s, fmaf(acc[mt][nt][1], w1s, ss0));
            ss1 = fmaf(acc[mt][nt][2], w0s, fmaf(acc[mt][nt][3], w1s, ss1));
            sd0 = fmaf(acc[mt][nt][0], w0d, fmaf(acc[mt][nt][1], w1d, sd0));
            sd1 = fmaf(acc[mt][nt][2], w0d, fmaf(acc[mt][nt][3], w1d, sd1));
        }
#pragma unroll
        for (int off = 1; off <= 2; off <<= 1) {
            ss0 += __shfl_xor_sync(0xffffffffu, ss0, off);
            ss1 += __shfl_xor_sync(0xffffffffu, ss1, off);
            sd0 += __shfl_xor_sync(0xffffffffu, sd0, off);
            sd1 += __shfl_xor_sync(0xffffffffu, sd1, off);
        }
        if ((lane & 3) == 0) {
            int r0 = warp_m * 64 + mt * 16 + (lane >> 2);
            bufss[warp_n * 128 + r0]     = ss0;
            bufss[warp_n * 128 + r0 + 8] = ss1;
            bufsd[warp_n * 128 + r0]     = sd0;
            bufsd[warp_n * 128 + r0 + 8] = sd1;
        }
    }
    __syncthreads();
    if (tid < 128) {
        float ss = bufss[tid] + bufss[128 + tid] + bufss[256 + tid] + bufss[384 + tid];
        float sd = bufsd[tid] + bufsd[128 + tid] + bufsd[256 + tid] + bufsd[384 + tid];
        size_t node = (size_t)(row0 + tid);
        alsP[(size_t)slot * PART_STRIDE + node * NHEAD + head] = ss;
        aldP[(size_t)slot * PART_STRIDE + node * NHEAD + head] = sd;
    }
}

// ---------------- layer-1 GAT combine: one block per node, emits bf16 hi/lo split ----------------
__global__ __launch_bounds__(256)
void gat_combine_l1(const float* __restrict__ hraw, const float* __restrict__ alsP,
                    const float* __restrict__ aldP, const float* __restrict__ bias,
                    __nv_bfloat16* __restrict__ out_hi, __nv_bfloat16* __restrict__ out_lo) {
    int d = blockIdx.x, c = threadIdx.x;              // C = 256
    bool has_prev = (d % NODES_PER) != 0;
    float acc = 0.f;
#pragma unroll
    for (int hh = 0; hh < NHEAD; hh++) {
        size_t ai = (size_t)d * NHEAD + hh;
        float als = alsP[ai] + alsP[PART_STRIDE + ai];
        float ald = aldP[ai] + aldP[PART_STRIDE + ai];
        float es  = lrelu(als + ald);
        float h_self = hraw[(size_t)d * NHEAD * HID_F + hh * HID_F + c];
        if (has_prev) {
            size_t pi = (size_t)(d - 1) * NHEAD + hh;
            float alsp = alsP[pi] + alsP[PART_STRIDE + pi];
            float ep = lrelu(alsp + ald);
            float m  = fmaxf(es, ep);
            float xs = __expf(es - m), xp = __expf(ep - m);
            float inv = 1.f / (xs + xp);
            float h_prev = hraw[(size_t)(d - 1) * NHEAD * HID_F + hh * HID_F + c];
            acc += (xs * h_self + xp * h_prev) * inv;
        } else {
            acc += h_self;
        }
    }
    acc = acc * (1.f / NHEAD) + bias[c];
    acc = fmaxf(acc, 0.f);
    size_t gid = (size_t)d * HID_F + c;
    __nv_bfloat16 h = __float2bfloat16(acc);
    out_hi[gid] = h;
    out_lo[gid] = __float2bfloat16(acc - __bfloat162float(h));
}

// ---------------- layer-2 combine + node heads, warp per node ----------------
__global__ __launch_bounds__(256)
void gat_l2_fused(const float* __restrict__ h2raw, const float* __restrict__ alsP,
                  const float* __restrict__ aldP, const float* __restrict__ b2,
                  const float* __restrict__ Wn, const float* __restrict__ bn,
                  const float* __restrict__ Wt, const float* __restrict__ bt,
                  float* __restrict__ emb, float* __restrict__ node_pred,
                  float* __restrict__ logit) {
    int d    = (blockIdx.x * blockDim.x + threadIdx.x) >> 5;
    int lane = threadIdx.x & 31;
    if (d >= N_NODES) return;
    bool has_prev = (d % NODES_PER) != 0;

    float e[4] = {0.f, 0.f, 0.f, 0.f};
#pragma unroll
    for (int hh = 0; hh < NHEAD; hh++) {
        size_t ai = (size_t)d * NHEAD + hh;
        float als = alsP[ai];
        float ald = aldP[ai];
        float es  = lrelu(als + ald);
        float4 hs = *(const float4*)&h2raw[(size_t)d * NHEAD * OUT_F + hh * OUT_F + lane * 4];
        if (has_prev) {
            float alsp = alsP[(size_t)(d - 1) * NHEAD + hh];
            float ep = lrelu(alsp + ald);
            float m  = fmaxf(es, ep);
            float xs = __expf(es - m), xp = __expf(ep - m);
            float inv = 1.f / (xs + xp);
            float4 hp = *(const float4*)&h2raw[(size_t)(d - 1) * NHEAD * OUT_F + hh * OUT_F + lane * 4];
            e[0] += (xs * hs.x + xp * hp.x) * inv;
            e[1] += (xs * hs.y + xp * hp.y) * inv;
            e[2] += (xs * hs.z + xp * hp.z) * inv;
            e[3] += (xs * hs.w + xp * hp.w) * inv;
        } else {
            e[0] += hs.x; e[1] += hs.y; e[2] += hs.z; e[3] += hs.w;
        }
    }
    float4 bb = *(const float4*)&b2[lane * 4];
    e[0] = e[0] * 0.5f + bb.x;
    e[1] = e[1] * 0.5f + bb.y;
    e[2] = e[2] * 0.5f + bb.z;
    e[3] = e[3] * 0.5f + bb.w;
    float4 ev; ev.x = e[0]; ev.y = e[1]; ev.z = e[2]; ev.w = e[3];
    *(float4*)&emb[(size_t)d * OUT_F + lane * 4] = ev;

    // heads: 7 node classes + temporal logit
    float vals[8];
#pragma unroll
    for (int o = 0; o < 8; o++) {
        const float* w = (o < NCLS) ? &Wn[o * OUT_F] : Wt;
        float4 w4 = *(const float4*)&w[lane * 4];
        float s = e[0] * w4.x + e[1] * w4.y + e[2] * w4.z + e[3] * w4.w;
#pragma unroll
        for (int sh = 16; sh; sh >>= 1) s += __shfl_xor_sync(0xffffffffu, s, sh);
        vals[o] = s;
    }
    if (lane == 0) {
        float z[NCLS], m = -1e30f;
#pragma unroll
        for (int i = 0; i < NCLS; i++) { z[i] = vals[i] + bn[i]; m = fmaxf(m, z[i]); }
        float ssum = 0.f;
#pragma unroll
        for (int i = 0; i < NCLS; i++) { z[i] = __expf(z[i] - m); ssum += z[i]; }
        float inv = 1.f / ssum;
#pragma unroll
        for (int i = 0; i < NCLS; i++) node_pred[(size_t)d * NCLS + i] = z[i] * inv;
        logit[d] = vals[7] + bt[0];
    }
}

// ---------------- audio pooling ----------------
__global__ __launch_bounds__(128)
void audio_pool(const float* __restrict__ emb, const float* __restrict__ logit,
                const float* __restrict__ Wa, const float* __restrict__ ba,
                float* __restrict__ audio_pred) {
    __shared__ float w_sh[NODES_PER];
    __shared__ float red[128];
    int b = blockIdx.x, t = threadIdx.x;
    const float* lg = logit + b * NODES_PER;

    float m = -1e30f;
    for (int i = t; i < NODES_PER; i += 128) m = fmaxf(m, lg[i]);
    red[t] = m; __syncthreads();
    for (int s = 64; s; s >>= 1) { if (t < s) red[t] = fmaxf(red[t], red[t + s]); __syncthreads(); }
    m = red[0]; __syncthreads();

    float ssum = 0.f;
    for (int i = t; i < NODES_PER; i += 128) {
        float e = __expf(lg[i] - m);
        w_sh[i] = e;
        ssum += e;
    }
    red[t] = ssum; __syncthreads();
    for (int s = 64; s; s >>= 1) { if (t < s) red[t] += red[t + s]; __syncthreads(); }
    float inv = 1.f / red[0]; __syncthreads();

    const float* eb = emb + (size_t)b * NODES_PER * OUT_F;
    float a0 = 0.f, a1 = 0.f, a2 = 0.f, a3 = 0.f;
    for (int i = 0; i < NODES_PER; i += 4) {
        a0 = fmaf(w_sh[i + 0], eb[(size_t)(i + 0) * OUT_F + t], a0);
        a1 = fmaf(w_sh[i + 1], eb[(size_t)(i + 1) * OUT_F + t], a1);
        a2 = fmaf(w_sh[i + 2], eb[(size_t)(i + 2) * OUT_F + t], a2);
        a3 = fmaf(w_sh[i + 3], eb[(size_t)(i + 3) * OUT_F + t], a3);
    }
    float att = ((a0 + a1) + (a2 + a3)) * inv;

#pragma unroll
    for (int o = 0; o < 2; o++) {
        red[t] = att * Wa[o * OUT_F + t]; __syncthreads();
        for (int s = 64; s; s >>= 1) { if (t < s) red[t] += red[t + s]; __syncthreads(); }
        if (t == 0) audio_pred[b * 2 + o] = red[0] + ba[o];
        __syncthreads();
    }
}

// ---------------- launch ----------------
extern "C" void kernel_launch(void* const* d_in, const int* in_sizes, int n_in,
                              void* d_out, int out_size) {
    int wi = n_in - 14;
    const float* x   = (const float*)d_in[0];
    const float* W1  = (const float*)d_in[wi + 0];
    const float* as1 = (const float*)d_in[wi + 1];
    const float* ad1 = (const float*)d_in[wi + 2];
    const float* b1  = (const float*)d_in[wi + 3];
    const float* W2  = (const float*)d_in[wi + 4];
    const float* as2 = (const float*)d_in[wi + 5];
    const float* ad2 = (const float*)d_in[wi + 6];
    const float* b2  = (const float*)d_in[wi + 7];
    const float* Wt  = (const float*)d_in[wi + 8];
    const float* bt  = (const float*)d_in[wi + 9];
    const float* Wa  = (const float*)d_in[wi + 10];
    const float* ba  = (const float*)d_in[wi + 11];
    const float* Wn  = (const float*)d_in[wi + 12];
    const float* bn  = (const float*)d_in[wi + 13];

    float *h1raw, *h2raw, *emb, *als1p, *ald1p, *als2p, *ald2p, *logit;
    __nv_bfloat16 *xh, *xl, *h1h, *h1l, *w1h, *w1l, *w2h, *w2l;
    cudaGetSymbolAddress((void**)&h1raw, g_h1raw);
    cudaGetSymbolAddress((void**)&h2raw, g_h2raw);
    cudaGetSymbolAddress((void**)&emb,   g_emb);
    cudaGetSymbolAddress((void**)&xh,    g_xh);
    cudaGetSymbolAddress((void**)&xl,    g_xl);
    cudaGetSymbolAddress((void**)&h1h,   g_h1h);
    cudaGetSymbolAddress((void**)&h1l,   g_h1l);
    cudaGetSymbolAddress((void**)&w1h,   g_w1h);
    cudaGetSymbolAddress((void**)&w1l,   g_w1l);
    cudaGetSymbolAddress((void**)&w2h,   g_w2h);
    cudaGetSymbolAddress((void**)&w2l,   g_w2l);
    cudaGetSymbolAddress((void**)&als1p, g_als1p);
    cudaGetSymbolAddress((void**)&ald1p, g_ald1p);
    cudaGetSymbolAddress((void**)&als2p, g_als2p);
    cudaGetSymbolAddress((void**)&ald2p, g_ald2p);
    cudaGetSymbolAddress((void**)&logit, g_logit);

    float* node_pred  = (float*)d_out;
    float* audio_pred = node_pred + (size_t)N_NODES * NCLS;

    cudaFuncSetAttribute(gemm_mma<512>, cudaFuncAttributeMaxDynamicSharedMemorySize, GEMM_SMEM);
    cudaFuncSetAttribute(gemm_mma<256>, cudaFuncAttributeMaxDynamicSharedMemorySize, GEMM_SMEM);

    // splits
    {
        int n4 = (N_NODES * IN_F) / 4;
        split_bf16<<<(n4 + 255) / 256, 256>>>(x, xh, xl, n4);
    }
    split_bf16<<<(512 * 512 / 4 + 255) / 256, 256>>>(W1, w1h, w1l, 512 * 512 / 4);
    split_bf16<<<(256 * 256 / 4 + 255) / 256, 256>>>(W2, w2h, w2l, 256 * 256 / 4);

    // layer 1: h1raw = x @ W1^T [N,512] + fused al1 partials
    gemm_mma<512><<<dim3(4, N_NODES / 128), 256, GEMM_SMEM>>>(
        xh, xl, w1h, w1l, h1raw, 512, as1, ad1, als1p, ald1p);
    gat_combine_l1<<<N_NODES, 256>>>(h1raw, als1p, ald1p, b1, h1h, h1l);

    // layer 2: h2raw = h1 @ W2^T [N,256] + fused al2 partials (slot 0 complete per head)
    gemm_mma<256><<<dim3(2, N_NODES / 128), 256, GEMM_SMEM>>>(
        h1h, h1l, w2h, w2l, h2raw, 256, as2, ad2, als2p, ald2p);
    gat_l2_fused<<<N_NODES / 8, 256>>>(h2raw, als2p, ald2p, b2, Wn, bn, Wt, bt,
                                       emb, node_pred, logit);

    // audio head
    audio_pool<<<B_AUD, 128>>>(emb, logit, Wa, ba, audio_pred);
}

// round 7
// speedup vs baseline: 2.0896x; 1.0028x over previous
#include <cuda_runtime.h>
#include <cuda_bf16.h>
#include <cstdint>

#define N_NODES   131072
#define NODES_PER 2048
#define B_AUD     64
#define IN_F      512
#define HID_F     256
#define OUT_F     128
#define NHEAD     2
#define NCLS      7
#define NEG_SLOPE 0.2f
#define PART_STRIDE ((size_t)N_NODES * NHEAD)

// ---------------- scratch (static device allocations; no cudaMalloc) ----------------
__device__ float         g_h1raw[(size_t)N_NODES * NHEAD * HID_F]; // 256 MB
__device__ float         g_h2raw[(size_t)N_NODES * NHEAD * OUT_F]; // 128 MB
__device__ float         g_emb  [(size_t)N_NODES * OUT_F];         //  64 MB
__device__ __nv_bfloat16 g_xh  [(size_t)N_NODES * IN_F];
__device__ __nv_bfloat16 g_xl  [(size_t)N_NODES * IN_F];
__device__ __nv_bfloat16 g_h1h [(size_t)N_NODES * HID_F];
__device__ __nv_bfloat16 g_h1l [(size_t)N_NODES * HID_F];
__device__ __nv_bfloat16 g_w1h [512 * 512];
__device__ __nv_bfloat16 g_w1l [512 * 512];
__device__ __nv_bfloat16 g_w2h [256 * 256];
__device__ __nv_bfloat16 g_w2l [256 * 256];
__device__ float g_als1p[2 * PART_STRIDE];
__device__ float g_ald1p[2 * PART_STRIDE];
__device__ float g_als2p[2 * PART_STRIDE];
__device__ float g_ald2p[2 * PART_STRIDE];
__device__ float g_logit[N_NODES];

__device__ __forceinline__ float lrelu(float v) { return v > 0.f ? v : NEG_SLOPE * v; }

// ---------------- PTX helpers (portable: sm_80-class, compiles at compute_103) ----------------
__device__ __forceinline__ uint32_t smem_u32(const void* p) {
    uint32_t a;
    asm("{ .reg .u64 t; cvta.to.shared.u64 t, %1; cvt.u32.u64 %0, t; }" : "=r"(a) : "l"(p));
    return a;
}
__device__ __forceinline__ uint32_t swz(uint32_t b) { return b ^ ((b >> 3) & 0x70); }
__device__ __forceinline__ void cp16(uint32_t dst, const void* src) {
    asm volatile("cp.async.cg.shared.global [%0], [%1], 16;" :: "r"(dst), "l"(src));
}
__device__ __forceinline__ void ldm_x4(uint32_t* r, uint32_t addr) {
    asm volatile("ldmatrix.sync.aligned.m8n8.x4.shared.b16 {%0,%1,%2,%3}, [%4];"
                 : "=r"(r[0]), "=r"(r[1]), "=r"(r[2]), "=r"(r[3]) : "r"(addr));
}
__device__ __forceinline__ void mma_bf16(float* c, const uint32_t* a, uint32_t b0, uint32_t b1) {
    asm volatile(
        "mma.sync.aligned.m16n8k16.row.col.f32.bf16.bf16.f32 "
        "{%0,%1,%2,%3}, {%4,%5,%6,%7}, {%8,%9}, {%0,%1,%2,%3};"
        : "+f"(c[0]), "+f"(c[1]), "+f"(c[2]), "+f"(c[3])
        : "r"(a[0]), "r"(a[1]), "r"(a[2]), "r"(a[3]), "r"(b0), "r"(b1));
}

// ---------------- hi/lo bf16 split ----------------
__global__ __launch_bounds__(256)
void split_bf16(const float* __restrict__ a, __nv_bfloat16* __restrict__ hi,
                __nv_bfloat16* __restrict__ lo, int n4) {
    int i = blockIdx.x * 256 + threadIdx.x;
    if (i >= n4) return;
    float4 v = ((const float4*)a)[i];
    __nv_bfloat16 h0 = __float2bfloat16(v.x), h1 = __float2bfloat16(v.y);
    __nv_bfloat16 h2 = __float2bfloat16(v.z), h3 = __float2bfloat16(v.w);
    __nv_bfloat16 l0 = __float2bfloat16(v.x - __bfloat162float(h0));
    __nv_bfloat16 l1 = __float2bfloat16(v.y - __bfloat162float(h1));
    __nv_bfloat16 l2 = __float2bfloat16(v.z - __bfloat162float(h2));
    __nv_bfloat16 l3 = __float2bfloat16(v.w - __bfloat162float(h3));
    __nv_bfloat162 ph0; ph0.x = h0; ph0.y = h1;
    __nv_bfloat162 ph1; ph1.x = h2; ph1.y = h3;
    __nv_bfloat162 pl0; pl0.x = l0; pl0.y = l1;
    __nv_bfloat162 pl1; pl1.x = l2; pl1.y = l3;
    ((__nv_bfloat162*)hi)[2 * i]     = ph0;
    ((__nv_bfloat162*)hi)[2 * i + 1] = ph1;
    ((__nv_bfloat162*)lo)[2 * i]     = pl0;
    ((__nv_bfloat162*)lo)[2 * i + 1] = pl1;
}

// ---------------- split-bf16 warp-MMA GEMM, pass-grouped, fused al-epilogue ----------------
// C[Ntot,Mtot] = (Ah+Al)(Bh+Bl)^T approx = Ah*Bh + Ah*Bl + Al*Bh (fp32 acc).
// Pass 0 stages {Ah,Bh,Bl} -> 2 terms per A-frag; pass 1 stages {Al,Bh} -> 1 term.
// CTA 128x128, BK=64, 2-stage cp.async; 8 warps 2x4, warp tile 64x32.
// Epilogue: store C + per-(node,head) partial dot with a_src/a_dst.
#define STG_A     0
#define STG_BH    16384
#define STG_BL    32768
#define STG_BYTES 49152
#define GEMM_SMEM (2 * STG_BYTES)

template <int K>
__global__ __launch_bounds__(256, 2)
void gemm_mma(const __nv_bfloat16* __restrict__ Ah, const __nv_bfloat16* __restrict__ Al,
              const __nv_bfloat16* __restrict__ Bh, const __nv_bfloat16* __restrict__ Bl,
              float* __restrict__ C, int Mtot,
              const float* __restrict__ ws_flat, const float* __restrict__ wd_flat,
              float* __restrict__ alsP, float* __restrict__ aldP) {
    extern __shared__ __align__(1024) char smem[];
    uint32_t sb = smem_u32(smem);
    const int tid = threadIdx.x, wid = tid >> 5, lane = tid & 31;
    const int row0 = blockIdx.y * 128, col0 = blockIdx.x * 128;
    const int warp_m = wid >> 2;   // 0..1 -> 64 rows
    const int warp_n = wid & 3;    // 0..3 -> 32 cols
    constexpr int KCH = K / 64;
    constexpr int NIT = 2 * KCH;

    auto load = [&](int it) {
        int p  = it >= KCH;
        int kc = it - p * KCH;
        const __nv_bfloat16* A = p ? Al : Ah;
        uint32_t st = sb + (it & 1) * STG_BYTES;
#pragma unroll
        for (int i = 0; i < 4; i++) {
            int idx = tid + i * 256;
            int r = idx >> 3, c16 = idx & 7;
            uint32_t so = swz(r * 128 + c16 * 16);
            cp16(st + STG_A + so,  A  + (size_t)(row0 + r) * K + kc * 64 + c16 * 8);
            cp16(st + STG_BH + so, Bh + (size_t)(col0 + r) * K + kc * 64 + c16 * 8);
            if (!p)
                cp16(st + STG_BL + so, Bl + (size_t)(col0 + r) * K + kc * 64 + c16 * 8);
        }
        asm volatile("cp.async.commit_group;" ::: "memory");
    };

    float acc[4][4][4] = {};

    load(0);
    load(1);

    const int lrow = lane & 15, lhi = lane >> 4;

#pragma unroll 1
    for (int it = 0; it < NIT; it++) {
        asm volatile("cp.async.wait_group 1;" ::: "memory");
        __syncthreads();

        const int p = it >= KCH;
        uint32_t st = sb + (it & 1) * STG_BYTES;
#pragma unroll
        for (int kk = 0; kk < 4; kk++) {
            uint32_t a[4][4];
#pragma unroll
            for (int mt = 0; mt < 4; mt++)
                ldm_x4(a[mt], st + STG_A + swz((warp_m * 64 + mt * 16 + lrow) * 128 + (kk * 2 + lhi) * 16));
#pragma unroll
            for (int nt2 = 0; nt2 < 2; nt2++) {
                uint32_t bso = swz((warp_n * 32 + nt2 * 16 + lrow) * 128 + (kk * 2 + lhi) * 16);
                uint32_t b[4];
                ldm_x4(b, st + STG_BH + bso);
#pragma unroll
                for (int mt = 0; mt < 4; mt++) {
                    mma_bf16(acc[mt][nt2 * 2 + 0], a[mt], b[0], b[2]);
                    mma_bf16(acc[mt][nt2 * 2 + 1], a[mt], b[1], b[3]);
                }
                if (!p) {
                    uint32_t bl[4];
                    ldm_x4(bl, st + STG_BL + bso);
#pragma unroll
                    for (int mt = 0; mt < 4; mt++) {
                        mma_bf16(acc[mt][nt2 * 2 + 0], a[mt], bl[0], bl[2]);
                        mma_bf16(acc[mt][nt2 * 2 + 1], a[mt], bl[1], bl[3]);
                    }
                }
            }
        }
        __syncthreads();
        if (it + 2 < NIT) load(it + 2);
        else asm volatile("cp.async.commit_group;" ::: "memory");
    }

    // ---- epilogue 1: store C tile ----
#pragma unroll
    for (int mt = 0; mt < 4; mt++) {
        int row = row0 + warp_m * 64 + mt * 16 + (lane >> 2);
#pragma unroll
        for (int nt = 0; nt < 4; nt++) {
            int col = col0 + warp_n * 32 + nt * 8 + (lane & 3) * 2;
            float2 v0; v0.x = acc[mt][nt][0]; v0.y = acc[mt][nt][1];
            float2 v1; v1.x = acc[mt][nt][2]; v1.y = acc[mt][nt][3];
            *(float2*)&C[(size_t)row * Mtot + col]       = v0;
            *(float2*)&C[(size_t)(row + 8) * Mtot + col] = v1;
        }
    }

    // ---- epilogue 2: partial attention logits (dot with a_src / a_dst over this CTA's 128 cols) ----
    const int C_head = Mtot / NHEAD;
    const int head = col0 / C_head;
    const int slot = (col0 % C_head) >> 7;   // 0 or 1 (which 128-col half of the head)
    float* bufss = (float*)smem;             // [4 warp_n][128 rows]
    float* bufsd = bufss + 512;

#pragma unroll
    for (int mt = 0; mt < 4; mt++) {
        float ss0 = 0.f, ss1 = 0.f, sd0 = 0.f, sd1 = 0.f;
#pragma unroll
        for (int nt = 0; nt < 4; nt++) {
            int c = col0 + warp_n * 32 + nt * 8 + (lane & 3) * 2;
            float w0s = ws_flat[c], w1s = ws_flat[c + 1];
            float w0d = wd_flat[c], w1d = wd_flat[c + 1];
            ss0 = fmaf(acc[mt][nt][0], w0s, fmaf(acc[mt][nt][1], w1s, ss0));
            ss1 = fmaf(acc[mt][nt][2], w0s, fmaf(acc[mt][nt][3], w1s, ss1));
            sd0 = fmaf(acc[mt][nt][0], w0d, fmaf(acc[mt][nt][1], w1d, sd0));
            sd1 = fmaf(acc[mt][nt][2], w0d, fmaf(acc[mt][nt][3], w1d, sd1));
        }
#pragma unroll
        for (int off = 1; off <= 2; off <<= 1) {
            ss0 += __shfl_xor_sync(0xffffffffu, ss0, off);
            ss1 += __shfl_xor_sync(0xffffffffu, ss1, off);
            sd0 += __shfl_xor_sync(0xffffffffu, sd0, off);
            sd1 += __shfl_xor_sync(0xffffffffu, sd1, off);
        }
        if ((lane & 3) == 0) {
            int r0 = warp_m * 64 + mt * 16 + (lane >> 2);
            bufss[warp_n * 128 + r0]     = ss0;
            bufss[warp_n * 128 + r0 + 8] = ss1;
            bufsd[warp_n * 128 + r0]     = sd0;
            bufsd[warp_n * 128 + r0 + 8] = sd1;
        }
    }
    __syncthreads();
    if (tid < 128) {
        float ss = bufss[tid] + bufss[128 + tid] + bufss[256 + tid] + bufss[384 + tid];
        float sd = bufsd[tid] + bufsd[128 + tid] + bufsd[256 + tid] + bufsd[384 + tid];
        size_t node = (size_t)(row0 + tid);
        alsP[(size_t)slot * PART_STRIDE + node * NHEAD + head] = ss;
        aldP[(size_t)slot * PART_STRIDE + node * NHEAD + head] = sd;
    }
}

// ---------------- layer-1 GAT combine: one block per node, emits bf16 hi/lo split ----------------
__global__ __launch_bounds__(256)
void gat_combine_l1(const float* __restrict__ hraw, const float* __restrict__ alsP,
                    const float* __restrict__ aldP, const float* __restrict__ bias,
                    __nv_bfloat16* __restrict__ out_hi, __nv_bfloat16* __restrict__ out_lo) {
    int d = blockIdx.x, c = threadIdx.x;              // C = 256
    bool has_prev = (d % NODES_PER) != 0;
    float acc = 0.f;
#pragma unroll
    for (int hh = 0; hh < NHEAD; hh++) {
        size_t ai = (size_t)d * NHEAD + hh;
        float als = alsP[ai] + alsP[PART_STRIDE + ai];
        float ald = aldP[ai] + aldP[PART_STRIDE + ai];
        float es  = lrelu(als + ald);
        float h_self = hraw[(size_t)d * NHEAD * HID_F + hh * HID_F + c];
        if (has_prev) {
            size_t pi = (size_t)(d - 1) * NHEAD + hh;
            float alsp = alsP[pi] + alsP[PART_STRIDE + pi];
            float ep = lrelu(alsp + ald);
            float m  = fmaxf(es, ep);
            float xs = __expf(es - m), xp = __expf(ep - m);
            float inv = 1.f / (xs + xp);
            float h_prev = hraw[(size_t)(d - 1) * NHEAD * HID_F + hh * HID_F + c];
            acc += (xs * h_self + xp * h_prev) * inv;
        } else {
            acc += h_self;
        }
    }
    acc = acc * (1.f / NHEAD) + bias[c];
    acc = fmaxf(acc, 0.f);
    size_t gid = (size_t)d * HID_F + c;
    __nv_bfloat16 h = __float2bfloat16(acc);
    out_hi[gid] = h;
    out_lo[gid] = __float2bfloat16(acc - __bfloat162float(h));
}

// ---------------- layer-2 combine + node heads, warp per node ----------------
__global__ __launch_bounds__(256)
void gat_l2_fused(const float* __restrict__ h2raw, const float* __restrict__ alsP,
                  const float* __restrict__ aldP, const float* __restrict__ b2,
                  const float* __restrict__ Wn, const float* __restrict__ bn,
                  const float* __restrict__ Wt, const float* __restrict__ bt,
                  float* __restrict__ emb, float* __restrict__ node_pred,
                  float* __restrict__ logit) {
    int d    = (blockIdx.x * blockDim.x + threadIdx.x) >> 5;
    int lane = threadIdx.x & 31;
    if (d >= N_NODES) return;
    bool has_prev = (d % NODES_PER) != 0;

    float e[4] = {0.f, 0.f, 0.f, 0.f};
#pragma unroll
    for (int hh = 0; hh < NHEAD; hh++) {
        size_t ai = (size_t)d * NHEAD + hh;
        float als = alsP[ai];
        float ald = aldP[ai];
        float es  = lrelu(als + ald);
        float4 hs = *(const float4*)&h2raw[(size_t)d * NHEAD * OUT_F + hh * OUT_F + lane * 4];
        if (has_prev) {
            float alsp = alsP[(size_t)(d - 1) * NHEAD + hh];
            float ep = lrelu(alsp + ald);
            float m  = fmaxf(es, ep);
            float xs = __expf(es - m), xp = __expf(ep - m);
            float inv = 1.f / (xs + xp);
            float4 hp = *(const float4*)&h2raw[(size_t)(d - 1) * NHEAD * OUT_F + hh * OUT_F + lane * 4];
            e[0] += (xs * hs.x + xp * hp.x) * inv;
            e[1] += (xs * hs.y + xp * hp.y) * inv;
            e[2] += (xs * hs.z + xp * hp.z) * inv;
            e[3] += (xs * hs.w + xp * hp.w) * inv;
        } else {
            e[0] += hs.x; e[1] += hs.y; e[2] += hs.z; e[3] += hs.w;
        }
    }
    float4 bb = *(const float4*)&b2[lane * 4];
    e[0] = e[0] * 0.5f + bb.x;
    e[1] = e[1] * 0.5f + bb.y;
    e[2] = e[2] * 0.5f + bb.z;
    e[3] = e[3] * 0.5f + bb.w;
    float4 ev; ev.x = e[0]; ev.y = e[1]; ev.z = e[2]; ev.w = e[3];
    *(float4*)&emb[(size_t)d * OUT_F + lane * 4] = ev;

    // heads: 7 node classes + temporal logit
    float vals[8];
#pragma unroll
    for (int o = 0; o < 8; o++) {
        const float* w = (o < NCLS) ? &Wn[o * OUT_F] : Wt;
        float4 w4 = *(const float4*)&w[lane * 4];
        float s = e[0] * w4.x + e[1] * w4.y + e[2] * w4.z + e[3] * w4.w;
#pragma unroll
        for (int sh = 16; sh; sh >>= 1) s += __shfl_xor_sync(0xffffffffu, s, sh);
        vals[o] = s;
    }
    if (lane == 0) {
        float z[NCLS], m = -1e30f;
#pragma unroll
        for (int i = 0; i < NCLS; i++) { z[i] = vals[i] + bn[i]; m = fmaxf(m, z[i]); }
        float ssum = 0.f;
#pragma unroll
        for (int i = 0; i < NCLS; i++) { z[i] = __expf(z[i] - m); ssum += z[i]; }
        float inv = 1.f / ssum;
#pragma unroll
        for (int i = 0; i < NCLS; i++) node_pred[(size_t)d * NCLS + i] = z[i] * inv;
        logit[d] = vals[7] + bt[0];
    }
}

// ---------------- audio pooling ----------------
__global__ __launch_bounds__(128)
void audio_pool(const float* __restrict__ emb, const float* __restrict__ logit,
                const float* __restrict__ Wa, const float* __restrict__ ba,
                float* __restrict__ audio_pred) {
    __shared__ float w_sh[NODES_PER];
    __shared__ float red[128];
    int b = blockIdx.x, t = threadIdx.x;
    const float* lg = logit + b * NODES_PER;

    float m = -1e30f;
    for (int i = t; i < NODES_PER; i += 128) m = fmaxf(m, lg[i]);
    red[t] = m; __syncthreads();
    for (int s = 64; s; s >>= 1) { if (t < s) red[t] = fmaxf(red[t], red[t + s]); __syncthreads(); }
    m = red[0]; __syncthreads();

    float ssum = 0.f;
    for (int i = t; i < NODES_PER; i += 128) {
        float e = __expf(lg[i] - m);
        w_sh[i] = e;
        ssum += e;
    }
    red[t] = ssum; __syncthreads();
    for (int s = 64; s; s >>= 1) { if (t < s) red[t] += red[t + s]; __syncthreads(); }
    float inv = 1.f / red[0]; __syncthreads();

    const float* eb = emb + (size_t)b * NODES_PER * OUT_F;
    float a0 = 0.f, a1 = 0.f, a2 = 0.f, a3 = 0.f;
    for (int i = 0; i < NODES_PER; i += 4) {
        a0 = fmaf(w_sh[i + 0], eb[(size_t)(i + 0) * OUT_F + t], a0);
        a1 = fmaf(w_sh[i + 1], eb[(size_t)(i + 1) * OUT_F + t], a1);
        a2 = fmaf(w_sh[i + 2], eb[(size_t)(i + 2) * OUT_F + t], a2);
        a3 = fmaf(w_sh[i + 3], eb[(size_t)(i + 3) * OUT_F + t], a3);
    }
    float att = ((a0 + a1) + (a2 + a3)) * inv;

#pragma unroll
    for (int o = 0; o < 2; o++) {
        red[t] = att * Wa[o * OUT_F + t]; __syncthreads();
        for (int s = 64; s; s >>= 1) { if (t < s) red[t] += red[t + s]; __syncthreads(); }
        if (t == 0) audio_pred[b * 2 + o] = red[0] + ba[o];
        __syncthreads();
    }
}

// ---------------- launch ----------------
extern "C" void kernel_launch(void* const* d_in, const int* in_sizes, int n_in,
                              void* d_out, int out_size) {
    int wi = n_in - 14;
    const float* x   = (const float*)d_in[0];
    const float* W1  = (const float*)d_in[wi + 0];
    const float* as1 = (const float*)d_in[wi + 1];
    const float* ad1 = (const float*)d_in[wi + 2];
    const float* b1  = (const float*)d_in[wi + 3];
    const float* W2  = (const float*)d_in[wi + 4];
    const float* as2 = (const float*)d_in[wi + 5];
    const float* ad2 = (const float*)d_in[wi + 6];
    const float* b2  = (const float*)d_in[wi + 7];
    const float* Wt  = (const float*)d_in[wi + 8];
    const float* bt  = (const float*)d_in[wi + 9];
    const float* Wa  = (const float*)d_in[wi + 10];
    const float* ba  = (const float*)d_in[wi + 11];
    const float* Wn  = (const float*)d_in[wi + 12];
    const float* bn  = (const float*)d_in[wi + 13];

    float *h1raw, *h2raw, *emb, *als1p, *ald1p, *als2p, *ald2p, *logit;
    __nv_bfloat16 *xh, *xl, *h1h, *h1l, *w1h, *w1l, *w2h, *w2l;
    cudaGetSymbolAddress((void**)&h1raw, g_h1raw);
    cudaGetSymbolAddress((void**)&h2raw, g_h2raw);
    cudaGetSymbolAddress((void**)&emb,   g_emb);
    cudaGetSymbolAddress((void**)&xh,    g_xh);
    cudaGetSymbolAddress((void**)&xl,    g_xl);
    cudaGetSymbolAddress((void**)&h1h,   g_h1h);
    cudaGetSymbolAddress((void**)&h1l,   g_h1l);
    cudaGetSymbolAddress((void**)&w1h,   g_w1h);
    cudaGetSymbolAddress((void**)&w1l,   g_w1l);
    cudaGetSymbolAddress((void**)&w2h,   g_w2h);
    cudaGetSymbolAddress((void**)&w2l,   g_w2l);
    cudaGetSymbolAddress((void**)&als1p, g_als1p);
    cudaGetSymbolAddress((void**)&ald1p, g_ald1p);
    cudaGetSymbolAddress((void**)&als2p, g_als2p);
    cudaGetSymbolAddress((void**)&ald2p, g_ald2p);
    cudaGetSymbolAddress((void**)&logit, g_logit);

    float* node_pred  = (float*)d_out;
    float* audio_pred = node_pred + (size_t)N_NODES * NCLS;

    cudaFuncSetAttribute(gemm_mma<512>, cudaFuncAttributeMaxDynamicSharedMemorySize, GEMM_SMEM);
    cudaFuncSetAttribute(gemm_mma<256>, cudaFuncAttributeMaxDynamicSharedMemorySize, GEMM_SMEM);

    // splits
    {
        int n4 = (N_NODES * IN_F) / 4;
        split_bf16<<<(n4 + 255) / 256, 256>>>(x, xh, xl, n4);
    }
    split_bf16<<<(512 * 512 / 4 + 255) / 256, 256>>>(W1, w1h, w1l, 512 * 512 / 4);
    split_bf16<<<(256 * 256 / 4 + 255) / 256, 256>>>(W2, w2h, w2l, 256 * 256 / 4);

    // layer 1: h1raw = x @ W1^T [N,512] + fused al1 partials
    gemm_mma<512><<<dim3(4, N_NODES / 128), 256, GEMM_SMEM>>>(
        xh, xl, w1h, w1l, h1raw, 512, as1, ad1, als1p, ald1p);
    gat_combine_l1<<<N_NODES, 256>>>(h1raw, als1p, ald1p, b1, h1h, h1l);

    // layer 2: h2raw = h1 @ W2^T [N,256] + fused al2 partials (slot 0 complete per head)
    gemm_mma<256><<<dim3(2, N_NODES / 128), 256, GEMM_SMEM>>>(
        h1h, h1l, w2h, w2l, h2raw, 256, as2, ad2, als2p, ald2p);
    gat_l2_fused<<<N_NODES / 8, 256>>>(h2raw, als2p, ald2p, b2, Wn, bn, Wt, bt,
                                       emb, node_pred, logit);

    // audio head
    audio_pool<<<B_AUD, 128>>>(emb, logit, Wa, ba, audio_pred);
}

// round 8
// speedup vs baseline: 2.4088x; 1.1528x over previous
#include <cuda_runtime.h>
#include <cuda_fp16.h>
#include <cstdint>

#define N_NODES   131072
#define NODES_PER 2048
#define B_AUD     64
#define IN_F      512
#define HID_F     256
#define OUT_F     128
#define NHEAD     2
#define NCLS      7
#define NEG_SLOPE 0.2f
#define PART_STRIDE ((size_t)N_NODES * NHEAD)

// ---------------- scratch (static device allocations; no cudaMalloc) ----------------
__device__ float  g_h1raw[(size_t)N_NODES * NHEAD * HID_F]; // 256 MB
__device__ float  g_h2raw[(size_t)N_NODES * NHEAD * OUT_F]; // 128 MB
__device__ float  g_emb  [(size_t)N_NODES * OUT_F];         //  64 MB
__device__ __half g_xh  [(size_t)N_NODES * IN_F];
__device__ __half g_xl  [(size_t)N_NODES * IN_F];
__device__ __half g_h1h [(size_t)N_NODES * HID_F];
__device__ __half g_h1l [(size_t)N_NODES * HID_F];
__device__ __half g_w1h [512 * 512];
__device__ __half g_w2h [256 * 256];
__device__ float g_als1p[2 * PART_STRIDE];
__device__ float g_ald1p[2 * PART_STRIDE];
__device__ float g_als2p[2 * PART_STRIDE];
__device__ float g_ald2p[2 * PART_STRIDE];
__device__ float g_logit[N_NODES];

__device__ __forceinline__ float lrelu(float v) { return v > 0.f ? v : NEG_SLOPE * v; }

// ---------------- PTX helpers (portable: sm_80-class, compiles at compute_103) ----------------
__device__ __forceinline__ uint32_t smem_u32(const void* p) {
    uint32_t a;
    asm("{ .reg .u64 t; cvta.to.shared.u64 t, %1; cvt.u32.u64 %0, t; }" : "=r"(a) : "l"(p));
    return a;
}
__device__ __forceinline__ uint32_t swz(uint32_t b) { return b ^ ((b >> 3) & 0x70); }
__device__ __forceinline__ void cp16(uint32_t dst, const void* src) {
    asm volatile("cp.async.cg.shared.global [%0], [%1], 16;" :: "r"(dst), "l"(src));
}
__device__ __forceinline__ void ldm_x4(uint32_t* r, uint32_t addr) {
    asm volatile("ldmatrix.sync.aligned.m8n8.x4.shared.b16 {%0,%1,%2,%3}, [%4];"
                 : "=r"(r[0]), "=r"(r[1]), "=r"(r[2]), "=r"(r[3]) : "r"(addr));
}
__device__ __forceinline__ void mma_f16(float* c, const uint32_t* a, uint32_t b0, uint32_t b1) {
    asm volatile(
        "mma.sync.aligned.m16n8k16.row.col.f32.f16.f16.f32 "
        "{%0,%1,%2,%3}, {%4,%5,%6,%7}, {%8,%9}, {%0,%1,%2,%3};"
        : "+f"(c[0]), "+f"(c[1]), "+f"(c[2]), "+f"(c[3])
        : "r"(a[0]), "r"(a[1]), "r"(a[2]), "r"(a[3]), "r"(b0), "r"(b1));
}

// ---------------- fp16 hi/lo split (activations, exact to ~22 bits) ----------------
__global__ __launch_bounds__(256)
void split_f16(const float* __restrict__ a, __half* __restrict__ hi,
               __half* __restrict__ lo, int n4) {
    int i = blockIdx.x * 256 + threadIdx.x;
    if (i >= n4) return;
    float4 v = ((const float4*)a)[i];
    __half h0 = __float2half(v.x), h1 = __float2half(v.y);
    __half h2 = __float2half(v.z), h3 = __float2half(v.w);
    __half l0 = __float2half(v.x - __half2float(h0));
    __half l1 = __float2half(v.y - __half2float(h1));
    __half l2 = __float2half(v.z - __half2float(h2));
    __half l3 = __float2half(v.w - __half2float(h3));
    __half2 ph0; ph0.x = h0; ph0.y = h1;
    __half2 ph1; ph1.x = h2; ph1.y = h3;
    __half2 pl0; pl0.x = l0; pl0.y = l1;
    __half2 pl1; pl1.x = l2; pl1.y = l3;
    ((__half2*)hi)[2 * i]     = ph0;
    ((__half2*)hi)[2 * i + 1] = ph1;
    ((__half2*)lo)[2 * i]     = pl0;
    ((__half2*)lo)[2 * i + 1] = pl1;
}

// ---------------- fp32 -> fp16 convert (weights) ----------------
__global__ __launch_bounds__(256)
void cvt_f16(const float* __restrict__ a, __half* __restrict__ o, int n4) {
    int i = blockIdx.x * 256 + threadIdx.x;
    if (i >= n4) return;
    float4 v = ((const float4*)a)[i];
    __half2 p0; p0.x = __float2half(v.x); p0.y = __float2half(v.y);
    __half2 p1; p1.x = __float2half(v.z); p1.y = __float2half(v.w);
    ((__half2*)o)[2 * i]     = p0;
    ((__half2*)o)[2 * i + 1] = p1;
}

// ---------------- split-fp16 warp-MMA GEMM: C = (Ah+Al) * Bh^T, fused al-epilogue ----------------
// CTA 128x128, BK=64, 2-stage cp.async; 8 warps 2x4, warp tile 64x32.
// Both terms share B fragments -> 32 MMAs / 10 ldmatrix per kk.
#define STG_AH    0
#define STG_AL    16384
#define STG_B     32768
#define STG_BYTES 49152
#define GEMM_SMEM (2 * STG_BYTES)

template <int K>
__global__ __launch_bounds__(256, 2)
void gemm_mma(const __half* __restrict__ Ah, const __half* __restrict__ Al,
              const __half* __restrict__ Bh,
              float* __restrict__ C, int Mtot,
              const float* __restrict__ ws_flat, const float* __restrict__ wd_flat,
              float* __restrict__ alsP, float* __restrict__ aldP) {
    extern __shared__ __align__(1024) char smem[];
    uint32_t sb = smem_u32(smem);
    const int tid = threadIdx.x, wid = tid >> 5, lane = tid & 31;
    const int row0 = blockIdx.y * 128, col0 = blockIdx.x * 128;
    const int warp_m = wid >> 2;   // 0..1 -> 64 rows
    const int warp_n = wid & 3;    // 0..3 -> 32 cols
    constexpr int NIT = K / 64;

    auto load = [&](int it) {
        uint32_t st = sb + (it & 1) * STG_BYTES;
#pragma unroll
        for (int i = 0; i < 4; i++) {
            int idx = tid + i * 256;
            int r = idx >> 3, c16 = idx & 7;
            uint32_t so = swz(r * 128 + c16 * 16);
            cp16(st + STG_AH + so, Ah + (size_t)(row0 + r) * K + it * 64 + c16 * 8);
            cp16(st + STG_AL + so, Al + (size_t)(row0 + r) * K + it * 64 + c16 * 8);
            cp16(st + STG_B  + so, Bh + (size_t)(col0 + r) * K + it * 64 + c16 * 8);
        }
        asm volatile("cp.async.commit_group;" ::: "memory");
    };

    float acc[4][4][4] = {};

    load(0);
    if (NIT > 1) load(1);

    const int lrow = lane & 15, lhi = lane >> 4;

#pragma unroll 1
    for (int it = 0; it < NIT; it++) {
        asm volatile("cp.async.wait_group 1;" ::: "memory");
        __syncthreads();

        uint32_t st = sb + (it & 1) * STG_BYTES;
#pragma unroll
        for (int kk = 0; kk < 4; kk++) {
            uint32_t ah[4][4], al[4][4];
#pragma unroll
            for (int mt = 0; mt < 4; mt++) {
                uint32_t aso = swz((warp_m * 64 + mt * 16 + lrow) * 128 + (kk * 2 + lhi) * 16);
                ldm_x4(ah[mt], st + STG_AH + aso);
                ldm_x4(al[mt], st + STG_AL + aso);
            }
#pragma unroll
            for (int nt2 = 0; nt2 < 2; nt2++) {
                uint32_t b[4];
                ldm_x4(b, st + STG_B + swz((warp_n * 32 + nt2 * 16 + lrow) * 128 + (kk * 2 + lhi) * 16));
#pragma unroll
                for (int mt = 0; mt < 4; mt++) {
                    mma_f16(acc[mt][nt2 * 2 + 0], ah[mt], b[0], b[2]);
                    mma_f16(acc[mt][nt2 * 2 + 1], ah[mt], b[1], b[3]);
                    mma_f16(acc[mt][nt2 * 2 + 0], al[mt], b[0], b[2]);
                    mma_f16(acc[mt][nt2 * 2 + 1], al[mt], b[1], b[3]);
                }
            }
        }
        __syncthreads();
        if (it + 2 < NIT) load(it + 2);
        else asm volatile("cp.async.commit_group;" ::: "memory");
    }

    // ---- epilogue 1: store C tile ----
#pragma unroll
    for (int mt = 0; mt < 4; mt++) {
        int row = row0 + warp_m * 64 + mt * 16 + (lane >> 2);
#pragma unroll
        for (int nt = 0; nt < 4; nt++) {
            int col = col0 + warp_n * 32 + nt * 8 + (lane & 3) * 2;
            float2 v0; v0.x = acc[mt][nt][0]; v0.y = acc[mt][nt][1];
            float2 v1; v1.x = acc[mt][nt][2]; v1.y = acc[mt][nt][3];
            *(float2*)&C[(size_t)row * Mtot + col]       = v0;
            *(float2*)&C[(size_t)(row + 8) * Mtot + col] = v1;
        }
    }

    // ---- epilogue 2: partial attention logits (dot with a_src / a_dst over this CTA's 128 cols) ----
    const int C_head = Mtot / NHEAD;
    const int head = col0 / C_head;
    const int slot = (col0 % C_head) >> 7;   // 0 or 1 (which 128-col half of the head)
    float* bufss = (float*)smem;             // [4 warp_n][128 rows]
    float* bufsd = bufss + 512;

#pragma unroll
    for (int mt = 0; mt < 4; mt++) {
        float ss0 = 0.f, ss1 = 0.f, sd0 = 0.f, sd1 = 0.f;
#pragma unroll
        for (int nt = 0; nt < 4; nt++) {
            int c = col0 + warp_n * 32 + nt * 8 + (lane & 3) * 2;
            float w0s = ws_flat[c], w1s = ws_flat[c + 1];
            float w0d = wd_flat[c], w1d = wd_flat[c + 1];
            ss0 = fmaf(acc[mt][nt][0], w0s, fmaf(acc[mt][nt][1], w1s, ss0));
            ss1 = fmaf(acc[mt][nt][2], w0s, fmaf(acc[mt][nt][3], w1s, ss1));
            sd0 = fmaf(acc[mt][nt][0], w0d, fmaf(acc[mt][nt][1], w1d, sd0));
            sd1 = fmaf(acc[mt][nt][2], w0d, fmaf(acc[mt][nt][3], w1d, sd1));
        }
#pragma unroll
        for (int off = 1; off <= 2; off <<= 1) {
            ss0 += __shfl_xor_sync(0xffffffffu, ss0, off);
            ss1 += __shfl_xor_sync(0xffffffffu, ss1, off);
            sd0 += __shfl_xor_sync(0xffffffffu, sd0, off);
            sd1 += __shfl_xor_sync(0xffffffffu, sd1, off);
        }
        if ((lane & 3) == 0) {
            int r0 = warp_m * 64 + mt * 16 + (lane >> 2);
            bufss[warp_n * 128 + r0]     = ss0;
            bufss[warp_n * 128 + r0 + 8] = ss1;
            bufsd[warp_n * 128 + r0]     = sd0;
            bufsd[warp_n * 128 + r0 + 8] = sd1;
        }
    }
    __syncthreads();
    if (tid < 128) {
        float ss = bufss[tid] + bufss[128 + tid] + bufss[256 + tid] + bufss[384 + tid];
        float sd = bufsd[tid] + bufsd[128 + tid] + bufsd[256 + tid] + bufsd[384 + tid];
        size_t node = (size_t)(row0 + tid);
        alsP[(size_t)slot * PART_STRIDE + node * NHEAD + head] = ss;
        aldP[(size_t)slot * PART_STRIDE + node * NHEAD + head] = sd;
    }
}

// ---------------- layer-1 GAT combine: one block per node, emits fp16 hi/lo split ----------------
__global__ __launch_bounds__(256)
void gat_combine_l1(const float* __restrict__ hraw, const float* __restrict__ alsP,
                    const float* __restrict__ aldP, const float* __restrict__ bias,
                    __half* __restrict__ out_hi, __half* __restrict__ out_lo) {
    int d = blockIdx.x, c = threadIdx.x;              // C = 256
    bool has_prev = (d % NODES_PER) != 0;
    float acc = 0.f;
#pragma unroll
    for (int hh = 0; hh < NHEAD; hh++) {
        size_t ai = (size_t)d * NHEAD + hh;
        float als = alsP[ai] + alsP[PART_STRIDE + ai];
        float ald = aldP[ai] + aldP[PART_STRIDE + ai];
        float es  = lrelu(als + ald);
        float h_self = hraw[(size_t)d * NHEAD * HID_F + hh * HID_F + c];
        if (has_prev) {
            size_t pi = (size_t)(d - 1) * NHEAD + hh;
            float alsp = alsP[pi] + alsP[PART_STRIDE + pi];
            float ep = lrelu(alsp + ald);
            float m  = fmaxf(es, ep);
            float xs = __expf(es - m), xp = __expf(ep - m);
            float inv = 1.f / (xs + xp);
            float h_prev = hraw[(size_t)(d - 1) * NHEAD * HID_F + hh * HID_F + c];
            acc += (xs * h_self + xp * h_prev) * inv;
        } else {
            acc += h_self;
        }
    }
    acc = acc * (1.f / NHEAD) + bias[c];
    acc = fmaxf(acc, 0.f);
    size_t gid = (size_t)d * HID_F + c;
    __half h = __float2half(acc);
    out_hi[gid] = h;
    out_lo[gid] = __float2half(acc - __half2float(h));
}

// ---------------- layer-2 combine + node heads, warp per node ----------------
__global__ __launch_bounds__(256)
void gat_l2_fused(const float* __restrict__ h2raw, const float* __restrict__ alsP,
                  const float* __restrict__ aldP, const float* __restrict__ b2,
                  const float* __restrict__ Wn, const float* __restrict__ bn,
                  const float* __restrict__ Wt, const float* __restrict__ bt,
                  float* __restrict__ emb, float* __restrict__ node_pred,
                  float* __restrict__ logit) {
    int d    = (blockIdx.x * blockDim.x + threadIdx.x) >> 5;
    int lane = threadIdx.x & 31;
    if (d >= N_NODES) return;
    bool has_prev = (d % NODES_PER) != 0;

    float e[4] = {0.f, 0.f, 0.f, 0.f};
#pragma unroll
    for (int hh = 0; hh < NHEAD; hh++) {
        size_t ai = (size_t)d * NHEAD + hh;
        float als = alsP[ai];
        float ald = aldP[ai];
        float es  = lrelu(als + ald);
        float4 hs = *(const float4*)&h2raw[(size_t)d * NHEAD * OUT_F + hh * OUT_F + lane * 4];
        if (has_prev) {
            float alsp = alsP[(size_t)(d - 1) * NHEAD + hh];
            float ep = lrelu(alsp + ald);
            float m  = fmaxf(es, ep);
            float xs = __expf(es - m), xp = __expf(ep - m);
            float inv = 1.f / (xs + xp);
            float4 hp = *(const float4*)&h2raw[(size_t)(d - 1) * NHEAD * OUT_F + hh * OUT_F + lane * 4];
            e[0] += (xs * hs.x + xp * hp.x) * inv;
            e[1] += (xs * hs.y + xp * hp.y) * inv;
            e[2] += (xs * hs.z + xp * hp.z) * inv;
            e[3] += (xs * hs.w + xp * hp.w) * inv;
        } else {
            e[0] += hs.x; e[1] += hs.y; e[2] += hs.z; e[3] += hs.w;
        }
    }
    float4 bb = *(const float4*)&b2[lane * 4];
    e[0] = e[0] * 0.5f + bb.x;
    e[1] = e[1] * 0.5f + bb.y;
    e[2] = e[2] * 0.5f + bb.z;
    e[3] = e[3] * 0.5f + bb.w;
    float4 ev; ev.x = e[0]; ev.y = e[1]; ev.z = e[2]; ev.w = e[3];
    *(float4*)&emb[(size_t)d * OUT_F + lane * 4] = ev;

    // heads: 7 node classes + temporal logit
    float vals[8];
#pragma unroll
    for (int o = 0; o < 8; o++) {
        const float* w = (o < NCLS) ? &Wn[o * OUT_F] : Wt;
        float4 w4 = *(const float4*)&w[lane * 4];
        float s = e[0] * w4.x + e[1] * w4.y + e[2] * w4.z + e[3] * w4.w;
#pragma unroll
        for (int sh = 16; sh; sh >>= 1) s += __shfl_xor_sync(0xffffffffu, s, sh);
        vals[o] = s;
    }
    if (lane == 0) {
        float z[NCLS], m = -1e30f;
#pragma unroll
        for (int i = 0; i < NCLS; i++) { z[i] = vals[i] + bn[i]; m = fmaxf(m, z[i]); }
        float ssum = 0.f;
#pragma unroll
        for (int i = 0; i < NCLS; i++) { z[i] = __expf(z[i] - m); ssum += z[i]; }
        float inv = 1.f / ssum;
#pragma unroll
        for (int i = 0; i < NCLS; i++) node_pred[(size_t)d * NCLS + i] = z[i] * inv;
        logit[d] = vals[7] + bt[0];
    }
}

// ---------------- audio pooling ----------------
__global__ __launch_bounds__(128)
void audio_pool(const float* __restrict__ emb, const float* __restrict__ logit,
                const float* __restrict__ Wa, const float* __restrict__ ba,
                float* __restrict__ audio_pred) {
    __shared__ float w_sh[NODES_PER];
    __shared__ float red[128];
    int b = blockIdx.x, t = threadIdx.x;
    const float* lg = logit + b * NODES_PER;

    float m = -1e30f;
    for (int i = t; i < NODES_PER; i += 128) m = fmaxf(m, lg[i]);
    red[t] = m; __syncthreads();
    for (int s = 64; s; s >>= 1) { if (t < s) red[t] = fmaxf(red[t], red[t + s]); __syncthreads(); }
    m = red[0]; __syncthreads();

    float ssum = 0.f;
    for (int i = t; i < NODES_PER; i += 128) {
        float e = __expf(lg[i] - m);
        w_sh[i] = e;
        ssum += e;
    }
    red[t] = ssum; __syncthreads();
    for (int s = 64; s; s >>= 1) { if (t < s) red[t] += red[t + s]; __syncthreads(); }
    float inv = 1.f / red[0]; __syncthreads();

    const float* eb = emb + (size_t)b * NODES_PER * OUT_F;
    float a0 = 0.f, a1 = 0.f, a2 = 0.f, a3 = 0.f;
    for (int i = 0; i < NODES_PER; i += 4) {
        a0 = fmaf(w_sh[i + 0], eb[(size_t)(i + 0) * OUT_F + t], a0);
        a1 = fmaf(w_sh[i + 1], eb[(size_t)(i + 1) * OUT_F + t], a1);
        a2 = fmaf(w_sh[i + 2], eb[(size_t)(i + 2) * OUT_F + t], a2);
        a3 = fmaf(w_sh[i + 3], eb[(size_t)(i + 3) * OUT_F + t], a3);
    }
    float att = ((a0 + a1) + (a2 + a3)) * inv;

#pragma unroll
    for (int o = 0; o < 2; o++) {
        red[t] = att * Wa[o * OUT_F + t]; __syncthreads();
        for (int s = 64; s; s >>= 1) { if (t < s) red[t] += red[t + s]; __syncthreads(); }
        if (t == 0) audio_pred[b * 2 + o] = red[0] + ba[o];
        __syncthreads();
    }
}

// ---------------- launch ----------------
extern "C" void kernel_launch(void* const* d_in, const int* in_sizes, int n_in,
                              void* d_out, int out_size) {
    int wi = n_in - 14;
    const float* x   = (const float*)d_in[0];
    const float* W1  = (const float*)d_in[wi + 0];
    const float* as1 = (const float*)d_in[wi + 1];
    const float* ad1 = (const float*)d_in[wi + 2];
    const float* b1  = (const float*)d_in[wi + 3];
    const float* W2  = (const float*)d_in[wi + 4];
    const float* as2 = (const float*)d_in[wi + 5];
    const float* ad2 = (const float*)d_in[wi + 6];
    const float* b2  = (const float*)d_in[wi + 7];
    const float* Wt  = (const float*)d_in[wi + 8];
    const float* bt  = (const float*)d_in[wi + 9];
    const float* Wa  = (const float*)d_in[wi + 10];
    const float* ba  = (const float*)d_in[wi + 11];
    const float* Wn  = (const float*)d_in[wi + 12];
    const float* bn  = (const float*)d_in[wi + 13];

    float *h1raw, *h2raw, *emb, *als1p, *ald1p, *als2p, *ald2p, *logit;
    __half *xh, *xl, *h1h, *h1l, *w1h, *w2h;
    cudaGetSymbolAddress((void**)&h1raw, g_h1raw);
    cudaGetSymbolAddress((void**)&h2raw, g_h2raw);
    cudaGetSymbolAddress((void**)&emb,   g_emb);
    cudaGetSymbolAddress((void**)&xh,    g_xh);
    cudaGetSymbolAddress((void**)&xl,    g_xl);
    cudaGetSymbolAddress((void**)&h1h,   g_h1h);
    cudaGetSymbolAddress((void**)&h1l,   g_h1l);
    cudaGetSymbolAddress((void**)&w1h,   g_w1h);
    cudaGetSymbolAddress((void**)&w2h,   g_w2h);
    cudaGetSymbolAddress((void**)&als1p, g_als1p);
    cudaGetSymbolAddress((void**)&ald1p, g_ald1p);
    cudaGetSymbolAddress((void**)&als2p, g_als2p);
    cudaGetSymbolAddress((void**)&ald2p, g_ald2p);
    cudaGetSymbolAddress((void**)&logit, g_logit);

    float* node_pred  = (float*)d_out;
    float* audio_pred = node_pred + (size_t)N_NODES * NCLS;

    cudaFuncSetAttribute(gemm_mma<512>, cudaFuncAttributeMaxDynamicSharedMemorySize, GEMM_SMEM);
    cudaFuncSetAttribute(gemm_mma<256>, cudaFuncAttributeMaxDynamicSharedMemorySize, GEMM_SMEM);

    // conversions
    {
        int n4 = (N_NODES * IN_F) / 4;
        split_f16<<<(n4 + 255) / 256, 256>>>(x, xh, xl, n4);
    }
    cvt_f16<<<(512 * 512 / 4 + 255) / 256, 256>>>(W1, w1h, 512 * 512 / 4);
    cvt_f16<<<(256 * 256 / 4 + 255) / 256, 256>>>(W2, w2h, 256 * 256 / 4);

    // layer 1: h1raw = x @ W1^T [N,512] + fused al1 partials
    gemm_mma<512><<<dim3(4, N_NODES / 128), 256, GEMM_SMEM>>>(
        xh, xl, w1h, h1raw, 512, as1, ad1, als1p, ald1p);
    gat_combine_l1<<<N_NODES, 256>>>(h1raw, als1p, ald1p, b1, h1h, h1l);

    // layer 2: h2raw = h1 @ W2^T [N,256] + fused al2 partials
    gemm_mma<256><<<dim3(2, N_NODES / 128), 256, GEMM_SMEM>>>(
        h1h, h1l, w2h, h2raw, 256, as2, ad2, als2p, ald2p);
    gat_l2_fused<<<N_NODES / 8, 256>>>(h2raw, als2p, ald2p, b2, Wn, bn, Wt, bt,
                                       emb, node_pred, logit);

    // audio head
    audio_pool<<<B_AUD, 128>>>(emb, logit, Wa, ba, audio_pred);
}

// round 9
// speedup vs baseline: 3.2375x; 1.3440x over previous
#include <cuda_runtime.h>
#include <cuda_fp16.h>
#include <cstdint>

#define N_NODES   131072
#define NODES_PER 2048
#define B_AUD     64
#define IN_F      512
#define HID_F     256
#define OUT_F     128
#define NHEAD     2
#define NCLS      7
#define NEG_SLOPE 0.2f
#define PART_STRIDE ((size_t)N_NODES * NHEAD)

// ---------------- scratch (static device allocations; no cudaMalloc) ----------------
__device__ float  g_h1raw[(size_t)N_NODES * NHEAD * HID_F]; // 256 MB
__device__ float  g_h2raw[(size_t)N_NODES * NHEAD * OUT_F]; // 128 MB
__device__ float  g_emb  [(size_t)N_NODES * OUT_F];         //  64 MB
__device__ __half g_xh  [(size_t)N_NODES * IN_F];
__device__ __half g_xl  [(size_t)N_NODES * IN_F];
__device__ __half g_h1h [(size_t)N_NODES * HID_F];
__device__ __half g_h1l [(size_t)N_NODES * HID_F];
__device__ __half g_w1h [512 * 512];
__device__ __half g_w2h [256 * 256];
__device__ float g_als1p[2 * PART_STRIDE];
__device__ float g_ald1p[2 * PART_STRIDE];
__device__ float g_als2p[2 * PART_STRIDE];
__device__ float g_ald2p[2 * PART_STRIDE];
__device__ float g_logit[N_NODES];
__device__ float g_aw   [B_AUD * NODES_PER];   // per-audio softmax weights
__device__ float g_att  [B_AUD * OUT_F];       // attended embeddings

__device__ __forceinline__ float lrelu(float v) { return v > 0.f ? v : NEG_SLOPE * v; }

// ---------------- PTX helpers (portable: sm_80-class, compiles at compute_103) ----------------
__device__ __forceinline__ uint32_t smem_u32(const void* p) {
    uint32_t a;
    asm("{ .reg .u64 t; cvta.to.shared.u64 t, %1; cvt.u32.u64 %0, t; }" : "=r"(a) : "l"(p));
    return a;
}
__device__ __forceinline__ uint32_t swz(uint32_t b) { return b ^ ((b >> 3) & 0x70); }
__device__ __forceinline__ void cp16(uint32_t dst, const void* src) {
    asm volatile("cp.async.cg.shared.global [%0], [%1], 16;" :: "r"(dst), "l"(src));
}
__device__ __forceinline__ void ldm_x4(uint32_t* r, uint32_t addr) {
    asm volatile("ldmatrix.sync.aligned.m8n8.x4.shared.b16 {%0,%1,%2,%3}, [%4];"
                 : "=r"(r[0]), "=r"(r[1]), "=r"(r[2]), "=r"(r[3]) : "r"(addr));
}
__device__ __forceinline__ void mma_f16(float* c, const uint32_t* a, uint32_t b0, uint32_t b1) {
    asm volatile(
        "mma.sync.aligned.m16n8k16.row.col.f32.f16.f16.f32 "
        "{%0,%1,%2,%3}, {%4,%5,%6,%7}, {%8,%9}, {%0,%1,%2,%3};"
        : "+f"(c[0]), "+f"(c[1]), "+f"(c[2]), "+f"(c[3])
        : "r"(a[0]), "r"(a[1]), "r"(a[2]), "r"(a[3]), "r"(b0), "r"(b1));
}

// ---------------- fp16 hi/lo split (activations, exact to ~22 bits) ----------------
__global__ __launch_bounds__(256)
void split_f16(const float* __restrict__ a, __half* __restrict__ hi,
               __half* __restrict__ lo, int n4) {
    int i = blockIdx.x * 256 + threadIdx.x;
    if (i >= n4) return;
    float4 v = ((const float4*)a)[i];
    __half h0 = __float2half(v.x), h1 = __float2half(v.y);
    __half h2 = __float2half(v.z), h3 = __float2half(v.w);
    __half l0 = __float2half(v.x - __half2float(h0));
    __half l1 = __float2half(v.y - __half2float(h1));
    __half l2 = __float2half(v.z - __half2float(h2));
    __half l3 = __float2half(v.w - __half2float(h3));
    __half2 ph0; ph0.x = h0; ph0.y = h1;
    __half2 ph1; ph1.x = h2; ph1.y = h3;
    __half2 pl0; pl0.x = l0; pl0.y = l1;
    __half2 pl1; pl1.x = l2; pl1.y = l3;
    ((__half2*)hi)[2 * i]     = ph0;
    ((__half2*)hi)[2 * i + 1] = ph1;
    ((__half2*)lo)[2 * i]     = pl0;
    ((__half2*)lo)[2 * i + 1] = pl1;
}

// ---------------- fp32 -> fp16 convert (weights) ----------------
__global__ __launch_bounds__(256)
void cvt_f16(const float* __restrict__ a, __half* __restrict__ o, int n4) {
    int i = blockIdx.x * 256 + threadIdx.x;
    if (i >= n4) return;
    float4 v = ((const float4*)a)[i];
    __half2 p0; p0.x = __float2half(v.x); p0.y = __float2half(v.y);
    __half2 p1; p1.x = __float2half(v.z); p1.y = __float2half(v.w);
    ((__half2*)o)[2 * i]     = p0;
    ((__half2*)o)[2 * i + 1] = p1;
}

// ---------------- split-fp16 warp-MMA GEMM: C = (Ah+Al) * Bh^T, fused al-epilogue ----------------
#define STG_AH    0
#define STG_AL    16384
#define STG_B     32768
#define STG_BYTES 49152
#define GEMM_SMEM (2 * STG_BYTES)

template <int K>
__global__ __launch_bounds__(256, 2)
void gemm_mma(const __half* __restrict__ Ah, const __half* __restrict__ Al,
              const __half* __restrict__ Bh,
              float* __restrict__ C, int Mtot,
              const float* __restrict__ ws_flat, const float* __restrict__ wd_flat,
              float* __restrict__ alsP, float* __restrict__ aldP) {
    extern __shared__ __align__(1024) char smem[];
    uint32_t sb = smem_u32(smem);
    const int tid = threadIdx.x, wid = tid >> 5, lane = tid & 31;
    const int row0 = blockIdx.y * 128, col0 = blockIdx.x * 128;
    const int warp_m = wid >> 2;   // 0..1 -> 64 rows
    const int warp_n = wid & 3;    // 0..3 -> 32 cols
    constexpr int NIT = K / 64;

    auto load = [&](int it) {
        uint32_t st = sb + (it & 1) * STG_BYTES;
#pragma unroll
        for (int i = 0; i < 4; i++) {
            int idx = tid + i * 256;
            int r = idx >> 3, c16 = idx & 7;
            uint32_t so = swz(r * 128 + c16 * 16);
            cp16(st + STG_AH + so, Ah + (size_t)(row0 + r) * K + it * 64 + c16 * 8);
            cp16(st + STG_AL + so, Al + (size_t)(row0 + r) * K + it * 64 + c16 * 8);
            cp16(st + STG_B  + so, Bh + (size_t)(col0 + r) * K + it * 64 + c16 * 8);
        }
        asm volatile("cp.async.commit_group;" ::: "memory");
    };

    float acc[4][4][4] = {};

    load(0);
    if (NIT > 1) load(1);

    const int lrow = lane & 15, lhi = lane >> 4;

#pragma unroll 1
    for (int it = 0; it < NIT; it++) {
        asm volatile("cp.async.wait_group 1;" ::: "memory");
        __syncthreads();

        uint32_t st = sb + (it & 1) * STG_BYTES;
#pragma unroll
        for (int kk = 0; kk < 4; kk++) {
            uint32_t ah[4][4], al[4][4];
#pragma unroll
            for (int mt = 0; mt < 4; mt++) {
                uint32_t aso = swz((warp_m * 64 + mt * 16 + lrow) * 128 + (kk * 2 + lhi) * 16);
                ldm_x4(ah[mt], st + STG_AH + aso);
                ldm_x4(al[mt], st + STG_AL + aso);
            }
#pragma unroll
            for (int nt2 = 0; nt2 < 2; nt2++) {
                uint32_t b[4];
                ldm_x4(b, st + STG_B + swz((warp_n * 32 + nt2 * 16 + lrow) * 128 + (kk * 2 + lhi) * 16));
#pragma unroll
                for (int mt = 0; mt < 4; mt++) {
                    mma_f16(acc[mt][nt2 * 2 + 0], ah[mt], b[0], b[2]);
                    mma_f16(acc[mt][nt2 * 2 + 1], ah[mt], b[1], b[3]);
                    mma_f16(acc[mt][nt2 * 2 + 0], al[mt], b[0], b[2]);
                    mma_f16(acc[mt][nt2 * 2 + 1], al[mt], b[1], b[3]);
                }
            }
        }
        __syncthreads();
        if (it + 2 < NIT) load(it + 2);
        else asm volatile("cp.async.commit_group;" ::: "memory");
    }

    // ---- epilogue 1: store C tile ----
#pragma unroll
    for (int mt = 0; mt < 4; mt++) {
        int row = row0 + warp_m * 64 + mt * 16 + (lane >> 2);
#pragma unroll
        for (int nt = 0; nt < 4; nt++) {
            int col = col0 + warp_n * 32 + nt * 8 + (lane & 3) * 2;
            float2 v0; v0.x = acc[mt][nt][0]; v0.y = acc[mt][nt][1];
            float2 v1; v1.x = acc[mt][nt][2]; v1.y = acc[mt][nt][3];
            *(float2*)&C[(size_t)row * Mtot + col]       = v0;
            *(float2*)&C[(size_t)(row + 8) * Mtot + col] = v1;
        }
    }

    // ---- epilogue 2: partial attention logits ----
    const int C_head = Mtot / NHEAD;
    const int head = col0 / C_head;
    const int slot = (col0 % C_head) >> 7;
    float* bufss = (float*)smem;             // [4 warp_n][128 rows]
    float* bufsd = bufss + 512;

#pragma unroll
    for (int mt = 0; mt < 4; mt++) {
        float ss0 = 0.f, ss1 = 0.f, sd0 = 0.f, sd1 = 0.f;
#pragma unroll
        for (int nt = 0; nt < 4; nt++) {
            int c = col0 + warp_n * 32 + nt * 8 + (lane & 3) * 2;
            float w0s = ws_flat[c], w1s = ws_flat[c + 1];
            float w0d = wd_flat[c], w1d = wd_flat[c + 1];
            ss0 = fmaf(acc[mt][nt][0], w0s, fmaf(acc[mt][nt][1], w1s, ss0));
            ss1 = fmaf(acc[mt][nt][2], w0s, fmaf(acc[mt][nt][3], w1s, ss1));
            sd0 = fmaf(acc[mt][nt][0], w0d, fmaf(acc[mt][nt][1], w1d, sd0));
            sd1 = fmaf(acc[mt][nt][2], w0d, fmaf(acc[mt][nt][3], w1d, sd1));
        }
#pragma unroll
        for (int off = 1; off <= 2; off <<= 1) {
            ss0 += __shfl_xor_sync(0xffffffffu, ss0, off);
            ss1 += __shfl_xor_sync(0xffffffffu, ss1, off);
            sd0 += __shfl_xor_sync(0xffffffffu, sd0, off);
            sd1 += __shfl_xor_sync(0xffffffffu, sd1, off);
        }
        if ((lane & 3) == 0) {
            int r0 = warp_m * 64 + mt * 16 + (lane >> 2);
            bufss[warp_n * 128 + r0]     = ss0;
            bufss[warp_n * 128 + r0 + 8] = ss1;
            bufsd[warp_n * 128 + r0]     = sd0;
            bufsd[warp_n * 128 + r0 + 8] = sd1;
        }
    }
    __syncthreads();
    if (tid < 128) {
        float ss = bufss[tid] + bufss[128 + tid] + bufss[256 + tid] + bufss[384 + tid];
        float sd = bufsd[tid] + bufsd[128 + tid] + bufsd[256 + tid] + bufsd[384 + tid];
        size_t node = (size_t)(row0 + tid);
        alsP[(size_t)slot * PART_STRIDE + node * NHEAD + head] = ss;
        aldP[(size_t)slot * PART_STRIDE + node * NHEAD + head] = sd;
    }
}

// ---------------- layer-1 GAT combine, vectorized: 4 nodes per block, float4 per thread ----------------
__global__ __launch_bounds__(256)
void gat_combine_l1(const float* __restrict__ hraw, const float* __restrict__ alsP,
                    const float* __restrict__ aldP, const float* __restrict__ bias,
                    __half* __restrict__ out_hi, __half* __restrict__ out_lo) {
    int tid = threadIdx.x;
    int d   = blockIdx.x * 4 + (tid >> 6);      // node
    int c4  = (tid & 63) * 4;                   // channel base (0..252)
    bool has_prev = (d % NODES_PER) != 0;

    float4 r = *(const float4*)&bias[c4];
    float acc0 = r.x, acc1 = r.y, acc2 = r.z, acc3 = r.w;
    float o0 = 0.f, o1 = 0.f, o2 = 0.f, o3 = 0.f;
#pragma unroll
    for (int hh = 0; hh < NHEAD; hh++) {
        size_t ai = (size_t)d * NHEAD + hh;
        float als = alsP[ai] + alsP[PART_STRIDE + ai];
        float ald = aldP[ai] + aldP[PART_STRIDE + ai];
        float es  = lrelu(als + ald);
        float4 hs = *(const float4*)&hraw[(size_t)d * NHEAD * HID_F + hh * HID_F + c4];
        if (has_prev) {
            size_t pi = (size_t)(d - 1) * NHEAD + hh;
            float alsp = alsP[pi] + alsP[PART_STRIDE + pi];
            float ep = lrelu(alsp + ald);
            float m  = fmaxf(es, ep);
            float xs = __expf(es - m), xp = __expf(ep - m);
            float inv = 0.5f / (xs + xp);          // fold head-mean 1/2
            xs *= inv; xp *= inv;
            float4 hp = *(const float4*)&hraw[(size_t)(d - 1) * NHEAD * HID_F + hh * HID_F + c4];
            o0 += xs * hs.x + xp * hp.x;
            o1 += xs * hs.y + xp * hp.y;
            o2 += xs * hs.z + xp * hp.z;
            o3 += xs * hs.w + xp * hp.w;
        } else {
            o0 += 0.5f * hs.x; o1 += 0.5f * hs.y; o2 += 0.5f * hs.z; o3 += 0.5f * hs.w;
        }
    }
    acc0 = fmaxf(acc0 + o0, 0.f);
    acc1 = fmaxf(acc1 + o1, 0.f);
    acc2 = fmaxf(acc2 + o2, 0.f);
    acc3 = fmaxf(acc3 + o3, 0.f);

    __half h0 = __float2half(acc0), h1 = __float2half(acc1);
    __half h2 = __float2half(acc2), h3 = __float2half(acc3);
    __half2 ph0; ph0.x = h0; ph0.y = h1;
    __half2 ph1; ph1.x = h2; ph1.y = h3;
    __half2 pl0; pl0.x = __float2half(acc0 - __half2float(h0));
    pl0.y = __float2half(acc1 - __half2float(h1));
    __half2 pl1; pl1.x = __float2half(acc2 - __half2float(h2));
    pl1.y = __float2half(acc3 - __half2float(h3));
    size_t gid2 = ((size_t)d * HID_F + c4) >> 1;
    ((__half2*)out_hi)[gid2]     = ph0;
    ((__half2*)out_hi)[gid2 + 1] = ph1;
    ((__half2*)out_lo)[gid2]     = pl0;
    ((__half2*)out_lo)[gid2 + 1] = pl1;
}

// ---------------- layer-2 combine + node heads, warp per node ----------------
__global__ __launch_bounds__(256)
void gat_l2_fused(const float* __restrict__ h2raw, const float* __restrict__ alsP,
                  const float* __restrict__ aldP, const float* __restrict__ b2,
                  const float* __restrict__ Wn, const float* __restrict__ bn,
                  const float* __restrict__ Wt, const float* __restrict__ bt,
                  float* __restrict__ emb, float* __restrict__ node_pred,
                  float* __restrict__ logit) {
    int d    = (blockIdx.x * blockDim.x + threadIdx.x) >> 5;
    int lane = threadIdx.x & 31;
    if (d >= N_NODES) return;
    bool has_prev = (d % NODES_PER) != 0;

    float e[4] = {0.f, 0.f, 0.f, 0.f};
#pragma unroll
    for (int hh = 0; hh < NHEAD; hh++) {
        size_t ai = (size_t)d * NHEAD + hh;
        float als = alsP[ai];
        float ald = aldP[ai];
        float es  = lrelu(als + ald);
        float4 hs = *(const float4*)&h2raw[(size_t)d * NHEAD * OUT_F + hh * OUT_F + lane * 4];
        if (has_prev) {
            float alsp = alsP[(size_t)(d - 1) * NHEAD + hh];
            float ep = lrelu(alsp + ald);
            float m  = fmaxf(es, ep);
            float xs = __expf(es - m), xp = __expf(ep - m);
            float inv = 1.f / (xs + xp);
            float4 hp = *(const float4*)&h2raw[(size_t)(d - 1) * NHEAD * OUT_F + hh * OUT_F + lane * 4];
            e[0] += (xs * hs.x + xp * hp.x) * inv;
            e[1] += (xs * hs.y + xp * hp.y) * inv;
            e[2] += (xs * hs.z + xp * hp.z) * inv;
            e[3] += (xs * hs.w + xp * hp.w) * inv;
        } else {
            e[0] += hs.x; e[1] += hs.y; e[2] += hs.z; e[3] += hs.w;
        }
    }
    float4 bb = *(const float4*)&b2[lane * 4];
    e[0] = e[0] * 0.5f + bb.x;
    e[1] = e[1] * 0.5f + bb.y;
    e[2] = e[2] * 0.5f + bb.z;
    e[3] = e[3] * 0.5f + bb.w;
    float4 ev; ev.x = e[0]; ev.y = e[1]; ev.z = e[2]; ev.w = e[3];
    *(float4*)&emb[(size_t)d * OUT_F + lane * 4] = ev;

    float vals[8];
#pragma unroll
    for (int o = 0; o < 8; o++) {
        const float* w = (o < NCLS) ? &Wn[o * OUT_F] : Wt;
        float4 w4 = *(const float4*)&w[lane * 4];
        float s = e[0] * w4.x + e[1] * w4.y + e[2] * w4.z + e[3] * w4.w;
#pragma unroll
        for (int sh = 16; sh; sh >>= 1) s += __shfl_xor_sync(0xffffffffu, s, sh);
        vals[o] = s;
    }
    if (lane == 0) {
        float z[NCLS], m = -1e30f;
#pragma unroll
        for (int i = 0; i < NCLS; i++) { z[i] = vals[i] + bn[i]; m = fmaxf(m, z[i]); }
        float ssum = 0.f;
#pragma unroll
        for (int i = 0; i < NCLS; i++) { z[i] = __expf(z[i] - m); ssum += z[i]; }
        float inv = 1.f / ssum;
#pragma unroll
        for (int i = 0; i < NCLS; i++) node_pred[(size_t)d * NCLS + i] = z[i] * inv;
        logit[d] = vals[7] + bt[0];
    }
}

// ---------------- audio pooling, stage 1: per-audio softmax weights ----------------
__global__ __launch_bounds__(256)
void audio_softmax(const float* __restrict__ logit, float* __restrict__ aw) {
    __shared__ float red[256];
    int b = blockIdx.x, t = threadIdx.x;
    const float* lg = logit + b * NODES_PER;

    float m = -1e30f;
    for (int i = t; i < NODES_PER; i += 256) m = fmaxf(m, lg[i]);
    red[t] = m; __syncthreads();
    for (int s = 128; s; s >>= 1) { if (t < s) red[t] = fmaxf(red[t], red[t + s]); __syncthreads(); }
    m = red[0]; __syncthreads();

    float e0 = __expf(lg[t] - m);
    float e1 = __expf(lg[t + 256] - m);
    float e2 = __expf(lg[t + 512] - m);
    float e3 = __expf(lg[t + 768] - m);
    float e4 = __expf(lg[t + 1024] - m);
    float e5 = __expf(lg[t + 1280] - m);
    float e6 = __expf(lg[t + 1536] - m);
    float e7 = __expf(lg[t + 1792] - m);
    red[t] = ((e0 + e1) + (e2 + e3)) + ((e4 + e5) + (e6 + e7));
    __syncthreads();
    for (int s = 128; s; s >>= 1) { if (t < s) red[t] += red[t + s]; __syncthreads(); }
    float inv = 1.f / red[0];
    float* dst = aw + b * NODES_PER;
    dst[t]        = e0 * inv;
    dst[t + 256]  = e1 * inv;
    dst[t + 512]  = e2 * inv;
    dst[t + 768]  = e3 * inv;
    dst[t + 1024] = e4 * inv;
    dst[t + 1280] = e5 * inv;
    dst[t + 1536] = e6 * inv;
    dst[t + 1792] = e7 * inv;
}

// ---------------- audio pooling, stage 2: weighted sum (chunked, coalesced) ----------------
// grid (4 chunks, 64 audios), block 256 = 8 warps; warp w handles rows [w*256, w*256+256),
// lane = channel within 32-channel chunk.
__global__ __launch_bounds__(256)
void audio_wsum(const float* __restrict__ emb, const float* __restrict__ aw,
                float* __restrict__ att) {
    __shared__ float red[8][33];
    int chunk = blockIdx.x, b = blockIdx.y;
    int w = threadIdx.x >> 5, lane = threadIdx.x & 31;
    int ch = chunk * 32 + lane;
    const float* eb = emb + (size_t)b * NODES_PER * OUT_F + ch;
    const float* wb = aw + b * NODES_PER;

    float a0 = 0.f, a1 = 0.f;
    int i0 = w * 256;
#pragma unroll 4
    for (int i = 0; i < 256; i += 2) {
        a0 = fmaf(wb[i0 + i],     eb[(size_t)(i0 + i) * OUT_F],     a0);
        a1 = fmaf(wb[i0 + i + 1], eb[(size_t)(i0 + i + 1) * OUT_F], a1);
    }
    red[w][lane] = a0 + a1;
    __syncthreads();
    if (w == 0) {
        float s = red[0][lane];
#pragma unroll
        for (int j = 1; j < 8; j++) s += red[j][lane];
        att[b * OUT_F + ch] = s;
    }
}

// ---------------- audio pooling, stage 3: Wa head ----------------
__global__ __launch_bounds__(128)
void audio_head(const float* __restrict__ att, const float* __restrict__ Wa,
                const float* __restrict__ ba, float* __restrict__ audio_pred) {
    __shared__ float red[128];
    int b = blockIdx.x, t = threadIdx.x;
    float a = att[b * OUT_F + t];
#pragma unroll
    for (int o = 0; o < 2; o++) {
        red[t] = a * Wa[o * OUT_F + t]; __syncthreads();
        for (int s = 64; s; s >>= 1) { if (t < s) red[t] += red[t + s]; __syncthreads(); }
        if (t == 0) audio_pred[b * 2 + o] = red[0] + ba[o];
        __syncthreads();
    }
}

// ---------------- launch ----------------
extern "C" void kernel_launch(void* const* d_in, const int* in_sizes, int n_in,
                              void* d_out, int out_size) {
    int wi = n_in - 14;
    const float* x   = (const float*)d_in[0];
    const float* W1  = (const float*)d_in[wi + 0];
    const float* as1 = (const float*)d_in[wi + 1];
    const float* ad1 = (const float*)d_in[wi + 2];
    const float* b1  = (const float*)d_in[wi + 3];
    const float* W2  = (const float*)d_in[wi + 4];
    const float* as2 = (const float*)d_in[wi + 5];
    const float* ad2 = (const float*)d_in[wi + 6];
    const float* b2  = (const float*)d_in[wi + 7];
    const float* Wt  = (const float*)d_in[wi + 8];
    const float* bt  = (const float*)d_in[wi + 9];
    const float* Wa  = (const float*)d_in[wi + 10];
    const float* ba  = (const float*)d_in[wi + 11];
    const float* Wn  = (const float*)d_in[wi + 12];
    const float* bn  = (const float*)d_in[wi + 13];

    float *h1raw, *h2raw, *emb, *als1p, *ald1p, *als2p, *ald2p, *logit, *aw, *att;
    __half *xh, *xl, *h1h, *h1l, *w1h, *w2h;
    cudaGetSymbolAddress((void**)&h1raw, g_h1raw);
    cudaGetSymbolAddress((void**)&h2raw, g_h2raw);
    cudaGetSymbolAddress((void**)&emb,   g_emb);
    cudaGetSymbolAddress((void**)&xh,    g_xh);
    cudaGetSymbolAddress((void**)&xl,    g_xl);
    cudaGetSymbolAddress((void**)&h1h,   g_h1h);
    cudaGetSymbolAddress((void**)&h1l,   g_h1l);
    cudaGetSymbolAddress((void**)&w1h,   g_w1h);
    cudaGetSymbolAddress((void**)&w2h,   g_w2h);
    cudaGetSymbolAddress((void**)&als1p, g_als1p);
    cudaGetSymbolAddress((void**)&ald1p, g_ald1p);
    cudaGetSymbolAddress((void**)&als2p, g_als2p);
    cudaGetSymbolAddress((void**)&ald2p, g_ald2p);
    cudaGetSymbolAddress((void**)&logit, g_logit);
    cudaGetSymbolAddress((void**)&aw,    g_aw);
    cudaGetSymbolAddress((void**)&att,   g_att);

    float* node_pred  = (float*)d_out;
    float* audio_pred = node_pred + (size_t)N_NODES * NCLS;

    cudaFuncSetAttribute(gemm_mma<512>, cudaFuncAttributeMaxDynamicSharedMemorySize, GEMM_SMEM);
    cudaFuncSetAttribute(gemm_mma<256>, cudaFuncAttributeMaxDynamicSharedMemorySize, GEMM_SMEM);

    // conversions
    {
        int n4 = (N_NODES * IN_F) / 4;
        split_f16<<<(n4 + 255) / 256, 256>>>(x, xh, xl, n4);
    }
    cvt_f16<<<(512 * 512 / 4 + 255) / 256, 256>>>(W1, w1h, 512 * 512 / 4);
    cvt_f16<<<(256 * 256 / 4 + 255) / 256, 256>>>(W2, w2h, 256 * 256 / 4);

    // layer 1: h1raw = x @ W1^T [N,512] + fused al1 partials
    gemm_mma<512><<<dim3(4, N_NODES / 128), 256, GEMM_SMEM>>>(
        xh, xl, w1h, h1raw, 512, as1, ad1, als1p, ald1p);
    gat_combine_l1<<<N_NODES / 4, 256>>>(h1raw, als1p, ald1p, b1, h1h, h1l);

    // layer 2: h2raw = h1 @ W2^T [N,256] + fused al2 partials
    gemm_mma<256><<<dim3(2, N_NODES / 128), 256, GEMM_SMEM>>>(
        h1h, h1l, w2h, h2raw, 256, as2, ad2, als2p, ald2p);
    gat_l2_fused<<<N_NODES / 8, 256>>>(h2raw, als2p, ald2p, b2, Wn, bn, Wt, bt,
                                       emb, node_pred, logit);

    // audio head (3-stage, parallel)
    audio_softmax<<<B_AUD, 256>>>(logit, aw);
    audio_wsum<<<dim3(4, B_AUD), 256>>>(emb, aw, att);
    audio_head<<<B_AUD, 128>>>(att, Wa, ba, audio_pred);
}

// round 10
// speedup vs baseline: 3.5080x; 1.0835x over previous
#include <cuda_runtime.h>
#include <cuda_fp16.h>
#include <cstdint>

#define N_NODES   131072
#define NODES_PER 2048
#define B_AUD     64
#define IN_F      512
#define HID_F     256
#define OUT_F     128
#define NHEAD     2
#define NCLS      7
#define NEG_SLOPE 0.2f
#define PART_STRIDE ((size_t)N_NODES * NHEAD)

// ---------------- scratch (static device allocations; no cudaMalloc) ----------------
__device__ float  g_h1raw[(size_t)N_NODES * NHEAD * HID_F]; // 256 MB
__device__ float  g_h2raw[(size_t)N_NODES * NHEAD * OUT_F]; // 128 MB
__device__ float  g_emb  [(size_t)N_NODES * OUT_F];         //  64 MB
__device__ __half g_xh  [(size_t)N_NODES * IN_F];
__device__ __half g_xl  [(size_t)N_NODES * IN_F];
__device__ __half g_h1h [(size_t)N_NODES * HID_F];
__device__ __half g_h1l [(size_t)N_NODES * HID_F];
__device__ __half g_w1h [512 * 512];
__device__ __half g_w2h [256 * 256];
__device__ float g_als1p[2 * PART_STRIDE];
__device__ float g_ald1p[2 * PART_STRIDE];
__device__ float g_als2p[2 * PART_STRIDE];
__device__ float g_ald2p[2 * PART_STRIDE];
__device__ float g_logit[N_NODES];
__device__ float g_aw   [B_AUD * NODES_PER];
__device__ float g_att  [B_AUD * OUT_F];

__device__ __forceinline__ float lrelu(float v) { return v > 0.f ? v : NEG_SLOPE * v; }

// ---------------- PTX helpers (portable: sm_80-class, compiles at compute_103) ----------------
__device__ __forceinline__ uint32_t smem_u32(const void* p) {
    uint32_t a;
    asm("{ .reg .u64 t; cvta.to.shared.u64 t, %1; cvt.u32.u64 %0, t; }" : "=r"(a) : "l"(p));
    return a;
}
__device__ __forceinline__ uint32_t swz(uint32_t b) { return b ^ ((b >> 3) & 0x70); }
__device__ __forceinline__ void cp16(uint32_t dst, const void* src) {
    asm volatile("cp.async.cg.shared.global [%0], [%1], 16;" :: "r"(dst), "l"(src));
}
__device__ __forceinline__ void ldm_x4(uint32_t* r, uint32_t addr) {
    asm volatile("ldmatrix.sync.aligned.m8n8.x4.shared.b16 {%0,%1,%2,%3}, [%4];"
                 : "=r"(r[0]), "=r"(r[1]), "=r"(r[2]), "=r"(r[3]) : "r"(addr));
}
__device__ __forceinline__ void mma_f16(float* c, const uint32_t* a, uint32_t b0, uint32_t b1) {
    asm volatile(
        "mma.sync.aligned.m16n8k16.row.col.f32.f16.f16.f32 "
        "{%0,%1,%2,%3}, {%4,%5,%6,%7}, {%8,%9}, {%0,%1,%2,%3};"
        : "+f"(c[0]), "+f"(c[1]), "+f"(c[2]), "+f"(c[3])
        : "r"(a[0]), "r"(a[1]), "r"(a[2]), "r"(a[3]), "r"(b0), "r"(b1));
}

// ---------------- fp16 hi/lo split (activations, exact to ~22 bits) ----------------
__global__ __launch_bounds__(256)
void split_f16(const float* __restrict__ a, __half* __restrict__ hi,
               __half* __restrict__ lo, int n4) {
    int i = blockIdx.x * 256 + threadIdx.x;
    if (i >= n4) return;
    float4 v = ((const float4*)a)[i];
    __half h0 = __float2half(v.x), h1 = __float2half(v.y);
    __half h2 = __float2half(v.z), h3 = __float2half(v.w);
    __half2 ph0; ph0.x = h0; ph0.y = h1;
    __half2 ph1; ph1.x = h2; ph1.y = h3;
    __half2 pl0; pl0.x = __float2half(v.x - __half2float(h0));
    pl0.y = __float2half(v.y - __half2float(h1));
    __half2 pl1; pl1.x = __float2half(v.z - __half2float(h2));
    pl1.y = __float2half(v.w - __half2float(h3));
    ((__half2*)hi)[2 * i]     = ph0;
    ((__half2*)hi)[2 * i + 1] = ph1;
    ((__half2*)lo)[2 * i]     = pl0;
    ((__half2*)lo)[2 * i + 1] = pl1;
}

// ---------------- fp32 -> fp16 convert (weights) ----------------
__global__ __launch_bounds__(256)
void cvt_f16(const float* __restrict__ a, __half* __restrict__ o, int n4) {
    int i = blockIdx.x * 256 + threadIdx.x;
    if (i >= n4) return;
    float4 v = ((const float4*)a)[i];
    __half2 p0; p0.x = __float2half(v.x); p0.y = __float2half(v.y);
    __half2 p1; p1.x = __float2half(v.z); p1.y = __float2half(v.w);
    ((__half2*)o)[2 * i]     = p0;
    ((__half2*)o)[2 * i + 1] = p1;
}

// ---------------- split-fp16 warp-MMA GEMM: C = (Ah+Al) * Bh^T, fused al-epilogue ----------------
// CTA 128x128, BK=64, 2-stage cp.async; 8 warps in 4m x 2n, warp tile 32x64.
// B fragments shared across hi/lo terms -> 8 ldmatrix / 32 MMAs per kk per warp.
#define STG_AH    0
#define STG_AL    16384
#define STG_B     32768
#define STG_BYTES 49152
#define GEMM_SMEM (2 * STG_BYTES)

template <int K>
__global__ __launch_bounds__(256, 2)
void gemm_mma(const __half* __restrict__ Ah, const __half* __restrict__ Al,
              const __half* __restrict__ Bh,
              float* __restrict__ C, int Mtot,
              const float* __restrict__ ws_flat, const float* __restrict__ wd_flat,
              float* __restrict__ alsP, float* __restrict__ aldP) {
    extern __shared__ __align__(1024) char smem[];
    uint32_t sb = smem_u32(smem);
    const int tid = threadIdx.x, wid = tid >> 5, lane = tid & 31;
    const int row0 = blockIdx.y * 128, col0 = blockIdx.x * 128;
    const int warp_m = wid & 3;    // 0..3 -> 32 rows each
    const int warp_n = wid >> 2;   // 0..1 -> 64 cols each
    constexpr int NIT = K / 64;

    auto load = [&](int it) {
        uint32_t st = sb + (it & 1) * STG_BYTES;
#pragma unroll
        for (int i = 0; i < 4; i++) {
            int idx = tid + i * 256;
            int r = idx >> 3, c16 = idx & 7;
            uint32_t so = swz(r * 128 + c16 * 16);
            cp16(st + STG_AH + so, Ah + (size_t)(row0 + r) * K + it * 64 + c16 * 8);
            cp16(st + STG_AL + so, Al + (size_t)(row0 + r) * K + it * 64 + c16 * 8);
            cp16(st + STG_B  + so, Bh + (size_t)(col0 + r) * K + it * 64 + c16 * 8);
        }
        asm volatile("cp.async.commit_group;" ::: "memory");
    };

    float acc[2][8][4] = {};   // [mt][n8 block][frag]

    load(0);
    if (NIT > 1) load(1);

    const int lrow = lane & 15, lhi = lane >> 4;

#pragma unroll 1
    for (int it = 0; it < NIT; it++) {
        asm volatile("cp.async.wait_group 1;" ::: "memory");
        __syncthreads();

        uint32_t st = sb + (it & 1) * STG_BYTES;
#pragma unroll
        for (int kk = 0; kk < 4; kk++) {
            uint32_t ah[2][4], al[2][4];
#pragma unroll
            for (int mt = 0; mt < 2; mt++) {
                uint32_t aso = swz((warp_m * 32 + mt * 16 + lrow) * 128 + (kk * 2 + lhi) * 16);
                ldm_x4(ah[mt], st + STG_AH + aso);
                ldm_x4(al[mt], st + STG_AL + aso);
            }
#pragma unroll
            for (int bf = 0; bf < 4; bf++) {
                uint32_t b[4];
                ldm_x4(b, st + STG_B + swz((warp_n * 64 + bf * 16 + lrow) * 128 + (kk * 2 + lhi) * 16));
                // b regs: r0=(n0:8,k0:8) r1=(n8:16,k0:8) r2=(n0:8,k8:16) r3=(n8:16,k8:16)
#pragma unroll
                for (int mt = 0; mt < 2; mt++) {
                    mma_f16(acc[mt][bf * 2 + 0], ah[mt], b[0], b[2]);
                    mma_f16(acc[mt][bf * 2 + 1], ah[mt], b[1], b[3]);
                    mma_f16(acc[mt][bf * 2 + 0], al[mt], b[0], b[2]);
                    mma_f16(acc[mt][bf * 2 + 1], al[mt], b[1], b[3]);
                }
            }
        }
        __syncthreads();
        if (it + 2 < NIT) load(it + 2);
        else asm volatile("cp.async.commit_group;" ::: "memory");
    }

    // ---- epilogue 1: store C tile ----
#pragma unroll
    for (int mt = 0; mt < 2; mt++) {
        int row = row0 + warp_m * 32 + mt * 16 + (lane >> 2);
#pragma unroll
        for (int nb = 0; nb < 8; nb++) {
            int col = col0 + warp_n * 64 + nb * 8 + (lane & 3) * 2;
            float2 v0; v0.x = acc[mt][nb][0]; v0.y = acc[mt][nb][1];
            float2 v1; v1.x = acc[mt][nb][2]; v1.y = acc[mt][nb][3];
            *(float2*)&C[(size_t)row * Mtot + col]       = v0;
            *(float2*)&C[(size_t)(row + 8) * Mtot + col] = v1;
        }
    }

    // ---- epilogue 2: partial attention logits ----
    const int C_head = Mtot / NHEAD;
    const int head = col0 / C_head;
    const int slot = (col0 % C_head) >> 7;
    float* bufss = (float*)smem;             // [2 warp_n][128 rows]
    float* bufsd = bufss + 256;

#pragma unroll
    for (int mt = 0; mt < 2; mt++) {
        float ss0 = 0.f, ss1 = 0.f, sd0 = 0.f, sd1 = 0.f;
#pragma unroll
        for (int nb = 0; nb < 8; nb++) {
            int c = col0 + warp_n * 64 + nb * 8 + (lane & 3) * 2;
            float w0s = ws_flat[c], w1s = ws_flat[c + 1];
            float w0d = wd_flat[c], w1d = wd_flat[c + 1];
            ss0 = fmaf(acc[mt][nb][0], w0s, fmaf(acc[mt][nb][1], w1s, ss0));
            ss1 = fmaf(acc[mt][nb][2], w0s, fmaf(acc[mt][nb][3], w1s, ss1));
            sd0 = fmaf(acc[mt][nb][0], w0d, fmaf(acc[mt][nb][1], w1d, sd0));
            sd1 = fmaf(acc[mt][nb][2], w0d, fmaf(acc[mt][nb][3], w1d, sd1));
        }
#pragma unroll
        for (int off = 1; off <= 2; off <<= 1) {
            ss0 += __shfl_xor_sync(0xffffffffu, ss0, off);
            ss1 += __shfl_xor_sync(0xffffffffu, ss1, off);
            sd0 += __shfl_xor_sync(0xffffffffu, sd0, off);
            sd1 += __shfl_xor_sync(0xffffffffu, sd1, off);
        }
        if ((lane & 3) == 0) {
            int r0 = warp_m * 32 + mt * 16 + (lane >> 2);
            bufss[warp_n * 128 + r0]     = ss0;
            bufss[warp_n * 128 + r0 + 8] = ss1;
            bufsd[warp_n * 128 + r0]     = sd0;
            bufsd[warp_n * 128 + r0 + 8] = sd1;
        }
    }
    __syncthreads();
    if (tid < 128) {
        float ss = bufss[tid] + bufss[128 + tid];
        float sd = bufsd[tid] + bufsd[128 + tid];
        size_t node = (size_t)(row0 + tid);
        alsP[(size_t)slot * PART_STRIDE + node * NHEAD + head] = ss;
        aldP[(size_t)slot * PART_STRIDE + node * NHEAD + head] = sd;
    }
}

// ---------------- layer-1 GAT combine, vectorized: 4 nodes per block, float4 per thread ----------------
__global__ __launch_bounds__(256)
void gat_combine_l1(const float* __restrict__ hraw, const float* __restrict__ alsP,
                    const float* __restrict__ aldP, const float* __restrict__ bias,
                    __half* __restrict__ out_hi, __half* __restrict__ out_lo) {
    int tid = threadIdx.x;
    int d   = blockIdx.x * 4 + (tid >> 6);
    int c4  = (tid & 63) * 4;
    bool has_prev = (d % NODES_PER) != 0;

    float4 r = *(const float4*)&bias[c4];
    float acc0 = r.x, acc1 = r.y, acc2 = r.z, acc3 = r.w;
    float o0 = 0.f, o1 = 0.f, o2 = 0.f, o3 = 0.f;
#pragma unroll
    for (int hh = 0; hh < NHEAD; hh++) {
        size_t ai = (size_t)d * NHEAD + hh;
        float als = alsP[ai] + alsP[PART_STRIDE + ai];
        float ald = aldP[ai] + aldP[PART_STRIDE + ai];
        float es  = lrelu(als + ald);
        float4 hs = *(const float4*)&hraw[(size_t)d * NHEAD * HID_F + hh * HID_F + c4];
        if (has_prev) {
            size_t pi = (size_t)(d - 1) * NHEAD + hh;
            float alsp = alsP[pi] + alsP[PART_STRIDE + pi];
            float ep = lrelu(alsp + ald);
            float m  = fmaxf(es, ep);
            float xs = __expf(es - m), xp = __expf(ep - m);
            float inv = 0.5f / (xs + xp);
            xs *= inv; xp *= inv;
            float4 hp = *(const float4*)&hraw[(size_t)(d - 1) * NHEAD * HID_F + hh * HID_F + c4];
            o0 += xs * hs.x + xp * hp.x;
            o1 += xs * hs.y + xp * hp.y;
            o2 += xs * hs.z + xp * hp.z;
            o3 += xs * hs.w + xp * hp.w;
        } else {
            o0 += 0.5f * hs.x; o1 += 0.5f * hs.y; o2 += 0.5f * hs.z; o3 += 0.5f * hs.w;
        }
    }
    acc0 = fmaxf(acc0 + o0, 0.f);
    acc1 = fmaxf(acc1 + o1, 0.f);
    acc2 = fmaxf(acc2 + o2, 0.f);
    acc3 = fmaxf(acc3 + o3, 0.f);

    __half h0 = __float2half(acc0), h1 = __float2half(acc1);
    __half h2 = __float2half(acc2), h3 = __float2half(acc3);
    __half2 ph0; ph0.x = h0; ph0.y = h1;
    __half2 ph1; ph1.x = h2; ph1.y = h3;
    __half2 pl0; pl0.x = __float2half(acc0 - __half2float(h0));
    pl0.y = __float2half(acc1 - __half2float(h1));
    __half2 pl1; pl1.x = __float2half(acc2 - __half2float(h2));
    pl1.y = __float2half(acc3 - __half2float(h3));
    size_t gid2 = ((size_t)d * HID_F + c4) >> 1;
    ((__half2*)out_hi)[gid2]     = ph0;
    ((__half2*)out_hi)[gid2 + 1] = ph1;
    ((__half2*)out_lo)[gid2]     = pl0;
    ((__half2*)out_lo)[gid2 + 1] = pl1;
}

// ---------------- layer-2 combine + node heads, warp per node ----------------
__global__ __launch_bounds__(256)
void gat_l2_fused(const float* __restrict__ h2raw, const float* __restrict__ alsP,
                  const float* __restrict__ aldP, const float* __restrict__ b2,
                  const float* __restrict__ Wn, const float* __restrict__ bn,
                  const float* __restrict__ Wt, const float* __restrict__ bt,
                  float* __restrict__ emb, float* __restrict__ node_pred,
                  float* __restrict__ logit) {
    int d    = (blockIdx.x * blockDim.x + threadIdx.x) >> 5;
    int lane = threadIdx.x & 31;
    if (d >= N_NODES) return;
    bool has_prev = (d % NODES_PER) != 0;

    float e[4] = {0.f, 0.f, 0.f, 0.f};
#pragma unroll
    for (int hh = 0; hh < NHEAD; hh++) {
        size_t ai = (size_t)d * NHEAD + hh;
        float als = alsP[ai];
        float ald = aldP[ai];
        float es  = lrelu(als + ald);
        float4 hs = *(const float4*)&h2raw[(size_t)d * NHEAD * OUT_F + hh * OUT_F + lane * 4];
        if (has_prev) {
            float alsp = alsP[(size_t)(d - 1) * NHEAD + hh];
            float ep = lrelu(alsp + ald);
            float m  = fmaxf(es, ep);
            float xs = __expf(es - m), xp = __expf(ep - m);
            float inv = 1.f / (xs + xp);
            float4 hp = *(const float4*)&h2raw[(size_t)(d - 1) * NHEAD * OUT_F + hh * OUT_F + lane * 4];
            e[0] += (xs * hs.x + xp * hp.x) * inv;
            e[1] += (xs * hs.y + xp * hp.y) * inv;
            e[2] += (xs * hs.z + xp * hp.z) * inv;
            e[3] += (xs * hs.w + xp * hp.w) * inv;
        } else {
            e[0] += hs.x; e[1] += hs.y; e[2] += hs.z; e[3] += hs.w;
        }
    }
    float4 bb = *(const float4*)&b2[lane * 4];
    e[0] = e[0] * 0.5f + bb.x;
    e[1] = e[1] * 0.5f + bb.y;
    e[2] = e[2] * 0.5f + bb.z;
    e[3] = e[3] * 0.5f + bb.w;
    float4 ev; ev.x = e[0]; ev.y = e[1]; ev.z = e[2]; ev.w = e[3];
    *(float4*)&emb[(size_t)d * OUT_F + lane * 4] = ev;

    float vals[8];
#pragma unroll
    for (int o = 0; o < 8; o++) {
        const float* w = (o < NCLS) ? &Wn[o * OUT_F] : Wt;
        float4 w4 = *(const float4*)&w[lane * 4];
        float s = e[0] * w4.x + e[1] * w4.y + e[2] * w4.z + e[3] * w4.w;
#pragma unroll
        for (int sh = 16; sh; sh >>= 1) s += __shfl_xor_sync(0xffffffffu, s, sh);
        vals[o] = s;
    }
    if (lane == 0) {
        float z[NCLS], m = -1e30f;
#pragma unroll
        for (int i = 0; i < NCLS; i++) { z[i] = vals[i] + bn[i]; m = fmaxf(m, z[i]); }
        float ssum = 0.f;
#pragma unroll
        for (int i = 0; i < NCLS; i++) { z[i] = __expf(z[i] - m); ssum += z[i]; }
        float inv = 1.f / ssum;
#pragma unroll
        for (int i = 0; i < NCLS; i++) node_pred[(size_t)d * NCLS + i] = z[i] * inv;
        logit[d] = vals[7] + bt[0];
    }
}

// ---------------- audio pooling, stage 1: per-audio softmax weights ----------------
__global__ __launch_bounds__(256)
void audio_softmax(const float* __restrict__ logit, float* __restrict__ aw) {
    __shared__ float red[256];
    int b = blockIdx.x, t = threadIdx.x;
    const float* lg = logit + b * NODES_PER;

    float m = -1e30f;
    for (int i = t; i < NODES_PER; i += 256) m = fmaxf(m, lg[i]);
    red[t] = m; __syncthreads();
    for (int s = 128; s; s >>= 1) { if (t < s) red[t] = fmaxf(red[t], red[t + s]); __syncthreads(); }
    m = red[0]; __syncthreads();

    float e0 = __expf(lg[t] - m);
    float e1 = __expf(lg[t + 256] - m);
    float e2 = __expf(lg[t + 512] - m);
    float e3 = __expf(lg[t + 768] - m);
    float e4 = __expf(lg[t + 1024] - m);
    float e5 = __expf(lg[t + 1280] - m);
    float e6 = __expf(lg[t + 1536] - m);
    float e7 = __expf(lg[t + 1792] - m);
    red[t] = ((e0 + e1) + (e2 + e3)) + ((e4 + e5) + (e6 + e7));
    __syncthreads();
    for (int s = 128; s; s >>= 1) { if (t < s) red[t] += red[t + s]; __syncthreads(); }
    float inv = 1.f / red[0];
    float* dst = aw + b * NODES_PER;
    dst[t]        = e0 * inv;
    dst[t + 256]  = e1 * inv;
    dst[t + 512]  = e2 * inv;
    dst[t + 768]  = e3 * inv;
    dst[t + 1024] = e4 * inv;
    dst[t + 1280] = e5 * inv;
    dst[t + 1536] = e6 * inv;
    dst[t + 1792] = e7 * inv;
}

// ---------------- audio pooling, stage 2: weighted sum (chunked, coalesced) ----------------
__global__ __launch_bounds__(256)
void audio_wsum(const float* __restrict__ emb, const float* __restrict__ aw,
                float* __restrict__ att) {
    __shared__ float red[8][33];
    int chunk = blockIdx.x, b = blockIdx.y;
    int w = threadIdx.x >> 5, lane = threadIdx.x & 31;
    int ch = chunk * 32 + lane;
    const float* eb = emb + (size_t)b * NODES_PER * OUT_F + ch;
    const float* wb = aw + b * NODES_PER;

    float a0 = 0.f, a1 = 0.f;
    int i0 = w * 256;
#pragma unroll 4
    for (int i = 0; i < 256; i += 2) {
        a0 = fmaf(wb[i0 + i],     eb[(size_t)(i0 + i) * OUT_F],     a0);
        a1 = fmaf(wb[i0 + i + 1], eb[(size_t)(i0 + i + 1) * OUT_F], a1);
    }
    red[w][lane] = a0 + a1;
    __syncthreads();
    if (w == 0) {
        float s = red[0][lane];
#pragma unroll
        for (int j = 1; j < 8; j++) s += red[j][lane];
        att[b * OUT_F + ch] = s;
    }
}

// ---------------- audio pooling, stage 3: Wa head ----------------
__global__ __launch_bounds__(128)
void audio_head(const float* __restrict__ att, const float* __restrict__ Wa,
                const float* __restrict__ ba, float* __restrict__ audio_pred) {
    __shared__ float red[128];
    int b = blockIdx.x, t = threadIdx.x;
    float a = att[b * OUT_F + t];
#pragma unroll
    for (int o = 0; o < 2; o++) {
        red[t] = a * Wa[o * OUT_F + t]; __syncthreads();
        for (int s = 64; s; s >>= 1) { if (t < s) red[t] += red[t + s]; __syncthreads(); }
        if (t == 0) audio_pred[b * 2 + o] = red[0] + ba[o];
        __syncthreads();
    }
}

// ---------------- launch ----------------
extern "C" void kernel_launch(void* const* d_in, const int* in_sizes, int n_in,
                              void* d_out, int out_size) {
    int wi = n_in - 14;
    const float* x   = (const float*)d_in[0];
    const float* W1  = (const float*)d_in[wi + 0];
    const float* as1 = (const float*)d_in[wi + 1];
    const float* ad1 = (const float*)d_in[wi + 2];
    const float* b1  = (const float*)d_in[wi + 3];
    const float* W2  = (const float*)d_in[wi + 4];
    const float* as2 = (const float*)d_in[wi + 5];
    const float* ad2 = (const float*)d_in[wi + 6];
    const float* b2  = (const float*)d_in[wi + 7];
    const float* Wt  = (const float*)d_in[wi + 8];
    const float* bt  = (const float*)d_in[wi + 9];
    const float* Wa  = (const float*)d_in[wi + 10];
    const float* ba  = (const float*)d_in[wi + 11];
    const float* Wn  = (const float*)d_in[wi + 12];
    const float* bn  = (const float*)d_in[wi + 13];

    float *h1raw, *h2raw, *emb, *als1p, *ald1p, *als2p, *ald2p, *logit, *aw, *att;
    __half *xh, *xl, *h1h, *h1l, *w1h, *w2h;
    cudaGetSymbolAddress((void**)&h1raw, g_h1raw);
    cudaGetSymbolAddress((void**)&h2raw, g_h2raw);
    cudaGetSymbolAddress((void**)&emb,   g_emb);
    cudaGetSymbolAddress((void**)&xh,    g_xh);
    cudaGetSymbolAddress((void**)&xl,    g_xl);
    cudaGetSymbolAddress((void**)&h1h,   g_h1h);
    cudaGetSymbolAddress((void**)&h1l,   g_h1l);
    cudaGetSymbolAddress((void**)&w1h,   g_w1h);
    cudaGetSymbolAddress((void**)&w2h,   g_w2h);
    cudaGetSymbolAddress((void**)&als1p, g_als1p);
    cudaGetSymbolAddress((void**)&ald1p, g_ald1p);
    cudaGetSymbolAddress((void**)&als2p, g_als2p);
    cudaGetSymbolAddress((void**)&ald2p, g_ald2p);
    cudaGetSymbolAddress((void**)&logit, g_logit);
    cudaGetSymbolAddress((void**)&aw,    g_aw);
    cudaGetSymbolAddress((void**)&att,   g_att);

    float* node_pred  = (float*)d_out;
    float* audio_pred = node_pred + (size_t)N_NODES * NCLS;

    cudaFuncSetAttribute(gemm_mma<512>, cudaFuncAttributeMaxDynamicSharedMemorySize, GEMM_SMEM);
    cudaFuncSetAttribute(gemm_mma<256>, cudaFuncAttributeMaxDynamicSharedMemorySize, GEMM_SMEM);

    // conversions
    {
        int n4 = (N_NODES * IN_F) / 4;
        split_f16<<<(n4 + 255) / 256, 256>>>(x, xh, xl, n4);
    }
    cvt_f16<<<(512 * 512 / 4 + 255) / 256, 256>>>(W1, w1h, 512 * 512 / 4);
    cvt_f16<<<(256 * 256 / 4 + 255) / 256, 256>>>(W2, w2h, 256 * 256 / 4);

    // layer 1: h1raw = x @ W1^T [N,512] + fused al1 partials
    gemm_mma<512><<<dim3(4, N_NODES / 128), 256, GEMM_SMEM>>>(
        xh, xl, w1h, h1raw, 512, as1, ad1, als1p, ald1p);
    gat_combine_l1<<<N_NODES / 4, 256>>>(h1raw, als1p, ald1p, b1, h1h, h1l);

    // layer 2: h2raw = h1 @ W2^T [N,256] + fused al2 partials
    gemm_mma<256><<<dim3(2, N_NODES / 128), 256, GEMM_SMEM>>>(
        h1h, h1l, w2h, h2raw, 256, as2, ad2, als2p, ald2p);
    gat_l2_fused<<<N_NODES / 8, 256>>>(h2raw, als2p, ald2p, b2, Wn, bn, Wt, bt,
                                       emb, node_pred, logit);

    // audio head (3-stage, parallel)
    audio_softmax<<<B_AUD, 256>>>(logit, aw);
    audio_wsum<<<dim3(4, B_AUD), 256>>>(emb, aw, att);
    audio_head<<<B_AUD, 128>>>(att, Wa, ba, audio_pred);
}

// round 11
// speedup vs baseline: 4.8173x; 1.3732x over previous
#include <cuda_runtime.h>
#include <cuda_fp16.h>
#include <cstdint>

#define N_NODES   131072
#define NODES_PER 2048
#define B_AUD     64
#define IN_F      512
#define HID_F     256
#define OUT_F     128
#define NHEAD     2
#define NCLS      7
#define NEG_SLOPE 0.2f
#define PART_STRIDE ((size_t)N_NODES * NHEAD)

// ---------------- scratch (static device allocations; no cudaMalloc) ----------------
__device__ float  g_h1raw[(size_t)N_NODES * NHEAD * HID_F]; // 256 MB
__device__ float  g_h2raw[(size_t)N_NODES * NHEAD * OUT_F]; // 128 MB
__device__ float  g_emb  [(size_t)N_NODES * OUT_F];         //  64 MB
__device__ __half g_xh  [(size_t)N_NODES * IN_F];
__device__ __half g_h1h [(size_t)N_NODES * HID_F];
__device__ __half g_w1h [512 * 512];
__device__ __half g_w2h [256 * 256];
__device__ float g_als1p[2 * PART_STRIDE];
__device__ float g_ald1p[2 * PART_STRIDE];
__device__ float g_als2p[2 * PART_STRIDE];
__device__ float g_ald2p[2 * PART_STRIDE];
__device__ float g_logit[N_NODES];
__device__ float g_aw   [B_AUD * NODES_PER];
__device__ float g_att  [B_AUD * OUT_F];

__device__ __forceinline__ float lrelu(float v) { return v > 0.f ? v : NEG_SLOPE * v; }

// ---------------- PTX helpers (portable: sm_80-class, compiles at compute_103) ----------------
__device__ __forceinline__ uint32_t smem_u32(const void* p) {
    uint32_t a;
    asm("{ .reg .u64 t; cvta.to.shared.u64 t, %1; cvt.u32.u64 %0, t; }" : "=r"(a) : "l"(p));
    return a;
}
__device__ __forceinline__ uint32_t swz(uint32_t b) { return b ^ ((b >> 3) & 0x70); }
__device__ __forceinline__ void cp16(uint32_t dst, const void* src) {
    asm volatile("cp.async.cg.shared.global [%0], [%1], 16;" :: "r"(dst), "l"(src));
}
__device__ __forceinline__ void ldm_x4(uint32_t* r, uint32_t addr) {
    asm volatile("ldmatrix.sync.aligned.m8n8.x4.shared.b16 {%0,%1,%2,%3}, [%4];"
                 : "=r"(r[0]), "=r"(r[1]), "=r"(r[2]), "=r"(r[3]) : "r"(addr));
}
__device__ __forceinline__ void mma_f16(float* c, const uint32_t* a, uint32_t b0, uint32_t b1) {
    asm volatile(
        "mma.sync.aligned.m16n8k16.row.col.f32.f16.f16.f32 "
        "{%0,%1,%2,%3}, {%4,%5,%6,%7}, {%8,%9}, {%0,%1,%2,%3};"
        : "+f"(c[0]), "+f"(c[1]), "+f"(c[2]), "+f"(c[3])
        : "r"(a[0]), "r"(a[1]), "r"(a[2]), "r"(a[3]), "r"(b0), "r"(b1));
}

// ---------------- fp32 -> fp16 convert ----------------
__global__ __launch_bounds__(256)
void cvt_f16(const float* __restrict__ a, __half* __restrict__ o, int n4) {
    int i = blockIdx.x * 256 + threadIdx.x;
    if (i >= n4) return;
    float4 v = ((const float4*)a)[i];
    __half2 p0; p0.x = __float2half(v.x); p0.y = __float2half(v.y);
    __half2 p1; p1.x = __float2half(v.z); p1.y = __float2half(v.w);
    ((__half2*)o)[2 * i]     = p0;
    ((__half2*)o)[2 * i + 1] = p1;
}

// ---------------- fp16 warp-MMA GEMM: C = A * B^T, fused al-epilogue ----------------
// CTA 128x128, BK=64; 3-stage cp.async, ONE __syncthreads per iter (early-load);
// 8 warps in 4m x 2n, warp tile 32x64: 6 ldmatrix / 16 MMA per kk per warp.
#define STG_A     0
#define STG_B     16384
#define STG_BYTES 32768
#define GEMM_SMEM (3 * STG_BYTES)

template <int K>
__global__ __launch_bounds__(256, 2)
void gemm_mma(const __half* __restrict__ A, const __half* __restrict__ B,
              float* __restrict__ C, int Mtot,
              const float* __restrict__ ws_flat, const float* __restrict__ wd_flat,
              float* __restrict__ alsP, float* __restrict__ aldP) {
    extern __shared__ __align__(1024) char smem[];
    uint32_t sb = smem_u32(smem);
    const int tid = threadIdx.x, wid = tid >> 5, lane = tid & 31;
    const int row0 = blockIdx.y * 128, col0 = blockIdx.x * 128;
    const int warp_m = wid & 3;    // 0..3 -> 32 rows each
    const int warp_n = wid >> 2;   // 0..1 -> 64 cols each
    constexpr int NIT = K / 64;

    auto load = [&](int it) {
        uint32_t st = sb + (it % 3) * STG_BYTES;
#pragma unroll
        for (int i = 0; i < 4; i++) {
            int idx = tid + i * 256;
            int r = idx >> 3, c16 = idx & 7;
            uint32_t so = swz(r * 128 + c16 * 16);
            cp16(st + STG_A + so, A + (size_t)(row0 + r) * K + it * 64 + c16 * 8);
            cp16(st + STG_B + so, B + (size_t)(col0 + r) * K + it * 64 + c16 * 8);
        }
        asm volatile("cp.async.commit_group;" ::: "memory");
    };

    float acc[2][8][4] = {};   // [mt][n8 block][frag]

    load(0);
    if (NIT > 1) load(1);

    const int lrow = lane & 15, lhi = lane >> 4;

#pragma unroll 1
    for (int it = 0; it < NIT; it++) {
        if (NIT > 1) asm volatile("cp.async.wait_group 1;" ::: "memory");
        else         asm volatile("cp.async.wait_group 0;" ::: "memory");
        __syncthreads();
        if (it + 2 < NIT) load(it + 2);        // writes oldest stage; readers retired by the barrier above

        uint32_t st = sb + (it % 3) * STG_BYTES;
#pragma unroll
        for (int kk = 0; kk < 4; kk++) {
            uint32_t a[2][4];
#pragma unroll
            for (int mt = 0; mt < 2; mt++)
                ldm_x4(a[mt], st + STG_A + swz((warp_m * 32 + mt * 16 + lrow) * 128 + (kk * 2 + lhi) * 16));
#pragma unroll
            for (int bf = 0; bf < 4; bf++) {
                uint32_t b[4];
                ldm_x4(b, st + STG_B + swz((warp_n * 64 + bf * 16 + lrow) * 128 + (kk * 2 + lhi) * 16));
#pragma unroll
                for (int mt = 0; mt < 2; mt++) {
                    mma_f16(acc[mt][bf * 2 + 0], a[mt], b[0], b[2]);
                    mma_f16(acc[mt][bf * 2 + 1], a[mt], b[1], b[3]);
                }
            }
        }
    }
    __syncthreads();   // smem about to be reused as reduction buffer

    // ---- epilogue 1: store C tile ----
#pragma unroll
    for (int mt = 0; mt < 2; mt++) {
        int row = row0 + warp_m * 32 + mt * 16 + (lane >> 2);
#pragma unroll
        for (int nb = 0; nb < 8; nb++) {
            int col = col0 + warp_n * 64 + nb * 8 + (lane & 3) * 2;
            float2 v0; v0.x = acc[mt][nb][0]; v0.y = acc[mt][nb][1];
            float2 v1; v1.x = acc[mt][nb][2]; v1.y = acc[mt][nb][3];
            *(float2*)&C[(size_t)row * Mtot + col]       = v0;
            *(float2*)&C[(size_t)(row + 8) * Mtot + col] = v1;
        }
    }

    // ---- epilogue 2: partial attention logits ----
    const int C_head = Mtot / NHEAD;
    const int head = col0 / C_head;
    const int slot = (col0 % C_head) >> 7;
    float* bufss = (float*)smem;             // [2 warp_n][128 rows]
    float* bufsd = bufss + 256;

#pragma unroll
    for (int mt = 0; mt < 2; mt++) {
        float ss0 = 0.f, ss1 = 0.f, sd0 = 0.f, sd1 = 0.f;
#pragma unroll
        for (int nb = 0; nb < 8; nb++) {
            int c = col0 + warp_n * 64 + nb * 8 + (lane & 3) * 2;
            float w0s = ws_flat[c], w1s = ws_flat[c + 1];
            float w0d = wd_flat[c], w1d = wd_flat[c + 1];
            ss0 = fmaf(acc[mt][nb][0], w0s, fmaf(acc[mt][nb][1], w1s, ss0));
            ss1 = fmaf(acc[mt][nb][2], w0s, fmaf(acc[mt][nb][3], w1s, ss1));
            sd0 = fmaf(acc[mt][nb][0], w0d, fmaf(acc[mt][nb][1], w1d, sd0));
            sd1 = fmaf(acc[mt][nb][2], w0d, fmaf(acc[mt][nb][3], w1d, sd1));
        }
#pragma unroll
        for (int off = 1; off <= 2; off <<= 1) {
            ss0 += __shfl_xor_sync(0xffffffffu, ss0, off);
            ss1 += __shfl_xor_sync(0xffffffffu, ss1, off);
            sd0 += __shfl_xor_sync(0xffffffffu, sd0, off);
            sd1 += __shfl_xor_sync(0xffffffffu, sd1, off);
        }
        if ((lane & 3) == 0) {
            int r0 = warp_m * 32 + mt * 16 + (lane >> 2);
            bufss[warp_n * 128 + r0]     = ss0;
            bufss[warp_n * 128 + r0 + 8] = ss1;
            bufsd[warp_n * 128 + r0]     = sd0;
            bufsd[warp_n * 128 + r0 + 8] = sd1;
        }
    }
    __syncthreads();
    if (tid < 128) {
        float ss = bufss[tid] + bufss[128 + tid];
        float sd = bufsd[tid] + bufsd[128 + tid];
        size_t node = (size_t)(row0 + tid);
        alsP[(size_t)slot * PART_STRIDE + node * NHEAD + head] = ss;
        aldP[(size_t)slot * PART_STRIDE + node * NHEAD + head] = sd;
    }
}

// ---------------- layer-1 GAT combine, vectorized: 4 nodes per block, fp16 out ----------------
__global__ __launch_bounds__(256)
void gat_combine_l1(const float* __restrict__ hraw, const float* __restrict__ alsP,
                    const float* __restrict__ aldP, const float* __restrict__ bias,
                    __half* __restrict__ out_hi) {
    int tid = threadIdx.x;
    int d   = blockIdx.x * 4 + (tid >> 6);
    int c4  = (tid & 63) * 4;
    bool has_prev = (d % NODES_PER) != 0;

    float4 r = *(const float4*)&bias[c4];
    float acc0 = r.x, acc1 = r.y, acc2 = r.z, acc3 = r.w;
    float o0 = 0.f, o1 = 0.f, o2 = 0.f, o3 = 0.f;
#pragma unroll
    for (int hh = 0; hh < NHEAD; hh++) {
        size_t ai = (size_t)d * NHEAD + hh;
        float als = alsP[ai] + alsP[PART_STRIDE + ai];
        float ald = aldP[ai] + aldP[PART_STRIDE + ai];
        float es  = lrelu(als + ald);
        float4 hs = *(const float4*)&hraw[(size_t)d * NHEAD * HID_F + hh * HID_F + c4];
        if (has_prev) {
            size_t pi = (size_t)(d - 1) * NHEAD + hh;
            float alsp = alsP[pi] + alsP[PART_STRIDE + pi];
            float ep = lrelu(alsp + ald);
            float m  = fmaxf(es, ep);
            float xs = __expf(es - m), xp = __expf(ep - m);
            float inv = 0.5f / (xs + xp);
            xs *= inv; xp *= inv;
            float4 hp = *(const float4*)&hraw[(size_t)(d - 1) * NHEAD * HID_F + hh * HID_F + c4];
            o0 += xs * hs.x + xp * hp.x;
            o1 += xs * hs.y + xp * hp.y;
            o2 += xs * hs.z + xp * hp.z;
            o3 += xs * hs.w + xp * hp.w;
        } else {
            o0 += 0.5f * hs.x; o1 += 0.5f * hs.y; o2 += 0.5f * hs.z; o3 += 0.5f * hs.w;
        }
    }
    acc0 = fmaxf(acc0 + o0, 0.f);
    acc1 = fmaxf(acc1 + o1, 0.f);
    acc2 = fmaxf(acc2 + o2, 0.f);
    acc3 = fmaxf(acc3 + o3, 0.f);

    __half2 ph0; ph0.x = __float2half(acc0); ph0.y = __float2half(acc1);
    __half2 ph1; ph1.x = __float2half(acc2); ph1.y = __float2half(acc3);
    size_t gid2 = ((size_t)d * HID_F + c4) >> 1;
    ((__half2*)out_hi)[gid2]     = ph0;
    ((__half2*)out_hi)[gid2 + 1] = ph1;
}

// ---------------- layer-2 combine + node heads, warp per node ----------------
__global__ __launch_bounds__(256)
void gat_l2_fused(const float* __restrict__ h2raw, const float* __restrict__ alsP,
                  const float* __restrict__ aldP, const float* __restrict__ b2,
                  const float* __restrict__ Wn, const float* __restrict__ bn,
                  const float* __restrict__ Wt, const float* __restrict__ bt,
                  float* __restrict__ emb, float* __restrict__ node_pred,
                  float* __restrict__ logit) {
    int d    = (blockIdx.x * blockDim.x + threadIdx.x) >> 5;
    int lane = threadIdx.x & 31;
    if (d >= N_NODES) return;
    bool has_prev = (d % NODES_PER) != 0;

    float e[4] = {0.f, 0.f, 0.f, 0.f};
#pragma unroll
    for (int hh = 0; hh < NHEAD; hh++) {
        size_t ai = (size_t)d * NHEAD + hh;
        float als = alsP[ai];
        float ald = aldP[ai];
        float es  = lrelu(als + ald);
        float4 hs = *(const float4*)&h2raw[(size_t)d * NHEAD * OUT_F + hh * OUT_F + lane * 4];
        if (has_prev) {
            float alsp = alsP[(size_t)(d - 1) * NHEAD + hh];
            float ep = lrelu(alsp + ald);
            float m  = fmaxf(es, ep);
            float xs = __expf(es - m), xp = __expf(ep - m);
            float inv = 1.f / (xs + xp);
            float4 hp = *(const float4*)&h2raw[(size_t)(d - 1) * NHEAD * OUT_F + hh * OUT_F + lane * 4];
            e[0] += (xs * hs.x + xp * hp.x) * inv;
            e[1] += (xs * hs.y + xp * hp.y) * inv;
            e[2] += (xs * hs.z + xp * hp.z) * inv;
            e[3] += (xs * hs.w + xp * hp.w) * inv;
        } else {
            e[0] += hs.x; e[1] += hs.y; e[2] += hs.z; e[3] += hs.w;
        }
    }
    float4 bb = *(const float4*)&b2[lane * 4];
    e[0] = e[0] * 0.5f + bb.x;
    e[1] = e[1] * 0.5f + bb.y;
    e[2] = e[2] * 0.5f + bb.z;
    e[3] = e[3] * 0.5f + bb.w;
    float4 ev; ev.x = e[0]; ev.y = e[1]; ev.z = e[2]; ev.w = e[3];
    *(float4*)&emb[(size_t)d * OUT_F + lane * 4] = ev;

    float vals[8];
#pragma unroll
    for (int o = 0; o < 8; o++) {
        const float* w = (o < NCLS) ? &Wn[o * OUT_F] : Wt;
        float4 w4 = *(const float4*)&w[lane * 4];
        float s = e[0] * w4.x + e[1] * w4.y + e[2] * w4.z + e[3] * w4.w;
#pragma unroll
        for (int sh = 16; sh; sh >>= 1) s += __shfl_xor_sync(0xffffffffu, s, sh);
        vals[o] = s;
    }
    if (lane == 0) {
        float z[NCLS], m = -1e30f;
#pragma unroll
        for (int i = 0; i < NCLS; i++) { z[i] = vals[i] + bn[i]; m = fmaxf(m, z[i]); }
        float ssum = 0.f;
#pragma unroll
        for (int i = 0; i < NCLS; i++) { z[i] = __expf(z[i] - m); ssum += z[i]; }
        float inv = 1.f / ssum;
#pragma unroll
        for (int i = 0; i < NCLS; i++) node_pred[(size_t)d * NCLS + i] = z[i] * inv;
        logit[d] = vals[7] + bt[0];
    }
}

// ---------------- audio pooling, stage 1: per-audio softmax weights ----------------
__global__ __launch_bounds__(256)
void audio_softmax(const float* __restrict__ logit, float* __restrict__ aw) {
    __shared__ float red[256];
    int b = blockIdx.x, t = threadIdx.x;
    const float* lg = logit + b * NODES_PER;

    float m = -1e30f;
    for (int i = t; i < NODES_PER; i += 256) m = fmaxf(m, lg[i]);
    red[t] = m; __syncthreads();
    for (int s = 128; s; s >>= 1) { if (t < s) red[t] = fmaxf(red[t], red[t + s]); __syncthreads(); }
    m = red[0]; __syncthreads();

    float e0 = __expf(lg[t] - m);
    float e1 = __expf(lg[t + 256] - m);
    float e2 = __expf(lg[t + 512] - m);
    float e3 = __expf(lg[t + 768] - m);
    float e4 = __expf(lg[t + 1024] - m);
    float e5 = __expf(lg[t + 1280] - m);
    float e6 = __expf(lg[t + 1536] - m);
    float e7 = __expf(lg[t + 1792] - m);
    red[t] = ((e0 + e1) + (e2 + e3)) + ((e4 + e5) + (e6 + e7));
    __syncthreads();
    for (int s = 128; s; s >>= 1) { if (t < s) red[t] += red[t + s]; __syncthreads(); }
    float inv = 1.f / red[0];
    float* dst = aw + b * NODES_PER;
    dst[t]        = e0 * inv;
    dst[t + 256]  = e1 * inv;
    dst[t + 512]  = e2 * inv;
    dst[t + 768]  = e3 * inv;
    dst[t + 1024] = e4 * inv;
    dst[t + 1280] = e5 * inv;
    dst[t + 1536] = e6 * inv;
    dst[t + 1792] = e7 * inv;
}

// ---------------- audio pooling, stage 2: weighted sum (chunked, coalesced) ----------------
__global__ __launch_bounds__(256)
void audio_wsum(const float* __restrict__ emb, const float* __restrict__ aw,
                float* __restrict__ att) {
    __shared__ float red[8][33];
    int chunk = blockIdx.x, b = blockIdx.y;
    int w = threadIdx.x >> 5, lane = threadIdx.x & 31;
    int ch = chunk * 32 + lane;
    const float* eb = emb + (size_t)b * NODES_PER * OUT_F + ch;
    const float* wb = aw + b * NODES_PER;

    float a0 = 0.f, a1 = 0.f;
    int i0 = w * 256;
#pragma unroll 4
    for (int i = 0; i < 256; i += 2) {
        a0 = fmaf(wb[i0 + i],     eb[(size_t)(i0 + i) * OUT_F],     a0);
        a1 = fmaf(wb[i0 + i + 1], eb[(size_t)(i0 + i + 1) * OUT_F], a1);
    }
    red[w][lane] = a0 + a1;
    __syncthreads();
    if (w == 0) {
        float s = red[0][lane];
#pragma unroll
        for (int j = 1; j < 8; j++) s += red[j][lane];
        att[b * OUT_F + ch] = s;
    }
}

// ---------------- audio pooling, stage 3: Wa head ----------------
__global__ __launch_bounds__(128)
void audio_head(const float* __restrict__ att, const float* __restrict__ Wa,
                const float* __restrict__ ba, float* __restrict__ audio_pred) {
    __shared__ float red[128];
    int b = blockIdx.x, t = threadIdx.x;
    float a = att[b * OUT_F + t];
#pragma unroll
    for (int o = 0; o < 2; o++) {
        red[t] = a * Wa[o * OUT_F + t]; __syncthreads();
        for (int s = 64; s; s >>= 1) { if (t < s) red[t] += red[t + s]; __syncthreads(); }
        if (t == 0) audio_pred[b * 2 + o] = red[0] + ba[o];
        __syncthreads();
    }
}

// ---------------- launch ----------------
extern "C" void kernel_launch(void* const* d_in, const int* in_sizes, int n_in,
                              void* d_out, int out_size) {
    int wi = n_in - 14;
    const float* x   = (const float*)d_in[0];
    const float* W1  = (const float*)d_in[wi + 0];
    const float* as1 = (const float*)d_in[wi + 1];
    const float* ad1 = (const float*)d_in[wi + 2];
    const float* b1  = (const float*)d_in[wi + 3];
    const float* W2  = (const float*)d_in[wi + 4];
    const float* as2 = (const float*)d_in[wi + 5];
    const float* ad2 = (const float*)d_in[wi + 6];
    const float* b2  = (const float*)d_in[wi + 7];
    const float* Wt  = (const float*)d_in[wi + 8];
    const float* bt  = (const float*)d_in[wi + 9];
    const float* Wa  = (const float*)d_in[wi + 10];
    const float* ba  = (const float*)d_in[wi + 11];
    const float* Wn  = (const float*)d_in[wi + 12];
    const float* bn  = (const float*)d_in[wi + 13];

    float *h1raw, *h2raw, *emb, *als1p, *ald1p, *als2p, *ald2p, *logit, *aw, *att;
    __half *xh, *h1h, *w1h, *w2h;
    cudaGetSymbolAddress((void**)&h1raw, g_h1raw);
    cudaGetSymbolAddress((void**)&h2raw, g_h2raw);
    cudaGetSymbolAddress((void**)&emb,   g_emb);
    cudaGetSymbolAddress((void**)&xh,    g_xh);
    cudaGetSymbolAddress((void**)&h1h,   g_h1h);
    cudaGetSymbolAddress((void**)&w1h,   g_w1h);
    cudaGetSymbolAddress((void**)&w2h,   g_w2h);
    cudaGetSymbolAddress((void**)&als1p, g_als1p);
    cudaGetSymbolAddress((void**)&ald1p, g_ald1p);
    cudaGetSymbolAddress((void**)&als2p, g_als2p);
    cudaGetSymbolAddress((void**)&ald2p, g_ald2p);
    cudaGetSymbolAddress((void**)&logit, g_logit);
    cudaGetSymbolAddress((void**)&aw,    g_aw);
    cudaGetSymbolAddress((void**)&att,   g_att);

    float* node_pred  = (float*)d_out;
    float* audio_pred = node_pred + (size_t)N_NODES * NCLS;

    cudaFuncSetAttribute(gemm_mma<512>, cudaFuncAttributeMaxDynamicSharedMemorySize, GEMM_SMEM);
    cudaFuncSetAttribute(gemm_mma<256>, cudaFuncAttributeMaxDynamicSharedMemorySize, GEMM_SMEM);

    // conversions (all single fp16)
    cvt_f16<<<(N_NODES * IN_F / 4 + 255) / 256, 256>>>(x, xh, N_NODES * IN_F / 4);
    cvt_f16<<<(512 * 512 / 4 + 255) / 256, 256>>>(W1, w1h, 512 * 512 / 4);
    cvt_f16<<<(256 * 256 / 4 + 255) / 256, 256>>>(W2, w2h, 256 * 256 / 4);

    // layer 1: h1raw = x @ W1^T [N,512] + fused al1 partials
    gemm_mma<512><<<dim3(4, N_NODES / 128), 256, GEMM_SMEM>>>(
        xh, w1h, h1raw, 512, as1, ad1, als1p, ald1p);
    gat_combine_l1<<<N_NODES / 4, 256>>>(h1raw, als1p, ald1p, b1, h1h);

    // layer 2: h2raw = h1 @ W2^T [N,256] + fused al2 partials
    gemm_mma<256><<<dim3(2, N_NODES / 128), 256, GEMM_SMEM>>>(
        h1h, w2h, h2raw, 256, as2, ad2, als2p, ald2p);
    gat_l2_fused<<<N_NODES / 8, 256>>>(h2raw, als2p, ald2p, b2, Wn, bn, Wt, bt,
                                       emb, node_pred, logit);

    // audio head (3-stage, parallel)
    audio_softmax<<<B_AUD, 256>>>(logit, aw);
    audio_wsum<<<dim3(4, B_AUD), 256>>>(emb, aw, att);
    audio_head<<<B_AUD, 128>>>(att, Wa, ba, audio_pred);
}

// round 12
// speedup vs baseline: 4.8697x; 1.0109x over previous
#include <cuda_runtime.h>
#include <cuda_fp16.h>
#include <cstdint>

#define N_NODES   131072
#define NODES_PER 2048
#define B_AUD     64
#define IN_F      512
#define HID_F     256
#define OUT_F     128
#define NHEAD     2
#define NCLS      7
#define NEG_SLOPE 0.2f
#define PART_STRIDE ((size_t)N_NODES * NHEAD)

// ---------------- scratch (static device allocations; no cudaMalloc) ----------------
__device__ __half g_h1raw[(size_t)N_NODES * NHEAD * HID_F]; // 128 MB (fp16)
__device__ __half g_h2raw[(size_t)N_NODES * NHEAD * OUT_F]; //  64 MB (fp16)
__device__ float  g_emb  [(size_t)N_NODES * OUT_F];         //  64 MB
__device__ __half g_xh  [(size_t)N_NODES * IN_F];
__device__ __half g_h1h [(size_t)N_NODES * HID_F];
__device__ __half g_w1h [512 * 512];
__device__ __half g_w2h [256 * 256];
__device__ float g_als1p[2 * PART_STRIDE];
__device__ float g_ald1p[2 * PART_STRIDE];
__device__ float g_als2p[2 * PART_STRIDE];
__device__ float g_ald2p[2 * PART_STRIDE];
__device__ float g_logit[N_NODES];
__device__ float g_aw   [B_AUD * NODES_PER];
__device__ float g_att  [B_AUD * OUT_F];

__device__ __forceinline__ float lrelu(float v) { return v > 0.f ? v : NEG_SLOPE * v; }

// ---------------- PTX helpers (portable: sm_80-class, compiles at compute_103) ----------------
__device__ __forceinline__ uint32_t smem_u32(const void* p) {
    uint32_t a;
    asm("{ .reg .u64 t; cvta.to.shared.u64 t, %1; cvt.u32.u64 %0, t; }" : "=r"(a) : "l"(p));
    return a;
}
__device__ __forceinline__ uint32_t swz(uint32_t b) { return b ^ ((b >> 3) & 0x70); }
__device__ __forceinline__ void cp16(uint32_t dst, const void* src) {
    asm volatile("cp.async.cg.shared.global [%0], [%1], 16;" :: "r"(dst), "l"(src));
}
__device__ __forceinline__ void ldm_x4(uint32_t* r, uint32_t addr) {
    asm volatile("ldmatrix.sync.aligned.m8n8.x4.shared.b16 {%0,%1,%2,%3}, [%4];"
                 : "=r"(r[0]), "=r"(r[1]), "=r"(r[2]), "=r"(r[3]) : "r"(addr));
}
__device__ __forceinline__ void mma_f16(float* c, const uint32_t* a, uint32_t b0, uint32_t b1) {
    asm volatile(
        "mma.sync.aligned.m16n8k16.row.col.f32.f16.f16.f32 "
        "{%0,%1,%2,%3}, {%4,%5,%6,%7}, {%8,%9}, {%0,%1,%2,%3};"
        : "+f"(c[0]), "+f"(c[1]), "+f"(c[2]), "+f"(c[3])
        : "r"(a[0]), "r"(a[1]), "r"(a[2]), "r"(a[3]), "r"(b0), "r"(b1));
}

// ---------------- fp32 -> fp16 convert ----------------
__global__ __launch_bounds__(256)
void cvt_f16(const float* __restrict__ a, __half* __restrict__ o, int n4) {
    int i = blockIdx.x * 256 + threadIdx.x;
    if (i >= n4) return;
    float4 v = ((const float4*)a)[i];
    __half2 p0; p0.x = __float2half(v.x); p0.y = __float2half(v.y);
    __half2 p1; p1.x = __float2half(v.z); p1.y = __float2half(v.w);
    ((__half2*)o)[2 * i]     = p0;
    ((__half2*)o)[2 * i + 1] = p1;
}

// ---------------- fp16 warp-MMA GEMM: C(fp16) = A * B^T, fused al-epilogue ----------------
// CTA 128x128, BK=64; 3-stage cp.async, ONE __syncthreads per iter (early-load);
// 8 warps in 4m x 2n, warp tile 32x64: 6 ldmatrix / 16 MMA per kk per warp.
#define STG_A     0
#define STG_B     16384
#define STG_BYTES 32768
#define GEMM_SMEM (3 * STG_BYTES)

template <int K>
__global__ __launch_bounds__(256, 2)
void gemm_mma(const __half* __restrict__ A, const __half* __restrict__ B,
              __half* __restrict__ C, int Mtot,
              const float* __restrict__ ws_flat, const float* __restrict__ wd_flat,
              float* __restrict__ alsP, float* __restrict__ aldP) {
    extern __shared__ __align__(1024) char smem[];
    uint32_t sb = smem_u32(smem);
    const int tid = threadIdx.x, wid = tid >> 5, lane = tid & 31;
    const int row0 = blockIdx.y * 128, col0 = blockIdx.x * 128;
    const int warp_m = wid & 3;    // 0..3 -> 32 rows each
    const int warp_n = wid >> 2;   // 0..1 -> 64 cols each
    constexpr int NIT = K / 64;

    auto load = [&](int it) {
        uint32_t st = sb + (it % 3) * STG_BYTES;
#pragma unroll
        for (int i = 0; i < 4; i++) {
            int idx = tid + i * 256;
            int r = idx >> 3, c16 = idx & 7;
            uint32_t so = swz(r * 128 + c16 * 16);
            cp16(st + STG_A + so, A + (size_t)(row0 + r) * K + it * 64 + c16 * 8);
            cp16(st + STG_B + so, B + (size_t)(col0 + r) * K + it * 64 + c16 * 8);
        }
        asm volatile("cp.async.commit_group;" ::: "memory");
    };

    float acc[2][8][4] = {};   // [mt][n8 block][frag]

    load(0);
    if (NIT > 1) load(1);

    const int lrow = lane & 15, lhi = lane >> 4;

#pragma unroll 1
    for (int it = 0; it < NIT; it++) {
        if (NIT > 1) asm volatile("cp.async.wait_group 1;" ::: "memory");
        else         asm volatile("cp.async.wait_group 0;" ::: "memory");
        __syncthreads();
        if (it + 2 < NIT) load(it + 2);        // writes oldest stage; readers retired by barrier above

        uint32_t st = sb + (it % 3) * STG_BYTES;
#pragma unroll
        for (int kk = 0; kk < 4; kk++) {
            uint32_t a[2][4];
#pragma unroll
            for (int mt = 0; mt < 2; mt++)
                ldm_x4(a[mt], st + STG_A + swz((warp_m * 32 + mt * 16 + lrow) * 128 + (kk * 2 + lhi) * 16));
#pragma unroll
            for (int bf = 0; bf < 4; bf++) {
                uint32_t b[4];
                ldm_x4(b, st + STG_B + swz((warp_n * 64 + bf * 16 + lrow) * 128 + (kk * 2 + lhi) * 16));
#pragma unroll
                for (int mt = 0; mt < 2; mt++) {
                    mma_f16(acc[mt][bf * 2 + 0], a[mt], b[0], b[2]);
                    mma_f16(acc[mt][bf * 2 + 1], a[mt], b[1], b[3]);
                }
            }
        }
    }
    __syncthreads();   // smem about to be reused as reduction buffer

    // ---- epilogue 1: store C tile as fp16 ----
#pragma unroll
    for (int mt = 0; mt < 2; mt++) {
        int row = row0 + warp_m * 32 + mt * 16 + (lane >> 2);
#pragma unroll
        for (int nb = 0; nb < 8; nb++) {
            int col = col0 + warp_n * 64 + nb * 8 + (lane & 3) * 2;
            __half2 v0; v0.x = __float2half(acc[mt][nb][0]); v0.y = __float2half(acc[mt][nb][1]);
            __half2 v1; v1.x = __float2half(acc[mt][nb][2]); v1.y = __float2half(acc[mt][nb][3]);
            *(__half2*)&C[(size_t)row * Mtot + col]       = v0;
            *(__half2*)&C[(size_t)(row + 8) * Mtot + col] = v1;
        }
    }

    // ---- epilogue 2: partial attention logits (from fp32 accumulators) ----
    const int C_head = Mtot / NHEAD;
    const int head = col0 / C_head;
    const int slot = (col0 % C_head) >> 7;
    float* bufss = (float*)smem;             // [2 warp_n][128 rows]
    float* bufsd = bufss + 256;

#pragma unroll
    for (int mt = 0; mt < 2; mt++) {
        float ss0 = 0.f, ss1 = 0.f, sd0 = 0.f, sd1 = 0.f;
#pragma unroll
        for (int nb = 0; nb < 8; nb++) {
            int c = col0 + warp_n * 64 + nb * 8 + (lane & 3) * 2;
            float w0s = ws_flat[c], w1s = ws_flat[c + 1];
            float w0d = wd_flat[c], w1d = wd_flat[c + 1];
            ss0 = fmaf(acc[mt][nb][0], w0s, fmaf(acc[mt][nb][1], w1s, ss0));
            ss1 = fmaf(acc[mt][nb][2], w0s, fmaf(acc[mt][nb][3], w1s, ss1));
            sd0 = fmaf(acc[mt][nb][0], w0d, fmaf(acc[mt][nb][1], w1d, sd0));
            sd1 = fmaf(acc[mt][nb][2], w0d, fmaf(acc[mt][nb][3], w1d, sd1));
        }
#pragma unroll
        for (int off = 1; off <= 2; off <<= 1) {
            ss0 += __shfl_xor_sync(0xffffffffu, ss0, off);
            ss1 += __shfl_xor_sync(0xffffffffu, ss1, off);
            sd0 += __shfl_xor_sync(0xffffffffu, sd0, off);
            sd1 += __shfl_xor_sync(0xffffffffu, sd1, off);
        }
        if ((lane & 3) == 0) {
            int r0 = warp_m * 32 + mt * 16 + (lane >> 2);
            bufss[warp_n * 128 + r0]     = ss0;
            bufss[warp_n * 128 + r0 + 8] = ss1;
            bufsd[warp_n * 128 + r0]     = sd0;
            bufsd[warp_n * 128 + r0 + 8] = sd1;
        }
    }
    __syncthreads();
    if (tid < 128) {
        float ss = bufss[tid] + bufss[128 + tid];
        float sd = bufsd[tid] + bufsd[128 + tid];
        size_t node = (size_t)(row0 + tid);
        alsP[(size_t)slot * PART_STRIDE + node * NHEAD + head] = ss;
        aldP[(size_t)slot * PART_STRIDE + node * NHEAD + head] = sd;
    }
}

// ---------------- layer-1 GAT combine, vectorized: 4 nodes per block, fp16 in/out ----------------
__global__ __launch_bounds__(256)
void gat_combine_l1(const __half* __restrict__ hraw, const float* __restrict__ alsP,
                    const float* __restrict__ aldP, const float* __restrict__ bias,
                    __half* __restrict__ out_hi) {
    int tid = threadIdx.x;
    int d   = blockIdx.x * 4 + (tid >> 6);
    int c4  = (tid & 63) * 4;
    bool has_prev = (d % NODES_PER) != 0;

    float4 r = *(const float4*)&bias[c4];
    float acc0 = r.x, acc1 = r.y, acc2 = r.z, acc3 = r.w;
    float o0 = 0.f, o1 = 0.f, o2 = 0.f, o3 = 0.f;
#pragma unroll
    for (int hh = 0; hh < NHEAD; hh++) {
        size_t ai = (size_t)d * NHEAD + hh;
        float als = alsP[ai] + alsP[PART_STRIDE + ai];
        float ald = aldP[ai] + aldP[PART_STRIDE + ai];
        float es  = lrelu(als + ald);
        const __half2* hsp = (const __half2*)&hraw[(size_t)d * NHEAD * HID_F + hh * HID_F + c4];
        float2 hs01 = __half22float2(hsp[0]);
        float2 hs23 = __half22float2(hsp[1]);
        if (has_prev) {
            size_t pi = (size_t)(d - 1) * NHEAD + hh;
            float alsp = alsP[pi] + alsP[PART_STRIDE + pi];
            float ep = lrelu(alsp + ald);
            float m  = fmaxf(es, ep);
            float xs = __expf(es - m), xp = __expf(ep - m);
            float inv = 0.5f / (xs + xp);
            xs *= inv; xp *= inv;
            const __half2* hpp = (const __half2*)&hraw[(size_t)(d - 1) * NHEAD * HID_F + hh * HID_F + c4];
            float2 hp01 = __half22float2(hpp[0]);
            float2 hp23 = __half22float2(hpp[1]);
            o0 += xs * hs01.x + xp * hp01.x;
            o1 += xs * hs01.y + xp * hp01.y;
            o2 += xs * hs23.x + xp * hp23.x;
            o3 += xs * hs23.y + xp * hp23.y;
        } else {
            o0 += 0.5f * hs01.x; o1 += 0.5f * hs01.y;
            o2 += 0.5f * hs23.x; o3 += 0.5f * hs23.y;
        }
    }
    acc0 = fmaxf(acc0 + o0, 0.f);
    acc1 = fmaxf(acc1 + o1, 0.f);
    acc2 = fmaxf(acc2 + o2, 0.f);
    acc3 = fmaxf(acc3 + o3, 0.f);

    __half2 ph0; ph0.x = __float2half(acc0); ph0.y = __float2half(acc1);
    __half2 ph1; ph1.x = __float2half(acc2); ph1.y = __float2half(acc3);
    size_t gid2 = ((size_t)d * HID_F + c4) >> 1;
    ((__half2*)out_hi)[gid2]     = ph0;
    ((__half2*)out_hi)[gid2 + 1] = ph1;
}

// ---------------- layer-2 combine + node heads, warp per node (fp16 h2raw) ----------------
__global__ __launch_bounds__(256)
void gat_l2_fused(const __half* __restrict__ h2raw, const float* __restrict__ alsP,
                  const float* __restrict__ aldP, const float* __restrict__ b2,
                  const float* __restrict__ Wn, const float* __restrict__ bn,
                  const float* __restrict__ Wt, const float* __restrict__ bt,
                  float* __restrict__ emb, float* __restrict__ node_pred,
                  float* __restrict__ logit) {
    int d    = (blockIdx.x * blockDim.x + threadIdx.x) >> 5;
    int lane = threadIdx.x & 31;
    if (d >= N_NODES) return;
    bool has_prev = (d % NODES_PER) != 0;

    float e[4] = {0.f, 0.f, 0.f, 0.f};
#pragma unroll
    for (int hh = 0; hh < NHEAD; hh++) {
        size_t ai = (size_t)d * NHEAD + hh;
        float als = alsP[ai];
        float ald = aldP[ai];
        float es  = lrelu(als + ald);
        const __half2* hsp = (const __half2*)&h2raw[(size_t)d * NHEAD * OUT_F + hh * OUT_F + lane * 4];
        float2 hs01 = __half22float2(hsp[0]);
        float2 hs23 = __half22float2(hsp[1]);
        if (has_prev) {
            float alsp = alsP[(size_t)(d - 1) * NHEAD + hh];
            float ep = lrelu(alsp + ald);
            float m  = fmaxf(es, ep);
            float xs = __expf(es - m), xp = __expf(ep - m);
            float inv = 1.f / (xs + xp);
            const __half2* hpp = (const __half2*)&h2raw[(size_t)(d - 1) * NHEAD * OUT_F + hh * OUT_F + lane * 4];
            float2 hp01 = __half22float2(hpp[0]);
            float2 hp23 = __half22float2(hpp[1]);
            e[0] += (xs * hs01.x + xp * hp01.x) * inv;
            e[1] += (xs * hs01.y + xp * hp01.y) * inv;
            e[2] += (xs * hs23.x + xp * hp23.x) * inv;
            e[3] += (xs * hs23.y + xp * hp23.y) * inv;
        } else {
            e[0] += hs01.x; e[1] += hs01.y; e[2] += hs23.x; e[3] += hs23.y;
        }
    }
    float4 bb = *(const float4*)&b2[lane * 4];
    e[0] = e[0] * 0.5f + bb.x;
    e[1] = e[1] * 0.5f + bb.y;
    e[2] = e[2] * 0.5f + bb.z;
    e[3] = e[3] * 0.5f + bb.w;
    float4 ev; ev.x = e[0]; ev.y = e[1]; ev.z = e[2]; ev.w = e[3];
    *(float4*)&emb[(size_t)d * OUT_F + lane * 4] = ev;

    float vals[8];
#pragma unroll
    for (int o = 0; o < 8; o++) {
        const float* w = (o < NCLS) ? &Wn[o * OUT_F] : Wt;
        float4 w4 = *(const float4*)&w[lane * 4];
        float s = e[0] * w4.x + e[1] * w4.y + e[2] * w4.z + e[3] * w4.w;
#pragma unroll
        for (int sh = 16; sh; sh >>= 1) s += __shfl_xor_sync(0xffffffffu, s, sh);
        vals[o] = s;
    }
    if (lane == 0) {
        float z[NCLS], m = -1e30f;
#pragma unroll
        for (int i = 0; i < NCLS; i++) { z[i] = vals[i] + bn[i]; m = fmaxf(m, z[i]); }
        float ssum = 0.f;
#pragma unroll
        for (int i = 0; i < NCLS; i++) { z[i] = __expf(z[i] - m); ssum += z[i]; }
        float inv = 1.f / ssum;
#pragma unroll
        for (int i = 0; i < NCLS; i++) node_pred[(size_t)d * NCLS + i] = z[i] * inv;
        logit[d] = vals[7] + bt[0];
    }
}

// ---------------- audio pooling, stage 1: per-audio softmax weights ----------------
__global__ __launch_bounds__(256)
void audio_softmax(const float* __restrict__ logit, float* __restrict__ aw) {
    __shared__ float red[256];
    int b = blockIdx.x, t = threadIdx.x;
    const float* lg = logit + b * NODES_PER;

    float m = -1e30f;
    for (int i = t; i < NODES_PER; i += 256) m = fmaxf(m, lg[i]);
    red[t] = m; __syncthreads();
    for (int s = 128; s; s >>= 1) { if (t < s) red[t] = fmaxf(red[t], red[t + s]); __syncthreads(); }
    m = red[0]; __syncthreads();

    float e0 = __expf(lg[t] - m);
    float e1 = __expf(lg[t + 256] - m);
    float e2 = __expf(lg[t + 512] - m);
    float e3 = __expf(lg[t + 768] - m);
    float e4 = __expf(lg[t + 1024] - m);
    float e5 = __expf(lg[t + 1280] - m);
    float e6 = __expf(lg[t + 1536] - m);
    float e7 = __expf(lg[t + 1792] - m);
    red[t] = ((e0 + e1) + (e2 + e3)) + ((e4 + e5) + (e6 + e7));
    __syncthreads();
    for (int s = 128; s; s >>= 1) { if (t < s) red[t] += red[t + s]; __syncthreads(); }
    float inv = 1.f / red[0];
    float* dst = aw + b * NODES_PER;
    dst[t]        = e0 * inv;
    dst[t + 256]  = e1 * inv;
    dst[t + 512]  = e2 * inv;
    dst[t + 768]  = e3 * inv;
    dst[t + 1024] = e4 * inv;
    dst[t + 1280] = e5 * inv;
    dst[t + 1536] = e6 * inv;
    dst[t + 1792] = e7 * inv;
}

// ---------------- audio pooling, stage 2: weighted sum (chunked, coalesced) ----------------
__global__ __launch_bounds__(256)
void audio_wsum(const float* __restrict__ emb, const float* __restrict__ aw,
                float* __restrict__ att) {
    __shared__ float red[8][33];
    int chunk = blockIdx.x, b = blockIdx.y;
    int w = threadIdx.x >> 5, lane = threadIdx.x & 31;
    int ch = chunk * 32 + lane;
    const float* eb = emb + (size_t)b * NODES_PER * OUT_F + ch;
    const float* wb = aw + b * NODES_PER;

    float a0 = 0.f, a1 = 0.f;
    int i0 = w * 256;
#pragma unroll 4
    for (int i = 0; i < 256; i += 2) {
        a0 = fmaf(wb[i0 + i],     eb[(size_t)(i0 + i) * OUT_F],     a0);
        a1 = fmaf(wb[i0 + i + 1], eb[(size_t)(i0 + i + 1) * OUT_F], a1);
    }
    red[w][lane] = a0 + a1;
    __syncthreads();
    if (w == 0) {
        float s = red[0][lane];
#pragma unroll
        for (int j = 1; j < 8; j++) s += red[j][lane];
        att[b * OUT_F + ch] = s;
    }
}

// ---------------- audio pooling, stage 3: Wa head ----------------
__global__ __launch_bounds__(128)
void audio_head(const float* __restrict__ att, const float* __restrict__ Wa,
                const float* __restrict__ ba, float* __restrict__ audio_pred) {
    __shared__ float red[128];
    int b = blockIdx.x, t = threadIdx.x;
    float a = att[b * OUT_F + t];
#pragma unroll
    for (int o = 0; o < 2; o++) {
        red[t] = a * Wa[o * OUT_F + t]; __syncthreads();
        for (int s = 64; s; s >>= 1) { if (t < s) red[t] += red[t + s]; __syncthreads(); }
        if (t == 0) audio_pred[b * 2 + o] = red[0] + ba[o];
        __syncthreads();
    }
}

// ---------------- launch ----------------
extern "C" void kernel_launch(void* const* d_in, const int* in_sizes, int n_in,
                              void* d_out, int out_size) {
    int wi = n_in - 14;
    const float* x   = (const float*)d_in[0];
    const float* W1  = (const float*)d_in[wi + 0];
    const float* as1 = (const float*)d_in[wi + 1];
    const float* ad1 = (const float*)d_in[wi + 2];
    const float* b1  = (const float*)d_in[wi + 3];
    const float* W2  = (const float*)d_in[wi + 4];
    const float* as2 = (const float*)d_in[wi + 5];
    const float* ad2 = (const float*)d_in[wi + 6];
    const float* b2  = (const float*)d_in[wi + 7];
    const float* Wt  = (const float*)d_in[wi + 8];
    const float* bt  = (const float*)d_in[wi + 9];
    const float* Wa  = (const float*)d_in[wi + 10];
    const float* ba  = (const float*)d_in[wi + 11];
    const float* Wn  = (const float*)d_in[wi + 12];
    const float* bn  = (const float*)d_in[wi + 13];

    float *emb, *als1p, *ald1p, *als2p, *ald2p, *logit, *aw, *att;
    __half *h1raw, *h2raw, *xh, *h1h, *w1h, *w2h;
    cudaGetSymbolAddress((void**)&h1raw, g_h1raw);
    cudaGetSymbolAddress((void**)&h2raw, g_h2raw);
    cudaGetSymbolAddress((void**)&emb,   g_emb);
    cudaGetSymbolAddress((void**)&xh,    g_xh);
    cudaGetSymbolAddress((void**)&h1h,   g_h1h);
    cudaGetSymbolAddress((void**)&w1h,   g_w1h);
    cudaGetSymbolAddress((void**)&w2h,   g_w2h);
    cudaGetSymbolAddress((void**)&als1p, g_als1p);
    cudaGetSymbolAddress((void**)&ald1p, g_ald1p);
    cudaGetSymbolAddress((void**)&als2p, g_als2p);
    cudaGetSymbolAddress((void**)&ald2p, g_ald2p);
    cudaGetSymbolAddress((void**)&logit, g_logit);
    cudaGetSymbolAddress((void**)&aw,    g_aw);
    cudaGetSymbolAddress((void**)&att,   g_att);

    float* node_pred  = (float*)d_out;
    float* audio_pred = node_pred + (size_t)N_NODES * NCLS;

    cudaFuncSetAttribute(gemm_mma<512>, cudaFuncAttributeMaxDynamicSharedMemorySize, GEMM_SMEM);
    cudaFuncSetAttribute(gemm_mma<256>, cudaFuncAttributeMaxDynamicSharedMemorySize, GEMM_SMEM);

    // conversions (all single fp16)
    cvt_f16<<<(N_NODES * IN_F / 4 + 255) / 256, 256>>>(x, xh, N_NODES * IN_F / 4);
    cvt_f16<<<(512 * 512 / 4 + 255) / 256, 256>>>(W1, w1h, 512 * 512 / 4);
    cvt_f16<<<(256 * 256 / 4 + 255) / 256, 256>>>(W2, w2h, 256 * 256 / 4);

    // layer 1: h1raw(fp16) = x @ W1^T [N,512] + fused al1 partials
    gemm_mma<512><<<dim3(4, N_NODES / 128), 256, GEMM_SMEM>>>(
        xh, w1h, h1raw, 512, as1, ad1, als1p, ald1p);
    gat_combine_l1<<<N_NODES / 4, 256>>>(h1raw, als1p, ald1p, b1, h1h);

    // layer 2: h2raw(fp16) = h1 @ W2^T [N,256] + fused al2 partials
    gemm_mma<256><<<dim3(2, N_NODES / 128), 256, GEMM_SMEM>>>(
        h1h, w2h, h2raw, 256, as2, ad2, als2p, ald2p);
    gat_l2_fused<<<N_NODES / 8, 256>>>(h2raw, als2p, ald2p, b2, Wn, bn, Wt, bt,
                                       emb, node_pred, logit);

    // audio head (3-stage, parallel)
    audio_softmax<<<B_AUD, 256>>>(logit, aw);
    audio_wsum<<<dim3(4, B_AUD), 256>>>(emb, aw, att);
    audio_head<<<B_AUD, 128>>>(att, Wa, ba, audio_pred);
}